// round 9
// baseline (speedup 1.0000x reference)
#include <cuda_runtime.h>
#include <cuda_fp16.h>
#include <math.h>
#include <stdint.h>

#define T_LEN 64
#define BATCH 32
#define SEQ   400
#define HID   512
#define VOC   50000
#define EXTD  400
#define VE    (VOC+EXTD)
#define TB    (T_LEN*BATCH)     /* 2048 */
#define H3    (3*HID)           /* 1536 */
#define VPAD  50176             /* VOC padded to 256 */

/* ---------------- scratch (device globals: allocation-free) -------------- */
__device__ float  g_cat [TB*H3];              /* (T*B,3H) fp32 (gate)        */
__device__ float  g_w   [BATCH*T_LEN*SEQ];    /* scores fp32 (B,T,S)         */
__device__ __half g_cat16[TB*H3];
__device__ __half g_wp16 [(long)VPAD*H3];
__device__ __half g_h16  [TB*HID];
__device__ __half g_mem16[SEQ*BATCH*HID];
__device__ __half g_W416 [4*HID*HID];         /* Wq,Wk,Wv,Wo                 */
__device__ __half g_q16  [BATCH*T_LEN*HID];   /* (B,T,H)                     */
__device__ __half g_k16  [BATCH*SEQ*HID];     /* (B,S,H)                     */
__device__ __half g_valT16[BATCH*HID*SEQ];    /* (B,H,S)                     */
__device__ __half g_w16  [BATCH*T_LEN*SEQ];   /* attn weights fp16           */
__device__ __half g_atts16[TB*HID];           /* (B,T,H) rows b*T+t          */

#define BN 128

__device__ __forceinline__ void cpa16u(unsigned dst, const void* src, int bytes){
  asm volatile("cp.async.cg.shared.global [%0], [%1], 16, %2;\n"
               :: "r"(dst), "l"(src), "r"(bytes));
}
#define CPA_COMMIT() asm volatile("cp.async.commit_group;\n")
#define CPA_WAIT2()  asm volatile("cp.async.wait_group 2;\n")

#define LDSM_X4(r0,r1,r2,r3,addr) \
  asm volatile("ldmatrix.sync.aligned.m8n8.x4.shared.b16 {%0,%1,%2,%3}, [%4];" \
               : "=r"(r0), "=r"(r1), "=r"(r2), "=r"(r3) : "r"(addr))

#define MMA16(d, a0,a1,a2,a3, b0,b1) \
  asm volatile("mma.sync.aligned.m16n8k16.row.col.f32.f16.f16.f32 " \
               "{%0,%1,%2,%3}, {%4,%5,%6,%7}, {%8,%9}, {%0,%1,%2,%3};\n" \
               : "+f"((d)[0]), "+f"((d)[1]), "+f"((d)[2]), "+f"((d)[3]) \
               : "r"(a0), "r"(a1), "r"(a2), "r"(a3), "r"(b0), "r"(b1))

/* ---------------- generic fp16 MMA GEMM --------------------------------- */
struct GH {
  const __half* A; const __half* B; const __half* B2;
  float* Cf; __half* Ch; __half* Ch2;
  long lda, ldb, ldc;
  long sA, sB, sC;            /* batch strides (grid.z)                      */
  int  M, N, K;
  const float* bias; const float* bias2;
  float alpha;
  int  mode, D1, D2;
  long col_off;
};

__device__ __forceinline__ void epih(const GH& p, float* Cf, __half* Ch,
                                     int m, int n, float v){
  if (m >= p.M || n >= p.N) return;
  if (p.mode == 0){                           /* scores fp32 flat            */
    Cf[(long)m*p.ldc + n] = v; return;
  }
  if (p.mode == 1){                           /* q fp16 permuted + bias*alpha*/
    long idx = ((long)(m % p.D1)*p.D2 + m/p.D1)*p.ldc + n;
    Ch[idx] = __float2half_rn(p.alpha*(v + p.bias[n])); return;
  }
  if (p.mode == 3){                           /* dual k/val fp16             */
    int s = m / BATCH, b = m % BATCH;
    if (n < HID)
      p.Ch[((long)b*SEQ + s)*HID + n] = __float2half_rn(v + p.bias[n]);
    else {
      int nn = n - HID;
      p.Ch2[((long)b*HID + nn)*SEQ + s] = __float2half_rn(v + p.bias2[nn]);
    }
    return;
  }
  if (p.mode == 4){                           /* atts fp16 flat              */
    Ch[(long)m*p.ldc + n] = __float2half_rn(v); return;
  }
  /* mode 5: wo -> cat fp32 + cat16, permuted, col_off                       */
  long idx = ((long)(m % p.D1)*p.D2 + m/p.D1)*p.ldc + p.col_off + n;
  float o = v + p.bias[n];
  Cf[idx] = o;
  Ch[idx] = __float2half_rn(o);
}

template<int BMT, int DUAL>
__global__ __launch_bounds__(256) void gemm_h16(GH p){
  constexpr int WM   = BMT/32;
  constexpr int NCOL = BN/(8/WM);
  constexpr int NFR  = NCOL/8;
  constexpr int NBL  = NCOL/16;
  constexpr int ABYT = BMT*128;
  constexpr int SBYT = ABYT + BN*128;
  constexpr int GT   = (BMT+BN)*8;

  extern __shared__ float smf[];
  uint32_t sbase = (uint32_t)__cvta_generic_to_shared(smf);
  const __half* A  = p.A + (long)blockIdx.z * p.sA;
  const __half* Bg = p.B + (long)blockIdx.z * p.sB;
  float*  Cf = p.Cf ? p.Cf + (long)blockIdx.z * p.sC : (float*)0;
  __half* Ch = p.Ch ? p.Ch + (long)blockIdx.z * p.sC : (__half*)0;

  int tid = threadIdx.x;
  int lane = tid & 31, warp = tid >> 5;
  int wm = warp % WM, wn = warp / WM;
  int m0 = blockIdx.x * BMT, n0 = blockIdx.y * BN;

  float acc[2][NFR][4];
  #pragma unroll
  for (int i=0;i<2;i++)
    #pragma unroll
    for (int j=0;j<NFR;j++){ acc[i][j][0]=0.f; acc[i][j][1]=0.f; acc[i][j][2]=0.f; acc[i][j][3]=0.f; }

  int ktiles = (p.K + 63)/64;

  auto load = [&](int st, int k0){            /* k0 in halfs */
    uint32_t ab = sbase + st*SBYT;
    uint32_t bb = ab + ABYT;
    #pragma unroll
    for (int i=0;i<GT/256;i++){
      int g = tid + i*256;
      int r = g >> 3, gc = g & 7;
      int kcol = k0 + gc*8;
      int kb = (kcol < p.K) ? 16 : 0;
      if (r < BMT){
        uint32_t soff = (uint32_t)(r*128 + ((gc ^ (r&7))<<4));
        int gm = m0 + r;
        cpa16u(ab + soff, A + (long)gm*p.lda + kcol, (gm < p.M) ? kb : 0);
      } else {
        int rb = r - BMT;
        uint32_t soff = (uint32_t)(rb*128 + ((gc ^ (rb&7))<<4));
        int gn = n0 + rb;
        const __half* src;
        if (DUAL && gn >= HID) src = p.B2 + (long)(gn-HID)*p.ldb + kcol;
        else                   src = Bg  + (long)gn*p.ldb + kcol;
        cpa16u(bb + soff, src, (gn < p.N) ? kb : 0);
      }
    }
  };

  load(0, 0); CPA_COMMIT();
  load(1, 64); CPA_COMMIT();

  int mi1 = (lane >> 3) & 1;
  int kg2 = lane >> 4;
  int ri  = lane & 7;
  int marow = wm*32 + mi1*8 + ri;
  int nbrow = wn*NCOL + mi1*8 + ri;
  int maxor = (marow & 7);
  int nbxor = (nbrow & 7);

  for (int kt = 0; kt < ktiles; kt++){
    if (kt + 2 < ktiles) load((kt+2)%3, (kt+2)*64);
    CPA_COMMIT();
    CPA_WAIT2();
    __syncthreads();

    uint32_t ab = sbase + (kt%3)*SBYT;
    uint32_t aA = ab + marow*128;
    uint32_t aB = ab + ABYT + nbrow*128;

    #pragma unroll
    for (int kk=0; kk<4; kk++){
      uint32_t asw = (uint32_t)(((kk*2 + kg2) ^ maxor) << 4);
      uint32_t bsw = (uint32_t)(((kk*2 + kg2) ^ nbxor) << 4);
      unsigned af0[4], af1[4], bf[NBL][4];
      LDSM_X4(af0[0],af0[1],af0[2],af0[3], aA + asw);
      LDSM_X4(af1[0],af1[1],af1[2],af1[3], aA + asw + 16*128);
      #pragma unroll
      for (int jp=0; jp<NBL; jp++)
        LDSM_X4(bf[jp][0],bf[jp][1],bf[jp][2],bf[jp][3], aB + bsw + jp*16*128);
      #pragma unroll
      for (int jp=0; jp<NBL; jp++){
        MMA16(acc[0][2*jp  ], af0[0],af0[1],af0[2],af0[3], bf[jp][0], bf[jp][2]);
        MMA16(acc[0][2*jp+1], af0[0],af0[1],af0[2],af0[3], bf[jp][1], bf[jp][3]);
        MMA16(acc[1][2*jp  ], af1[0],af1[1],af1[2],af1[3], bf[jp][0], bf[jp][2]);
        MMA16(acc[1][2*jp+1], af1[0],af1[1],af1[2],af1[3], bf[jp][1], bf[jp][3]);
      }
    }
    __syncthreads();
  }

  int r = lane >> 2, c2 = (lane & 3)*2;
  #pragma unroll
  for (int im=0; im<2; im++)
    #pragma unroll
    for (int jn=0; jn<NFR; jn++){
      int mr = m0 + wm*32 + im*16 + r;
      int nc = n0 + wn*NCOL + jn*8 + c2;
      epih(p, Cf, Ch, mr,   nc,   acc[im][jn][0]);
      epih(p, Cf, Ch, mr,   nc+1, acc[im][jn][1]);
      epih(p, Cf, Ch, mr+8, nc,   acc[im][jn][2]);
      epih(p, Cf, Ch, mr+8, nc+1, acc[im][jn][3]);
    }
}

/* ---------------- fp16 converters ---------------------------------------- */
__global__ void conv_wp16(const float* __restrict__ Wp){
  long i = (long)blockIdx.x*blockDim.x + threadIdx.x;
  const long tot = (long)VPAD*(H3/2);
  if (i >= tot) return;
  long row = i / (H3/2);
  long c2  = i % (H3/2);
  __half2* dst = (__half2*)g_wp16;
  if (row < VOC){
    const float2 v = *(const float2*)(Wp + row*H3 + c2*2);
    dst[i] = __floats2half2_rn(v.x, v.y);
  } else {
    dst[i] = __floats2half2_rn(0.f, 0.f);
  }
}
__global__ void conv_h16(const float* __restrict__ h){
  int i = blockIdx.x*blockDim.x + threadIdx.x;
  if (i >= TB*(HID/2)) return;
  const float2 v = *(const float2*)(h + (long)i*2);
  ((__half2*)g_h16)[i] = __floats2half2_rn(v.x, v.y);
}
__global__ void conv_mem16(const float* __restrict__ mem){
  long i = (long)blockIdx.x*blockDim.x + threadIdx.x;
  if (i >= (long)SEQ*BATCH*(HID/2)) return;
  const float2 v = *(const float2*)(mem + i*2);
  ((__half2*)g_mem16)[i] = __floats2half2_rn(v.x, v.y);
}
__global__ void conv_wts16(const float* __restrict__ Wq, const float* __restrict__ Wk,
                           const float* __restrict__ Wv, const float* __restrict__ Wo){
  int i = blockIdx.x*blockDim.x + threadIdx.x;
  const int per = HID*HID/2;
  if (i >= 4*per) return;
  int seg = i / per, off = i % per;
  const float* src = (seg==0)?Wq:(seg==1)?Wk:(seg==2)?Wv:Wo;
  const float2 v = *(const float2*)(src + (long)off*2);
  ((__half2*)g_W416)[i] = __floats2half2_rn(v.x, v.y);
}

/* ====== fp16 Wp GEMM: 128x256 CTA, 512 thr, 32x64 warp tile ============== */
#define WBM 128
#define WBN 256
#define WKI 64
#define WABY (WBM*128)
#define WSBY (WABY + WBN*128)
#define WSMEM (3*WSBY)

__global__ __launch_bounds__(512,1) void gemm_wp16(
    const __half* __restrict__ A, const __half* __restrict__ B,
    const float* __restrict__ bias, float* __restrict__ out)
{
  extern __shared__ float smf[];
  uint32_t sbase = (uint32_t)__cvta_generic_to_shared(smf);
  int tid = threadIdx.x;
  int lane = tid & 31, warp = tid >> 5;
  int wm = warp & 3, wn = warp >> 2;
  int m0 = blockIdx.x * WBM, n0 = blockIdx.y * WBN;

  float acc[2][8][4];
  #pragma unroll
  for (int i=0;i<2;i++)
    #pragma unroll
    for (int j=0;j<8;j++){ acc[i][j][0]=0.f; acc[i][j][1]=0.f; acc[i][j][2]=0.f; acc[i][j][3]=0.f; }

  const int ktiles = H3/WKI;             /* 24 */

  auto load = [&](int st, int k0){
    uint32_t ab = sbase + st*WSBY;
    uint32_t bb = ab + WABY;
    #pragma unroll
    for (int i=0;i<6;i++){
      int g = tid + i*512;
      int r = g >> 3, gc = g & 7;
      int kcol = k0 + gc*8;
      if (r < WBM){
        uint32_t soff = (uint32_t)(r*128 + ((gc ^ (r&7))<<4));
        cpa16u(ab + soff, A + (long)(m0 + r)*H3 + kcol, 16);
      } else {
        int rb = r - WBM;
        uint32_t soff = (uint32_t)(rb*128 + ((gc ^ (rb&7))<<4));
        cpa16u(bb + soff, B + (long)(n0 + rb)*H3 + kcol, 16);
      }
    }
  };

  load(0, 0); CPA_COMMIT();
  load(1, WKI); CPA_COMMIT();

  int mi1 = (lane >> 3) & 1;
  int kg2 = lane >> 4;
  int ri  = lane & 7;
  int marow = wm*32 + mi1*8 + ri;
  int nbrow = wn*64 + mi1*8 + ri;
  int maxor = (marow & 7);
  int nbxor = (nbrow & 7);

  for (int kt = 0; kt < ktiles; kt++){
    if (kt + 2 < ktiles) load((kt+2)%3, (kt+2)*WKI);
    CPA_COMMIT();
    CPA_WAIT2();
    __syncthreads();

    uint32_t ab = sbase + (kt%3)*WSBY;
    uint32_t aA = ab + marow*128;
    uint32_t aB = ab + WABY + nbrow*128;

    #pragma unroll
    for (int kk=0; kk<4; kk++){
      uint32_t asw = (uint32_t)(((kk*2 + kg2) ^ maxor) << 4);
      uint32_t bsw = (uint32_t)(((kk*2 + kg2) ^ nbxor) << 4);
      unsigned af0[4], af1[4], bf[4][4];
      LDSM_X4(af0[0],af0[1],af0[2],af0[3], aA + asw);
      LDSM_X4(af1[0],af1[1],af1[2],af1[3], aA + asw + 16*128);
      #pragma unroll
      for (int jb=0; jb<4; jb++)
        LDSM_X4(bf[jb][0],bf[jb][1],bf[jb][2],bf[jb][3], aB + bsw + jb*16*128);
      #pragma unroll
      for (int jb=0; jb<4; jb++){
        MMA16(acc[0][2*jb  ], af0[0],af0[1],af0[2],af0[3], bf[jb][0], bf[jb][2]);
        MMA16(acc[0][2*jb+1], af0[0],af0[1],af0[2],af0[3], bf[jb][1], bf[jb][3]);
        MMA16(acc[1][2*jb  ], af1[0],af1[1],af1[2],af1[3], bf[jb][0], bf[jb][2]);
        MMA16(acc[1][2*jb+1], af1[0],af1[1],af1[2],af1[3], bf[jb][1], bf[jb][3]);
      }
    }
    __syncthreads();
  }

  int r2 = lane >> 2, c2 = (lane & 3)*2;
  #pragma unroll
  for (int im=0; im<2; im++)
    #pragma unroll
    for (int nj=0; nj<8; nj++){
      int mr = m0 + wm*32 + im*16 + r2;
      int nc = n0 + wn*64 + nj*8 + c2;
      if (nc < VOC){
        float b0 = bias[nc], b1 = bias[nc+1];
        float* o0 = out + (long)mr*VE + nc;
        float* o1 = out + (long)(mr+8)*VE + nc;
        o0[0] = acc[im][nj][0] + b0;  o0[1] = acc[im][nj][1] + b1;
        o1[0] = acc[im][nj][2] + b0;  o1[1] = acc[im][nj][3] + b1;
      }
    }
}

/* -------- cat[:,0:1024] = [h,y_emb] (fp32 + fp16) ------------------------ */
__global__ void cat_copy(const float* __restrict__ h, const float* __restrict__ y){
  int i = blockIdx.x*blockDim.x + threadIdx.x;
  if (i >= TB*(HID/4)) return;
  int row = i / (HID/4);
  int c   = i % (HID/4);
  const float4 hv = ((const float4*)h)[i];
  const float4 yv = ((const float4*)y)[i];
  float4* cat4 = (float4*)g_cat;
  cat4[(long)row*(H3/4) + c]           = hv;
  cat4[(long)row*(H3/4) + (HID/4) + c] = yv;
  __half2* c16 = (__half2*)g_cat16;
  long b = (long)row*(H3/2);
  c16[b + c*2]               = __floats2half2_rn(hv.x, hv.y);
  c16[b + c*2 + 1]           = __floats2half2_rn(hv.z, hv.w);
  c16[b + (HID/2) + c*2]     = __floats2half2_rn(yv.x, yv.y);
  c16[b + (HID/2) + c*2 + 1] = __floats2half2_rn(yv.z, yv.w);
}

/* ------ softmax over S; writes w16 (B,T,S) + dists fp32 (T,B,S) ---------- */
__global__ void softmax_s(float* __restrict__ dists, const unsigned char* __restrict__ mask){
  int bt = blockIdx.x;                  /* b*T + t */
  int b = bt / T_LEN, t = bt % T_LEN;
  float* row = g_w + (long)bt*SEQ;
  const unsigned char* mrow = mask + (long)b*SEQ;
  int tid = threadIdx.x;                /* 128 */
  __shared__ float red[128];
  float mx = -1e30f;
  for (int s=tid; s<SEQ; s+=128){
    float x = mrow[s] ? -1e9f : row[s];
    mx = fmaxf(mx, x);
  }
  red[tid]=mx; __syncthreads();
  for (int off=64; off>0; off>>=1){ if (tid<off) red[tid]=fmaxf(red[tid],red[tid+off]); __syncthreads(); }
  mx = red[0]; __syncthreads();
  float sum=0.f;
  for (int s=tid; s<SEQ; s+=128){
    float x = mrow[s] ? -1e9f : row[s];
    sum += __expf(x-mx);
  }
  red[tid]=sum; __syncthreads();
  for (int off=64; off>0; off>>=1){ if (tid<off) red[tid]+=red[tid+off]; __syncthreads(); }
  float inv = 1.f/red[0];
  for (int s=tid; s<SEQ; s+=128){
    float x = mrow[s] ? -1e9f : row[s];
    float wv = __expf(x-mx)*inv;
    g_w16[(long)bt*SEQ + s] = __float2half_rn(wv);
    dists[((long)t*BATCH + b)*SEQ + s] = wv;
  }
}

/* -------- fused: gate + softmax over V + ext zero + pointer scatter ------ */
__global__ void softmax_v(float* __restrict__ out, const float* __restrict__ dists,
                          const int* __restrict__ xids,
                          const float* __restrict__ vv, const float* __restrict__ bvv){
  int rid = blockIdx.x;                 /* t*B + b */
  int b = rid % BATCH, t = rid / BATCH;
  float* row = out + (long)rid*VE;
  int tid = threadIdx.x;                /* 512 */
  __shared__ float rm[512], rs[512];
  __shared__ float gsh;

  const float* cr = g_cat + (long)rid*H3;
  float s0 = 0.f;
  for (int j=tid; j<H3; j+=512) s0 += cr[j]*vv[j];
  rm[tid]=s0; __syncthreads();
  for (int off=256; off>0; off>>=1){ if (tid<off) rm[tid]+=rm[tid+off]; __syncthreads(); }
  if (tid==0) gsh = 1.f/(1.f+__expf(-(rm[0]+bvv[0])));
  __syncthreads();
  float g = gsh;

  float m = row[tid], s = 1.f;
  for (int j=tid+512; j<VOC; j+=512){
    float x = row[j];
    if (x > m){ s = s*__expf(m-x) + 1.f; m = x; }
    else        s += __expf(x-m);
  }
  rm[tid]=m; rs[tid]=s; __syncthreads();
  for (int off=256; off>0; off>>=1){
    if (tid<off){
      float m2=rm[tid+off], s2=rs[tid+off];
      float M=fmaxf(rm[tid],m2);
      rs[tid]=rs[tid]*__expf(rm[tid]-M)+s2*__expf(m2-M);
      rm[tid]=M;
    }
    __syncthreads();
  }
  float M = rm[0];
  float gscale = g/rs[0];
  for (int j=tid; j<VOC; j+=512) row[j] = __expf(row[j]-M)*gscale;
  for (int j=VOC+tid; j<VE; j+=512) row[j] = 0.f;

  __threadfence(); __syncthreads();

  float omg = 1.f - g;
  const float* drow = dists + ((long)t*BATCH + b)*SEQ;
  for (int si=tid; si<SEQ; si+=512){
    int col = xids[(long)si*BATCH + b];
    atomicAdd(row + col, omg*drow[si]);
  }
}

/* ------------------------------- host ----------------------------------- */
template<int BMT, int DUAL>
static inline void launch_h16(const GH& p, int batches){
  constexpr int SM = 3*((BMT+BN)*128);
  static bool done = false;
  if (!done){
    cudaFuncSetAttribute(gemm_h16<BMT,DUAL>,
                         cudaFuncAttributeMaxDynamicSharedMemorySize, SM);
    done = true;
  }
  dim3 grid((p.M+BMT-1)/BMT, (p.N+BN-1)/BN, batches);
  gemm_h16<BMT,DUAL><<<grid, 256, SM>>>(p);
}

extern "C" void kernel_launch(void* const* d_in, const int* in_sizes, int n_in,
                              void* d_out, int out_size){
  const float* h    = (const float*)d_in[0];
  const float* yemb = (const float*)d_in[1];
  const float* mem  = (const float*)d_in[2];
  const unsigned char* mask = (const unsigned char*)d_in[3];
  const int* xids   = (const int*)d_in[4];
  int wb = 5;
  if (n_in >= 18 && in_sizes[5] == 1) wb = 6;
  const float* Wq = (const float*)d_in[wb+0];
  const float* bq = (const float*)d_in[wb+1];
  const float* Wk = (const float*)d_in[wb+2];
  const float* bk = (const float*)d_in[wb+3];
  const float* Wv = (const float*)d_in[wb+4];
  const float* bva= (const float*)d_in[wb+5];
  const float* Wo = (const float*)d_in[wb+6];
  const float* bo = (const float*)d_in[wb+7];
  const float* Wp = (const float*)d_in[wb+8];
  const float* bp = (const float*)d_in[wb+9];
  const float* vv = (const float*)d_in[wb+10];
  const float* bv = (const float*)d_in[wb+11];

  float* out   = (float*)d_out;
  float* dists = out + (long)TB*VE;

  cudaFuncSetAttribute(gemm_wp16, cudaFuncAttributeMaxDynamicSharedMemorySize, WSMEM);

  void *wbuf, *catp, *cat16p, *wp16p, *h16p, *mem16p, *w4p;
  void *q16p, *k16p, *valT16p, *w16p, *atts16p;
  cudaGetSymbolAddress(&wbuf, g_w);
  cudaGetSymbolAddress(&catp, g_cat);
  cudaGetSymbolAddress(&cat16p, g_cat16);
  cudaGetSymbolAddress(&wp16p, g_wp16);
  cudaGetSymbolAddress(&h16p, g_h16);
  cudaGetSymbolAddress(&mem16p, g_mem16);
  cudaGetSymbolAddress(&w4p, g_W416);
  cudaGetSymbolAddress(&q16p, g_q16);
  cudaGetSymbolAddress(&k16p, g_k16);
  cudaGetSymbolAddress(&valT16p, g_valT16);
  cudaGetSymbolAddress(&w16p, g_w16);
  cudaGetSymbolAddress(&atts16p, g_atts16);

  const __half* W16 = (const __half*)w4p;
  const __half* Wq16 = W16;
  const __half* Wk16 = W16 + (long)HID*HID;
  const __half* Wv16 = W16 + 2L*HID*HID;
  const __half* Wo16 = W16 + 3L*HID*HID;

  float scale = 1.0f/sqrtf((float)HID);

  /* conversions */
  {
    long tot = (long)VPAD*(H3/2);
    conv_wp16<<<(int)((tot + 255)/256), 256>>>(Wp);
  }
  conv_h16<<<(TB*(HID/2)+255)/256, 256>>>(h);
  {
    long tot = (long)SEQ*BATCH*(HID/2);
    conv_mem16<<<(int)((tot+255)/256), 256>>>(mem);
  }
  conv_wts16<<<(4*HID*HID/2+255)/256, 256>>>(Wq, Wk, Wv, Wo);

  /* cat[:,0:1024] = [h, y_emb] (fp32 + fp16) */
  cat_copy<<<(TB*(HID/4)+255)/256, 256>>>(h, yemb);

  GH p;

  /* q16 = (h16@Wq16^T + bq)*scale -> (B,T,H) fp16 */
  p = GH{};
  p.A = (const __half*)h16p; p.B = Wq16; p.Ch = (__half*)q16p;
  p.lda = HID; p.ldb = HID; p.ldc = HID;
  p.M = TB; p.N = HID; p.K = HID;
  p.bias = bq; p.alpha = scale;
  p.mode = 1; p.D1 = BATCH; p.D2 = T_LEN;
  launch_h16<64,0>(p, 1);

  /* fused k & val projection -> k16 (B,S,H), valT16 (B,H,S) */
  p = GH{};
  p.A = (const __half*)mem16p; p.B = Wk16; p.B2 = Wv16;
  p.Ch = (__half*)k16p; p.Ch2 = (__half*)valT16p;
  p.lda = HID; p.ldb = HID;
  p.M = SEQ*BATCH; p.N = 2*HID; p.K = HID;
  p.bias = bk; p.bias2 = bva;
  p.mode = 3;
  launch_h16<128,1>(p, 1);

  /* scores[b]: (T,S) = q16_b @ k16_b^T -> fp32 g_w */
  p = GH{};
  p.A = (const __half*)q16p; p.B = (const __half*)k16p; p.Cf = (float*)wbuf;
  p.lda = HID; p.ldb = HID; p.ldc = SEQ;
  p.sA = (long)T_LEN*HID; p.sB = (long)SEQ*HID; p.sC = (long)T_LEN*SEQ;
  p.M = T_LEN; p.N = SEQ; p.K = HID;
  p.mode = 0;
  launch_h16<64,0>(p, BATCH);

  softmax_s<<<BATCH*T_LEN, 128>>>(dists, mask);

  /* atts16[b]: (T,H) = w16_b @ valT16_b^T -> fp16 */
  p = GH{};
  p.A = (const __half*)w16p; p.B = (const __half*)valT16p; p.Ch = (__half*)atts16p;
  p.lda = SEQ; p.ldb = SEQ; p.ldc = HID;
  p.sA = (long)T_LEN*SEQ; p.sB = (long)HID*SEQ; p.sC = (long)T_LEN*HID;
  p.M = T_LEN; p.N = HID; p.K = SEQ;
  p.mode = 4;
  launch_h16<64,0>(p, BATCH);

  /* cat[:,1024:1536] = atts16@Wo16^T + bo (writes fp32 cat + fp16 cat16) */
  p = GH{};
  p.A = (const __half*)atts16p; p.B = Wo16;
  p.Cf = (float*)catp; p.Ch = (__half*)cat16p;
  p.lda = HID; p.ldb = HID; p.ldc = H3;
  p.M = TB; p.N = HID; p.K = HID;
  p.bias = bo;
  p.mode = 5; p.D1 = T_LEN; p.D2 = BATCH; p.col_off = 1024;
  launch_h16<64,0>(p, 1);

  /* logits = cat16@Wp16^T + bp -> d_out */
  gemm_wp16<<<dim3(TB/WBM, VPAD/WBN), 512, WSMEM>>>(
      (const __half*)cat16p, (const __half*)wp16p, bp, out);

  /* fused gate + softmax over V + ext zero + scatter */
  softmax_v<<<TB, 512>>>(out, dists, xids, vv, bv);

  (void)out_size; (void)n_in;
}

// round 10
// speedup vs baseline: 1.0545x; 1.0545x over previous
#include <cuda_runtime.h>
#include <cuda_fp16.h>
#include <math.h>
#include <stdint.h>

#define T_LEN 64
#define BATCH 32
#define SEQ   400
#define HID   512
#define VOC   50000
#define EXTD  400
#define VE    (VOC+EXTD)
#define TB    (T_LEN*BATCH)     /* 2048 */
#define H3    (3*HID)           /* 1536 */
#define VPAD  50176             /* VOC padded to 256 */
#define NSTRIPE (VPAD/256)      /* 196 */

/* ---------------- scratch (device globals: allocation-free) -------------- */
__device__ float  g_cat [TB*H3];              /* (T*B,3H) fp32 (gate)        */
__device__ float  g_w   [BATCH*T_LEN*SEQ];    /* scores fp32 (B,T,S)         */
__device__ __half g_cat16[TB*H3];
__device__ __half g_wp16 [(long)VPAD*H3];
__device__ __half g_h16  [TB*HID];
__device__ __half g_mem16[SEQ*BATCH*HID];
__device__ __half g_W416 [4*HID*HID];         /* Wq,Wk,Wv,Wo                 */
__device__ __half g_q16  [BATCH*T_LEN*HID];   /* (B,T,H)                     */
__device__ __half g_k16  [BATCH*SEQ*HID];     /* (B,S,H)                     */
__device__ __half g_valT16[BATCH*HID*SEQ];    /* (B,H,S)                     */
__device__ __half g_w16  [BATCH*T_LEN*SEQ];   /* attn weights fp16           */
__device__ __half g_atts16[TB*HID];           /* (B,T,H) rows b*T+t          */
__device__ __half g_l16  [(long)TB*VPAD];     /* fp16 logits                 */
__device__ float  g_pm   [NSTRIPE*TB];        /* per-stripe softmax max      */
__device__ float  g_ps   [NSTRIPE*TB];        /* per-stripe softmax sum      */

#define BN 128

__device__ __forceinline__ void cpa16u(unsigned dst, const void* src, int bytes){
  asm volatile("cp.async.cg.shared.global [%0], [%1], 16, %2;\n"
               :: "r"(dst), "l"(src), "r"(bytes));
}
#define CPA_COMMIT() asm volatile("cp.async.commit_group;\n")
#define CPA_WAIT2()  asm volatile("cp.async.wait_group 2;\n")
#define CPA_WAIT3()  asm volatile("cp.async.wait_group 3;\n")

#define LDSM_X4(r0,r1,r2,r3,addr) \
  asm volatile("ldmatrix.sync.aligned.m8n8.x4.shared.b16 {%0,%1,%2,%3}, [%4];" \
               : "=r"(r0), "=r"(r1), "=r"(r2), "=r"(r3) : "r"(addr))

#define MMA16(d, a0,a1,a2,a3, b0,b1) \
  asm volatile("mma.sync.aligned.m16n8k16.row.col.f32.f16.f16.f32 " \
               "{%0,%1,%2,%3}, {%4,%5,%6,%7}, {%8,%9}, {%0,%1,%2,%3};\n" \
               : "+f"((d)[0]), "+f"((d)[1]), "+f"((d)[2]), "+f"((d)[3]) \
               : "r"(a0), "r"(a1), "r"(a2), "r"(a3), "r"(b0), "r"(b1))

/* ---------------- generic fp16 MMA GEMM --------------------------------- */
struct GH {
  const __half* A; const __half* B; const __half* B2;
  float* Cf; __half* Ch; __half* Ch2;
  long lda, ldb, ldc;
  long sA, sB, sC;
  int  M, N, K;
  const float* bias; const float* bias2;
  float alpha;
  int  mode, D1, D2;
  long col_off;
};

__device__ __forceinline__ void epih(const GH& p, float* Cf, __half* Ch,
                                     int m, int n, float v){
  if (m >= p.M || n >= p.N) return;
  if (p.mode == 0){                           /* scores fp32 flat            */
    Cf[(long)m*p.ldc + n] = v; return;
  }
  if (p.mode == 1){                           /* q fp16 permuted + bias*alpha*/
    long idx = ((long)(m % p.D1)*p.D2 + m/p.D1)*p.ldc + n;
    Ch[idx] = __float2half_rn(p.alpha*(v + p.bias[n])); return;
  }
  if (p.mode == 3){                           /* dual k/val fp16             */
    int s = m / BATCH, b = m % BATCH;
    if (n < HID)
      p.Ch[((long)b*SEQ + s)*HID + n] = __float2half_rn(v + p.bias[n]);
    else {
      int nn = n - HID;
      p.Ch2[((long)b*HID + nn)*SEQ + s] = __float2half_rn(v + p.bias2[nn]);
    }
    return;
  }
  if (p.mode == 4){                           /* atts fp16 flat              */
    Ch[(long)m*p.ldc + n] = __float2half_rn(v); return;
  }
  /* mode 5: wo -> cat fp32 + cat16, permuted, col_off                       */
  long idx = ((long)(m % p.D1)*p.D2 + m/p.D1)*p.ldc + p.col_off + n;
  float o = v + p.bias[n];
  Cf[idx] = o;
  Ch[idx] = __float2half_rn(o);
}

template<int BMT, int DUAL>
__global__ __launch_bounds__(256) void gemm_h16(GH p){
  constexpr int WM   = BMT/32;
  constexpr int NCOL = BN/(8/WM);
  constexpr int NFR  = NCOL/8;
  constexpr int NBL  = NCOL/16;
  constexpr int ABYT = BMT*128;
  constexpr int SBYT = ABYT + BN*128;
  constexpr int GT   = (BMT+BN)*8;

  extern __shared__ float smf[];
  uint32_t sbase = (uint32_t)__cvta_generic_to_shared(smf);
  const __half* A  = p.A + (long)blockIdx.z * p.sA;
  const __half* Bg = p.B + (long)blockIdx.z * p.sB;
  float*  Cf = p.Cf ? p.Cf + (long)blockIdx.z * p.sC : (float*)0;
  __half* Ch = p.Ch ? p.Ch + (long)blockIdx.z * p.sC : (__half*)0;

  int tid = threadIdx.x;
  int lane = tid & 31, warp = tid >> 5;
  int wm = warp % WM, wn = warp / WM;
  int m0 = blockIdx.x * BMT, n0 = blockIdx.y * BN;

  float acc[2][NFR][4];
  #pragma unroll
  for (int i=0;i<2;i++)
    #pragma unroll
    for (int j=0;j<NFR;j++){ acc[i][j][0]=0.f; acc[i][j][1]=0.f; acc[i][j][2]=0.f; acc[i][j][3]=0.f; }

  int ktiles = (p.K + 63)/64;

  auto load = [&](int st, int k0){
    uint32_t ab = sbase + st*SBYT;
    uint32_t bb = ab + ABYT;
    #pragma unroll
    for (int i=0;i<GT/256;i++){
      int g = tid + i*256;
      int r = g >> 3, gc = g & 7;
      int kcol = k0 + gc*8;
      int kb = (kcol < p.K) ? 16 : 0;
      if (r < BMT){
        uint32_t soff = (uint32_t)(r*128 + ((gc ^ (r&7))<<4));
        int gm = m0 + r;
        cpa16u(ab + soff, A + (long)gm*p.lda + kcol, (gm < p.M) ? kb : 0);
      } else {
        int rb = r - BMT;
        uint32_t soff = (uint32_t)(rb*128 + ((gc ^ (rb&7))<<4));
        int gn = n0 + rb;
        const __half* src;
        if (DUAL && gn >= HID) src = p.B2 + (long)(gn-HID)*p.ldb + kcol;
        else                   src = Bg  + (long)gn*p.ldb + kcol;
        cpa16u(bb + soff, src, (gn < p.N) ? kb : 0);
      }
    }
  };

  load(0, 0); CPA_COMMIT();
  load(1, 64); CPA_COMMIT();

  int mi1 = (lane >> 3) & 1;
  int kg2 = lane >> 4;
  int ri  = lane & 7;
  int marow = wm*32 + mi1*8 + ri;
  int nbrow = wn*NCOL + mi1*8 + ri;
  int maxor = (marow & 7);
  int nbxor = (nbrow & 7);

  for (int kt = 0; kt < ktiles; kt++){
    if (kt + 2 < ktiles) load((kt+2)%3, (kt+2)*64);
    CPA_COMMIT();
    CPA_WAIT2();
    __syncthreads();

    uint32_t ab = sbase + (kt%3)*SBYT;
    uint32_t aA = ab + marow*128;
    uint32_t aB = ab + ABYT + nbrow*128;

    #pragma unroll
    for (int kk=0; kk<4; kk++){
      uint32_t asw = (uint32_t)(((kk*2 + kg2) ^ maxor) << 4);
      uint32_t bsw = (uint32_t)(((kk*2 + kg2) ^ nbxor) << 4);
      unsigned af0[4], af1[4], bf[NBL][4];
      LDSM_X4(af0[0],af0[1],af0[2],af0[3], aA + asw);
      LDSM_X4(af1[0],af1[1],af1[2],af1[3], aA + asw + 16*128);
      #pragma unroll
      for (int jp=0; jp<NBL; jp++)
        LDSM_X4(bf[jp][0],bf[jp][1],bf[jp][2],bf[jp][3], aB + bsw + jp*16*128);
      #pragma unroll
      for (int jp=0; jp<NBL; jp++){
        MMA16(acc[0][2*jp  ], af0[0],af0[1],af0[2],af0[3], bf[jp][0], bf[jp][2]);
        MMA16(acc[0][2*jp+1], af0[0],af0[1],af0[2],af0[3], bf[jp][1], bf[jp][3]);
        MMA16(acc[1][2*jp  ], af1[0],af1[1],af1[2],af1[3], bf[jp][0], bf[jp][2]);
        MMA16(acc[1][2*jp+1], af1[0],af1[1],af1[2],af1[3], bf[jp][1], bf[jp][3]);
      }
    }
    __syncthreads();
  }

  int r = lane >> 2, c2 = (lane & 3)*2;
  #pragma unroll
  for (int im=0; im<2; im++)
    #pragma unroll
    for (int jn=0; jn<NFR; jn++){
      int mr = m0 + wm*32 + im*16 + r;
      int nc = n0 + wn*NCOL + jn*8 + c2;
      epih(p, Cf, Ch, mr,   nc,   acc[im][jn][0]);
      epih(p, Cf, Ch, mr,   nc+1, acc[im][jn][1]);
      epih(p, Cf, Ch, mr+8, nc,   acc[im][jn][2]);
      epih(p, Cf, Ch, mr+8, nc+1, acc[im][jn][3]);
    }
}

/* ---------------- fp16 converters ---------------------------------------- */
__global__ void conv_wp16(const float* __restrict__ Wp){
  long i = (long)blockIdx.x*blockDim.x + threadIdx.x;
  const long tot = (long)VPAD*(H3/2);
  if (i >= tot) return;
  long row = i / (H3/2);
  long c2  = i % (H3/2);
  __half2* dst = (__half2*)g_wp16;
  if (row < VOC){
    const float2 v = *(const float2*)(Wp + row*H3 + c2*2);
    dst[i] = __floats2half2_rn(v.x, v.y);
  } else {
    dst[i] = __floats2half2_rn(0.f, 0.f);
  }
}
__global__ void conv_mem16(const float* __restrict__ mem){
  long i = (long)blockIdx.x*blockDim.x + threadIdx.x;
  if (i >= (long)SEQ*BATCH*(HID/2)) return;
  const float2 v = *(const float2*)(mem + i*2);
  ((__half2*)g_mem16)[i] = __floats2half2_rn(v.x, v.y);
}
__global__ void conv_wts16(const float* __restrict__ Wq, const float* __restrict__ Wk,
                           const float* __restrict__ Wv, const float* __restrict__ Wo){
  int i = blockIdx.x*blockDim.x + threadIdx.x;
  const int per = HID*HID/2;
  if (i >= 4*per) return;
  int seg = i / per, off = i % per;
  const float* src = (seg==0)?Wq:(seg==1)?Wk:(seg==2)?Wv:Wo;
  const float2 v = *(const float2*)(src + (long)off*2);
  ((__half2*)g_W416)[i] = __floats2half2_rn(v.x, v.y);
}

/* ====== fp16 Wp GEMM: 128x256 CTA, 512 thr, 4-stage, fused softmax stats = */
#define WBM 128
#define WBN 256
#define WKI 64
#define WABY (WBM*128)
#define WSBY (WABY + WBN*128)
#define WSMEM (4*WSBY)                  /* 196608 */

__device__ __forceinline__ void merge_ms(float& m, float& s, float m2, float s2){
  float M = fmaxf(m, m2);
  s = s*__expf(m-M) + s2*__expf(m2-M);
  m = M;
}

__global__ __launch_bounds__(512,1) void gemm_wp16(
    const __half* __restrict__ A, const __half* __restrict__ B,
    const float* __restrict__ bias, __half* __restrict__ l16,
    float* __restrict__ pm, float* __restrict__ ps)
{
  extern __shared__ float smf[];
  __shared__ float red_m[4][128], red_s[4][128];
  uint32_t sbase = (uint32_t)__cvta_generic_to_shared(smf);
  int tid = threadIdx.x;
  int lane = tid & 31, warp = tid >> 5;
  int wm = warp & 3, wn = warp >> 2;
  int m0 = blockIdx.x * WBM, n0 = blockIdx.y * WBN;

  float acc[2][8][4];
  #pragma unroll
  for (int i=0;i<2;i++)
    #pragma unroll
    for (int j=0;j<8;j++){ acc[i][j][0]=0.f; acc[i][j][1]=0.f; acc[i][j][2]=0.f; acc[i][j][3]=0.f; }

  const int ktiles = H3/WKI;             /* 24 */

  auto load = [&](int st, int k0){
    uint32_t ab = sbase + st*WSBY;
    uint32_t bb = ab + WABY;
    #pragma unroll
    for (int i=0;i<6;i++){
      int g = tid + i*512;
      int r = g >> 3, gc = g & 7;
      int kcol = k0 + gc*8;
      if (r < WBM){
        uint32_t soff = (uint32_t)(r*128 + ((gc ^ (r&7))<<4));
        cpa16u(ab + soff, A + (long)(m0 + r)*H3 + kcol, 16);
      } else {
        int rb = r - WBM;
        uint32_t soff = (uint32_t)(rb*128 + ((gc ^ (rb&7))<<4));
        cpa16u(bb + soff, B + (long)(n0 + rb)*H3 + kcol, 16);
      }
    }
  };

  load(0, 0); CPA_COMMIT();
  load(1, WKI); CPA_COMMIT();
  load(2, 2*WKI); CPA_COMMIT();

  int mi1 = (lane >> 3) & 1;
  int kg2 = lane >> 4;
  int ri  = lane & 7;
  int marow = wm*32 + mi1*8 + ri;
  int nbrow = wn*64 + mi1*8 + ri;
  int maxor = (marow & 7);
  int nbxor = (nbrow & 7);

  for (int kt = 0; kt < ktiles; kt++){
    if (kt + 3 < ktiles) load((kt+3)&3, (kt+3)*WKI);
    CPA_COMMIT();
    CPA_WAIT3();
    __syncthreads();

    uint32_t ab = sbase + (kt&3)*WSBY;
    uint32_t aA = ab + marow*128;
    uint32_t aB = ab + WABY + nbrow*128;

    #pragma unroll
    for (int kk=0; kk<4; kk++){
      uint32_t asw = (uint32_t)(((kk*2 + kg2) ^ maxor) << 4);
      uint32_t bsw = (uint32_t)(((kk*2 + kg2) ^ nbxor) << 4);
      unsigned af0[4], af1[4], bf[4][4];
      LDSM_X4(af0[0],af0[1],af0[2],af0[3], aA + asw);
      LDSM_X4(af1[0],af1[1],af1[2],af1[3], aA + asw + 16*128);
      #pragma unroll
      for (int jb=0; jb<4; jb++)
        LDSM_X4(bf[jb][0],bf[jb][1],bf[jb][2],bf[jb][3], aB + bsw + jb*16*128);
      #pragma unroll
      for (int jb=0; jb<4; jb++){
        MMA16(acc[0][2*jb  ], af0[0],af0[1],af0[2],af0[3], bf[jb][0], bf[jb][2]);
        MMA16(acc[0][2*jb+1], af0[0],af0[1],af0[2],af0[3], bf[jb][1], bf[jb][3]);
        MMA16(acc[1][2*jb  ], af1[0],af1[1],af1[2],af1[3], bf[jb][0], bf[jb][2]);
        MMA16(acc[1][2*jb+1], af1[0],af1[1],af1[2],af1[3], bf[jb][1], bf[jb][3]);
      }
    }
    __syncthreads();
  }

  /* epilogue: add bias, write fp16 logits, accumulate (max, sumexp) per row */
  int r2 = lane >> 2, c2 = (lane & 3)*2;
  #pragma unroll
  for (int im=0; im<2; im++){
    int mr = m0 + wm*32 + im*16 + r2;
    float m0v=-1e30f, m1v=-1e30f, s0v=0.f, s1v=0.f;
    #pragma unroll
    for (int nj=0; nj<8; nj++){
      int nc = n0 + wn*64 + nj*8 + c2;
      if (nc < VOC){
        float b0 = bias[nc], b1 = bias[nc+1];
        float v00 = acc[im][nj][0]+b0, v01 = acc[im][nj][1]+b1;
        float v10 = acc[im][nj][2]+b0, v11 = acc[im][nj][3]+b1;
        acc[im][nj][0]=v00; acc[im][nj][1]=v01;
        acc[im][nj][2]=v10; acc[im][nj][3]=v11;
        *(__half2*)(l16 + (long)mr*VPAD + nc)     = __floats2half2_rn(v00,v01);
        *(__half2*)(l16 + (long)(mr+8)*VPAD + nc) = __floats2half2_rn(v10,v11);
        m0v = fmaxf(m0v, fmaxf(v00,v01));
        m1v = fmaxf(m1v, fmaxf(v10,v11));
      }
    }
    #pragma unroll
    for (int nj=0; nj<8; nj++){
      int nc = n0 + wn*64 + nj*8 + c2;
      if (nc < VOC){
        s0v += __expf(acc[im][nj][0]-m0v) + __expf(acc[im][nj][1]-m0v);
        s1v += __expf(acc[im][nj][2]-m1v) + __expf(acc[im][nj][3]-m1v);
      }
    }
    /* reduce across the 4 lanes sharing this row (lane&3 = c2 group) */
    #pragma unroll
    for (int off=1; off<4; off<<=1){
      float om0 = __shfl_xor_sync(0xFFFFFFFFu, m0v, off);
      float os0 = __shfl_xor_sync(0xFFFFFFFFu, s0v, off);
      merge_ms(m0v, s0v, om0, os0);
      float om1 = __shfl_xor_sync(0xFFFFFFFFu, m1v, off);
      float os1 = __shfl_xor_sync(0xFFFFFFFFu, s1v, off);
      merge_ms(m1v, s1v, om1, os1);
    }
    if ((lane & 3) == 0){
      int rl = wm*32 + im*16 + r2;
      red_m[wn][rl]   = m0v; red_s[wn][rl]   = s0v;
      red_m[wn][rl+8] = m1v; red_s[wn][rl+8] = s1v;
    }
  }
  __syncthreads();
  if (tid < 128){
    float M = red_m[0][tid], S = red_s[0][tid];
    #pragma unroll
    for (int w=1; w<4; w++) merge_ms(M, S, red_m[w][tid], red_s[w][tid]);
    pm[(long)blockIdx.y*TB + m0 + tid] = M;
    ps[(long)blockIdx.y*TB + m0 + tid] = S;
  }
}

/* -------- cat[:,0:1024] = [h,y_emb] (fp32 + fp16) + h16 ------------------ */
__global__ void cat_copy(const float* __restrict__ h, const float* __restrict__ y){
  int i = blockIdx.x*blockDim.x + threadIdx.x;
  if (i >= TB*(HID/4)) return;
  int row = i / (HID/4);
  int c   = i % (HID/4);
  const float4 hv = ((const float4*)h)[i];
  const float4 yv = ((const float4*)y)[i];
  float4* cat4 = (float4*)g_cat;
  cat4[(long)row*(H3/4) + c]           = hv;
  cat4[(long)row*(H3/4) + (HID/4) + c] = yv;
  __half2* c16 = (__half2*)g_cat16;
  long b = (long)row*(H3/2);
  __half2 h01 = __floats2half2_rn(hv.x, hv.y);
  __half2 h23 = __floats2half2_rn(hv.z, hv.w);
  c16[b + c*2]               = h01;
  c16[b + c*2 + 1]           = h23;
  c16[b + (HID/2) + c*2]     = __floats2half2_rn(yv.x, yv.y);
  c16[b + (HID/2) + c*2 + 1] = __floats2half2_rn(yv.z, yv.w);
  __half2* h16 = (__half2*)g_h16;
  h16[i*2]   = h01;
  h16[i*2+1] = h23;
}

/* ------ softmax over S; writes w16 (B,T,S) + dists fp32 (T,B,S) ---------- */
__global__ void softmax_s(float* __restrict__ dists, const unsigned char* __restrict__ mask){
  int bt = blockIdx.x;                  /* b*T + t */
  int b = bt / T_LEN, t = bt % T_LEN;
  float* row = g_w + (long)bt*SEQ;
  const unsigned char* mrow = mask + (long)b*SEQ;
  int tid = threadIdx.x;                /* 128 */
  __shared__ float red[128];
  float mx = -1e30f;
  for (int s=tid; s<SEQ; s+=128){
    float x = mrow[s] ? -1e9f : row[s];
    mx = fmaxf(mx, x);
  }
  red[tid]=mx; __syncthreads();
  for (int off=64; off>0; off>>=1){ if (tid<off) red[tid]=fmaxf(red[tid],red[tid+off]); __syncthreads(); }
  mx = red[0]; __syncthreads();
  float sum=0.f;
  for (int s=tid; s<SEQ; s+=128){
    float x = mrow[s] ? -1e9f : row[s];
    sum += __expf(x-mx);
  }
  red[tid]=sum; __syncthreads();
  for (int off=64; off>0; off>>=1){ if (tid<off) red[tid]+=red[tid+off]; __syncthreads(); }
  float inv = 1.f/red[0];
  for (int s=tid; s<SEQ; s+=128){
    float x = mrow[s] ? -1e9f : row[s];
    float wv = __expf(x-mx)*inv;
    g_w16[(long)bt*SEQ + s] = __float2half_rn(wv);
    dists[((long)t*BATCH + b)*SEQ + s] = wv;
  }
}

/* -------- fused: gate + final softmax (from partials) + scatter ---------- */
__global__ void softmax_v(float* __restrict__ out, const float* __restrict__ dists,
                          const int* __restrict__ xids,
                          const float* __restrict__ vv, const float* __restrict__ bvv){
  int rid = blockIdx.x;                 /* t*B + b */
  int b = rid % BATCH, t = rid / BATCH;
  float* row = out + (long)rid*VE;
  int tid = threadIdx.x;                /* 512 */
  __shared__ float rm[512], rs[512];
  __shared__ float gsh;

  /* gate = sigmoid(cat[rid] . v + bv) */
  const float* cr = g_cat + (long)rid*H3;
  float s0 = 0.f;
  for (int j=tid; j<H3; j+=512) s0 += cr[j]*vv[j];
  rm[tid]=s0; __syncthreads();
  for (int off=256; off>0; off>>=1){ if (tid<off) rm[tid]+=rm[tid+off]; __syncthreads(); }
  if (tid==0) gsh = 1.f/(1.f+__expf(-(rm[0]+bvv[0])));
  __syncthreads();
  float g = gsh;

  /* combine per-stripe (m,s) partials */
  float m = -1e30f, s = 0.f;
  if (tid < NSTRIPE){
    m = g_pm[(long)tid*TB + rid];
    s = g_ps[(long)tid*TB + rid];
  }
  rm[tid]=m; rs[tid]=s; __syncthreads();
  for (int off=256; off>0; off>>=1){
    if (tid<off){
      float m2=rm[tid+off], s2=rs[tid+off];
      float M=fmaxf(rm[tid],m2);
      rs[tid]=rs[tid]*__expf(rm[tid]-M)+s2*__expf(m2-M);
      rm[tid]=M;
    }
    __syncthreads();
  }
  float M = rm[0];
  float gscale = g/rs[0];

  /* single pass: fp16 logit -> fp32 prob */
  const __half* lrow = g_l16 + (long)rid*VPAD;
  for (int j=tid; j<VOC; j+=512)
    row[j] = __expf(__half2float(lrow[j]) - M)*gscale;
  for (int j=VOC+tid; j<VE; j+=512) row[j] = 0.f;

  __threadfence(); __syncthreads();

  float omg = 1.f - g;
  const float* drow = dists + ((long)t*BATCH + b)*SEQ;
  for (int si=tid; si<SEQ; si+=512){
    int col = xids[(long)si*BATCH + b];
    atomicAdd(row + col, omg*drow[si]);
  }
}

/* ------------------------------- host ----------------------------------- */
template<int BMT, int DUAL>
static inline void launch_h16(const GH& p, int batches){
  constexpr int SM = 3*((BMT+BN)*128);
  static bool done = false;
  if (!done){
    cudaFuncSetAttribute(gemm_h16<BMT,DUAL>,
                         cudaFuncAttributeMaxDynamicSharedMemorySize, SM);
    done = true;
  }
  dim3 grid((p.M+BMT-1)/BMT, (p.N+BN-1)/BN, batches);
  gemm_h16<BMT,DUAL><<<grid, 256, SM>>>(p);
}

extern "C" void kernel_launch(void* const* d_in, const int* in_sizes, int n_in,
                              void* d_out, int out_size){
  const float* h    = (const float*)d_in[0];
  const float* yemb = (const float*)d_in[1];
  const float* mem  = (const float*)d_in[2];
  const unsigned char* mask = (const unsigned char*)d_in[3];
  const int* xids   = (const int*)d_in[4];
  int wb = 5;
  if (n_in >= 18 && in_sizes[5] == 1) wb = 6;
  const float* Wq = (const float*)d_in[wb+0];
  const float* bq = (const float*)d_in[wb+1];
  const float* Wk = (const float*)d_in[wb+2];
  const float* bk = (const float*)d_in[wb+3];
  const float* Wv = (const float*)d_in[wb+4];
  const float* bva= (const float*)d_in[wb+5];
  const float* Wo = (const float*)d_in[wb+6];
  const float* bo = (const float*)d_in[wb+7];
  const float* Wp = (const float*)d_in[wb+8];
  const float* bp = (const float*)d_in[wb+9];
  const float* vv = (const float*)d_in[wb+10];
  const float* bv = (const float*)d_in[wb+11];

  float* out   = (float*)d_out;
  float* dists = out + (long)TB*VE;

  cudaFuncSetAttribute(gemm_wp16, cudaFuncAttributeMaxDynamicSharedMemorySize, WSMEM);

  void *wbuf, *catp, *cat16p, *wp16p, *h16p, *mem16p, *w4p;
  void *q16p, *k16p, *valT16p, *w16p, *atts16p, *l16p, *pmp, *psp;
  cudaGetSymbolAddress(&wbuf, g_w);
  cudaGetSymbolAddress(&catp, g_cat);
  cudaGetSymbolAddress(&cat16p, g_cat16);
  cudaGetSymbolAddress(&wp16p, g_wp16);
  cudaGetSymbolAddress(&h16p, g_h16);
  cudaGetSymbolAddress(&mem16p, g_mem16);
  cudaGetSymbolAddress(&w4p, g_W416);
  cudaGetSymbolAddress(&q16p, g_q16);
  cudaGetSymbolAddress(&k16p, g_k16);
  cudaGetSymbolAddress(&valT16p, g_valT16);
  cudaGetSymbolAddress(&w16p, g_w16);
  cudaGetSymbolAddress(&atts16p, g_atts16);
  cudaGetSymbolAddress(&l16p, g_l16);
  cudaGetSymbolAddress(&pmp, g_pm);
  cudaGetSymbolAddress(&psp, g_ps);

  const __half* W16 = (const __half*)w4p;
  const __half* Wq16 = W16;
  const __half* Wk16 = W16 + (long)HID*HID;
  const __half* Wv16 = W16 + 2L*HID*HID;
  const __half* Wo16 = W16 + 3L*HID*HID;

  float scale = 1.0f/sqrtf((float)HID);

  /* conversions */
  {
    long tot = (long)VPAD*(H3/2);
    conv_wp16<<<(int)((tot + 255)/256), 256>>>(Wp);
  }
  {
    long tot = (long)SEQ*BATCH*(HID/2);
    conv_mem16<<<(int)((tot+255)/256), 256>>>(mem);
  }
  conv_wts16<<<(4*HID*HID/2+255)/256, 256>>>(Wq, Wk, Wv, Wo);

  /* cat[:,0:1024] = [h, y_emb] (fp32 + fp16) + h16 */
  cat_copy<<<(TB*(HID/4)+255)/256, 256>>>(h, yemb);

  GH p;

  /* q16 = (h16@Wq16^T + bq)*scale -> (B,T,H) fp16 */
  p = GH{};
  p.A = (const __half*)h16p; p.B = Wq16; p.Ch = (__half*)q16p;
  p.lda = HID; p.ldb = HID; p.ldc = HID;
  p.M = TB; p.N = HID; p.K = HID;
  p.bias = bq; p.alpha = scale;
  p.mode = 1; p.D1 = BATCH; p.D2 = T_LEN;
  launch_h16<64,0>(p, 1);

  /* fused k & val projection -> k16 (B,S,H), valT16 (B,H,S) */
  p = GH{};
  p.A = (const __half*)mem16p; p.B = Wk16; p.B2 = Wv16;
  p.Ch = (__half*)k16p; p.Ch2 = (__half*)valT16p;
  p.lda = HID; p.ldb = HID;
  p.M = SEQ*BATCH; p.N = 2*HID; p.K = HID;
  p.bias = bk; p.bias2 = bva;
  p.mode = 3;
  launch_h16<128,1>(p, 1);

  /* scores[b]: (T,S) = q16_b @ k16_b^T -> fp32 g_w */
  p = GH{};
  p.A = (const __half*)q16p; p.B = (const __half*)k16p; p.Cf = (float*)wbuf;
  p.lda = HID; p.ldb = HID; p.ldc = SEQ;
  p.sA = (long)T_LEN*HID; p.sB = (long)SEQ*HID; p.sC = (long)T_LEN*SEQ;
  p.M = T_LEN; p.N = SEQ; p.K = HID;
  p.mode = 0;
  launch_h16<64,0>(p, BATCH);

  softmax_s<<<BATCH*T_LEN, 128>>>(dists, mask);

  /* atts16[b]: (T,H) = w16_b @ valT16_b^T -> fp16 */
  p = GH{};
  p.A = (const __half*)w16p; p.B = (const __half*)valT16p; p.Ch = (__half*)atts16p;
  p.lda = SEQ; p.ldb = SEQ; p.ldc = HID;
  p.sA = (long)T_LEN*SEQ; p.sB = (long)HID*SEQ; p.sC = (long)T_LEN*HID;
  p.M = T_LEN; p.N = HID; p.K = SEQ;
  p.mode = 4;
  launch_h16<64,0>(p, BATCH);

  /* cat[:,1024:1536] = atts16@Wo16^T + bo (writes fp32 cat + fp16 cat16) */
  p = GH{};
  p.A = (const __half*)atts16p; p.B = Wo16;
  p.Cf = (float*)catp; p.Ch = (__half*)cat16p;
  p.lda = HID; p.ldb = HID; p.ldc = H3;
  p.M = TB; p.N = HID; p.K = HID;
  p.bias = bo;
  p.mode = 5; p.D1 = T_LEN; p.D2 = BATCH; p.col_off = 1024;
  launch_h16<64,0>(p, 1);

  /* logits = cat16@Wp16^T + bp -> fp16 l16 + per-stripe (m,s) partials */
  gemm_wp16<<<dim3(TB/WBM, VPAD/WBN), 512, WSMEM>>>(
      (const __half*)cat16p, (const __half*)wp16p, bp,
      (__half*)l16p, (float*)pmp, (float*)psp);

  /* fused gate + final softmax + ext zero + scatter */
  softmax_v<<<TB, 512>>>(out, dists, xids, vv, bv);

  (void)out_size; (void)n_in;
}

// round 11
// speedup vs baseline: 1.1311x; 1.0727x over previous
#include <cuda_runtime.h>
#include <cuda_fp16.h>
#include <math.h>
#include <stdint.h>

#define T_LEN 64
#define BATCH 32
#define SEQ   400
#define HID   512
#define VOC   50000
#define EXTD  400
#define VE    (VOC+EXTD)
#define TB    (T_LEN*BATCH)     /* 2048 */
#define H3    (3*HID)           /* 1536 */
#define VPAD  50176             /* VOC padded to 256 */
#define NSTRIPE (VPAD/128)      /* 392 */

/* ---------------- scratch (device globals: allocation-free) -------------- */
__device__ float  g_cat [TB*H3];              /* (T*B,3H) fp32 (gate)        */
__device__ float  g_w   [BATCH*T_LEN*SEQ];    /* scores fp32 (B,T,S)         */
__device__ __half g_cat16[TB*H3];
__device__ __half g_wp16 [(long)VPAD*H3];
__device__ __half g_h16  [TB*HID];
__device__ __half g_mem16[SEQ*BATCH*HID];
__device__ __half g_W416 [4*HID*HID];         /* Wq,Wk,Wv,Wo                 */
__device__ __half g_q16  [BATCH*T_LEN*HID];   /* (B,T,H)                     */
__device__ __half g_k16  [BATCH*SEQ*HID];     /* (B,S,H)                     */
__device__ __half g_valT16[BATCH*HID*SEQ];    /* (B,H,S)                     */
__device__ __half g_w16  [BATCH*T_LEN*SEQ];   /* attn weights fp16           */
__device__ __half g_atts16[TB*HID];           /* (B,T,H) rows b*T+t          */
__device__ __half g_l16  [(long)TB*VPAD];     /* fp16 logits                 */
__device__ float  g_pm   [NSTRIPE*TB];        /* per-stripe softmax max      */
__device__ float  g_ps   [NSTRIPE*TB];        /* per-stripe softmax sum      */

#define BN 128

__device__ __forceinline__ void cpa16u(unsigned dst, const void* src, int bytes){
  asm volatile("cp.async.cg.shared.global [%0], [%1], 16, %2;\n"
               :: "r"(dst), "l"(src), "r"(bytes));
}
#define CPA_COMMIT() asm volatile("cp.async.commit_group;\n")
#define CPA_WAIT2()  asm volatile("cp.async.wait_group 2;\n")

#define LDSM_X4(r0,r1,r2,r3,addr) \
  asm volatile("ldmatrix.sync.aligned.m8n8.x4.shared.b16 {%0,%1,%2,%3}, [%4];" \
               : "=r"(r0), "=r"(r1), "=r"(r2), "=r"(r3) : "r"(addr))

#define MMA16(d, a0,a1,a2,a3, b0,b1) \
  asm volatile("mma.sync.aligned.m16n8k16.row.col.f32.f16.f16.f32 " \
               "{%0,%1,%2,%3}, {%4,%5,%6,%7}, {%8,%9}, {%0,%1,%2,%3};\n" \
               : "+f"((d)[0]), "+f"((d)[1]), "+f"((d)[2]), "+f"((d)[3]) \
               : "r"(a0), "r"(a1), "r"(a2), "r"(a3), "r"(b0), "r"(b1))

/* ---------------- generic fp16 MMA GEMM --------------------------------- */
struct GH {
  const __half* A; const __half* B; const __half* B2;
  float* Cf; __half* Ch; __half* Ch2;
  long lda, ldb, ldc;
  long sA, sB, sC;
  int  M, N, K;
  const float* bias; const float* bias2;
  float alpha;
  int  mode, D1, D2;
  long col_off;
};

__device__ __forceinline__ void epih(const GH& p, float* Cf, __half* Ch,
                                     int m, int n, float v){
  if (m >= p.M || n >= p.N) return;
  if (p.mode == 0){                           /* scores fp32 flat            */
    Cf[(long)m*p.ldc + n] = v; return;
  }
  if (p.mode == 1){                           /* q fp16 permuted + bias*alpha*/
    long idx = ((long)(m % p.D1)*p.D2 + m/p.D1)*p.ldc + n;
    Ch[idx] = __float2half_rn(p.alpha*(v + p.bias[n])); return;
  }
  if (p.mode == 3){                           /* dual k/val fp16             */
    int s = m / BATCH, b = m % BATCH;
    if (n < HID)
      p.Ch[((long)b*SEQ + s)*HID + n] = __float2half_rn(v + p.bias[n]);
    else {
      int nn = n - HID;
      p.Ch2[((long)b*HID + nn)*SEQ + s] = __float2half_rn(v + p.bias2[nn]);
    }
    return;
  }
  if (p.mode == 4){                           /* atts fp16 flat              */
    Ch[(long)m*p.ldc + n] = __float2half_rn(v); return;
  }
  /* mode 5: wo -> cat fp32 + cat16, permuted, col_off                       */
  long idx = ((long)(m % p.D1)*p.D2 + m/p.D1)*p.ldc + p.col_off + n;
  float o = v + p.bias[n];
  Cf[idx] = o;
  Ch[idx] = __float2half_rn(o);
}

template<int BMT, int DUAL>
__global__ __launch_bounds__(256) void gemm_h16(GH p){
  constexpr int WM   = BMT/32;
  constexpr int NCOL = BN/(8/WM);
  constexpr int NFR  = NCOL/8;
  constexpr int NBL  = NCOL/16;
  constexpr int ABYT = BMT*128;
  constexpr int SBYT = ABYT + BN*128;
  constexpr int GT   = (BMT+BN)*8;

  extern __shared__ float smf[];
  uint32_t sbase = (uint32_t)__cvta_generic_to_shared(smf);
  const __half* A  = p.A + (long)blockIdx.z * p.sA;
  const __half* Bg = p.B + (long)blockIdx.z * p.sB;
  float*  Cf = p.Cf ? p.Cf + (long)blockIdx.z * p.sC : (float*)0;
  __half* Ch = p.Ch ? p.Ch + (long)blockIdx.z * p.sC : (__half*)0;

  int tid = threadIdx.x;
  int lane = tid & 31, warp = tid >> 5;
  int wm = warp % WM, wn = warp / WM;
  int m0 = blockIdx.x * BMT, n0 = blockIdx.y * BN;

  float acc[2][NFR][4];
  #pragma unroll
  for (int i=0;i<2;i++)
    #pragma unroll
    for (int j=0;j<NFR;j++){ acc[i][j][0]=0.f; acc[i][j][1]=0.f; acc[i][j][2]=0.f; acc[i][j][3]=0.f; }

  int ktiles = (p.K + 63)/64;

  auto load = [&](int st, int k0){
    uint32_t ab = sbase + st*SBYT;
    uint32_t bb = ab + ABYT;
    #pragma unroll
    for (int i=0;i<GT/256;i++){
      int g = tid + i*256;
      int r = g >> 3, gc = g & 7;
      int kcol = k0 + gc*8;
      int kb = (kcol < p.K) ? 16 : 0;
      if (r < BMT){
        uint32_t soff = (uint32_t)(r*128 + ((gc ^ (r&7))<<4));
        int gm = m0 + r;
        cpa16u(ab + soff, A + (long)gm*p.lda + kcol, (gm < p.M) ? kb : 0);
      } else {
        int rb = r - BMT;
        uint32_t soff = (uint32_t)(rb*128 + ((gc ^ (rb&7))<<4));
        int gn = n0 + rb;
        const __half* src;
        if (DUAL && gn >= HID) src = p.B2 + (long)(gn-HID)*p.ldb + kcol;
        else                   src = Bg  + (long)gn*p.ldb + kcol;
        cpa16u(bb + soff, src, (gn < p.N) ? kb : 0);
      }
    }
  };

  load(0, 0); CPA_COMMIT();
  load(1, 64); CPA_COMMIT();

  int mi1 = (lane >> 3) & 1;
  int kg2 = lane >> 4;
  int ri  = lane & 7;
  int marow = wm*32 + mi1*8 + ri;
  int nbrow = wn*NCOL + mi1*8 + ri;
  int maxor = (marow & 7);
  int nbxor = (nbrow & 7);

  for (int kt = 0; kt < ktiles; kt++){
    if (kt + 2 < ktiles) load((kt+2)%3, (kt+2)*64);
    CPA_COMMIT();
    CPA_WAIT2();
    __syncthreads();

    uint32_t ab = sbase + (kt%3)*SBYT;
    uint32_t aA = ab + marow*128;
    uint32_t aB = ab + ABYT + nbrow*128;

    #pragma unroll
    for (int kk=0; kk<4; kk++){
      uint32_t asw = (uint32_t)(((kk*2 + kg2) ^ maxor) << 4);
      uint32_t bsw = (uint32_t)(((kk*2 + kg2) ^ nbxor) << 4);
      unsigned af0[4], af1[4], bf[NBL][4];
      LDSM_X4(af0[0],af0[1],af0[2],af0[3], aA + asw);
      LDSM_X4(af1[0],af1[1],af1[2],af1[3], aA + asw + 16*128);
      #pragma unroll
      for (int jp=0; jp<NBL; jp++)
        LDSM_X4(bf[jp][0],bf[jp][1],bf[jp][2],bf[jp][3], aB + bsw + jp*16*128);
      #pragma unroll
      for (int jp=0; jp<NBL; jp++){
        MMA16(acc[0][2*jp  ], af0[0],af0[1],af0[2],af0[3], bf[jp][0], bf[jp][2]);
        MMA16(acc[0][2*jp+1], af0[0],af0[1],af0[2],af0[3], bf[jp][1], bf[jp][3]);
        MMA16(acc[1][2*jp  ], af1[0],af1[1],af1[2],af1[3], bf[jp][0], bf[jp][2]);
        MMA16(acc[1][2*jp+1], af1[0],af1[1],af1[2],af1[3], bf[jp][1], bf[jp][3]);
      }
    }
    __syncthreads();
  }

  int r = lane >> 2, c2 = (lane & 3)*2;
  #pragma unroll
  for (int im=0; im<2; im++)
    #pragma unroll
    for (int jn=0; jn<NFR; jn++){
      int mr = m0 + wm*32 + im*16 + r;
      int nc = n0 + wn*NCOL + jn*8 + c2;
      epih(p, Cf, Ch, mr,   nc,   acc[im][jn][0]);
      epih(p, Cf, Ch, mr,   nc+1, acc[im][jn][1]);
      epih(p, Cf, Ch, mr+8, nc,   acc[im][jn][2]);
      epih(p, Cf, Ch, mr+8, nc+1, acc[im][jn][3]);
    }
}

/* ---------------- fp16 converters ---------------------------------------- */
__global__ void conv_wp16(const float* __restrict__ Wp){
  long i = (long)blockIdx.x*blockDim.x + threadIdx.x;   /* float4 index */
  const long tot = (long)VPAD*(H3/4);
  if (i >= tot) return;
  long row = i / (H3/4);
  long c4  = i % (H3/4);
  __half2* dst = (__half2*)g_wp16;
  if (row < VOC){
    const float4 v = *(const float4*)(Wp + row*H3 + c4*4);
    dst[i*2]   = __floats2half2_rn(v.x, v.y);
    dst[i*2+1] = __floats2half2_rn(v.z, v.w);
  } else {
    dst[i*2]   = __floats2half2_rn(0.f, 0.f);
    dst[i*2+1] = __floats2half2_rn(0.f, 0.f);
  }
}
__global__ void conv_mem16(const float* __restrict__ mem){
  long i = (long)blockIdx.x*blockDim.x + threadIdx.x;
  if (i >= (long)SEQ*BATCH*(HID/2)) return;
  const float2 v = *(const float2*)(mem + i*2);
  ((__half2*)g_mem16)[i] = __floats2half2_rn(v.x, v.y);
}
__global__ void conv_wts16(const float* __restrict__ Wq, const float* __restrict__ Wk,
                           const float* __restrict__ Wv, const float* __restrict__ Wo){
  int i = blockIdx.x*blockDim.x + threadIdx.x;
  const int per = HID*HID/2;
  if (i >= 4*per) return;
  int seg = i / per, off = i % per;
  const float* src = (seg==0)?Wq:(seg==1)?Wk:(seg==2)?Wv:Wo;
  const float2 v = *(const float2*)(src + (long)off*2);
  ((__half2*)g_W416)[i] = __floats2half2_rn(v.x, v.y);
}

/* == fp16 Wp GEMM: 128x128 CTA, 256 thr, 2 CTA/SM, fused softmax stats === */
#define WBM 128
#define WBN2 128
#define WABY (WBM*128)                  /* 16384 */
#define WSBY (WABY + WBN2*128)          /* 32768 per stage */
#define WSMEM (3*WSBY)                  /* 98304 -> 2 CTAs/SM */

__device__ __forceinline__ void merge_ms(float& m, float& s, float m2, float s2){
  float M = fmaxf(m, m2);
  s = s*__expf(m-M) + s2*__expf(m2-M);
  m = M;
}

__global__ __launch_bounds__(256,2) void gemm_wp16(
    const __half* __restrict__ A, const __half* __restrict__ B,
    const float* __restrict__ bias, __half* __restrict__ l16,
    float* __restrict__ pm, float* __restrict__ ps)
{
  extern __shared__ float smf[];
  __shared__ float red_m[2][128], red_s[2][128];
  uint32_t sbase = (uint32_t)__cvta_generic_to_shared(smf);
  int tid = threadIdx.x;
  int lane = tid & 31, warp = tid >> 5;
  int wm = warp & 3, wn = warp >> 2;     /* 4 x 2 warp grid, 32x64 tiles     */
  int m0 = blockIdx.x * WBM, n0 = blockIdx.y * WBN2;

  float acc[2][8][4];
  #pragma unroll
  for (int i=0;i<2;i++)
    #pragma unroll
    for (int j=0;j<8;j++){ acc[i][j][0]=0.f; acc[i][j][1]=0.f; acc[i][j][2]=0.f; acc[i][j][3]=0.f; }

  const int ktiles = H3/64;              /* 24 */

  auto load = [&](int st, int k0){
    uint32_t ab = sbase + st*WSBY;
    uint32_t bb = ab + WABY;
    #pragma unroll
    for (int i=0;i<8;i++){               /* (128+128)*8 / 256 granules       */
      int g = tid + i*256;
      int r = g >> 3, gc = g & 7;
      int kcol = k0 + gc*8;
      if (r < WBM){
        uint32_t soff = (uint32_t)(r*128 + ((gc ^ (r&7))<<4));
        cpa16u(ab + soff, A + (long)(m0 + r)*H3 + kcol, 16);
      } else {
        int rb = r - WBM;
        uint32_t soff = (uint32_t)(rb*128 + ((gc ^ (rb&7))<<4));
        cpa16u(bb + soff, B + (long)(n0 + rb)*H3 + kcol, 16);
      }
    }
  };

  load(0, 0); CPA_COMMIT();
  load(1, 64); CPA_COMMIT();

  int mi1 = (lane >> 3) & 1;
  int kg2 = lane >> 4;
  int ri  = lane & 7;
  int marow = wm*32 + mi1*8 + ri;
  int nbrow = wn*64 + mi1*8 + ri;
  int maxor = (marow & 7);
  int nbxor = (nbrow & 7);

  for (int kt = 0; kt < ktiles; kt++){
    if (kt + 2 < ktiles) load((kt+2)%3, (kt+2)*64);
    CPA_COMMIT();
    CPA_WAIT2();
    __syncthreads();

    uint32_t ab = sbase + (kt%3)*WSBY;
    uint32_t aA = ab + marow*128;
    uint32_t aB = ab + WABY + nbrow*128;

    #pragma unroll
    for (int kk=0; kk<4; kk++){
      uint32_t asw = (uint32_t)(((kk*2 + kg2) ^ maxor) << 4);
      uint32_t bsw = (uint32_t)(((kk*2 + kg2) ^ nbxor) << 4);
      unsigned af0[4], af1[4], bf[4][4];
      LDSM_X4(af0[0],af0[1],af0[2],af0[3], aA + asw);
      LDSM_X4(af1[0],af1[1],af1[2],af1[3], aA + asw + 16*128);
      #pragma unroll
      for (int jb=0; jb<4; jb++)
        LDSM_X4(bf[jb][0],bf[jb][1],bf[jb][2],bf[jb][3], aB + bsw + jb*16*128);
      #pragma unroll
      for (int jb=0; jb<4; jb++){
        MMA16(acc[0][2*jb  ], af0[0],af0[1],af0[2],af0[3], bf[jb][0], bf[jb][2]);
        MMA16(acc[0][2*jb+1], af0[0],af0[1],af0[2],af0[3], bf[jb][1], bf[jb][3]);
        MMA16(acc[1][2*jb  ], af1[0],af1[1],af1[2],af1[3], bf[jb][0], bf[jb][2]);
        MMA16(acc[1][2*jb+1], af1[0],af1[1],af1[2],af1[3], bf[jb][1], bf[jb][3]);
      }
    }
    __syncthreads();
  }

  /* epilogue: add bias, write fp16 logits, accumulate (max, sumexp) per row */
  int r2 = lane >> 2, c2 = (lane & 3)*2;
  #pragma unroll
  for (int im=0; im<2; im++){
    int mr = m0 + wm*32 + im*16 + r2;
    float m0v=-1e30f, m1v=-1e30f, s0v=0.f, s1v=0.f;
    #pragma unroll
    for (int nj=0; nj<8; nj++){
      int nc = n0 + wn*64 + nj*8 + c2;
      if (nc < VOC){
        float b0 = bias[nc], b1 = bias[nc+1];
        float v00 = acc[im][nj][0]+b0, v01 = acc[im][nj][1]+b1;
        float v10 = acc[im][nj][2]+b0, v11 = acc[im][nj][3]+b1;
        acc[im][nj][0]=v00; acc[im][nj][1]=v01;
        acc[im][nj][2]=v10; acc[im][nj][3]=v11;
        *(__half2*)(l16 + (long)mr*VPAD + nc)     = __floats2half2_rn(v00,v01);
        *(__half2*)(l16 + (long)(mr+8)*VPAD + nc) = __floats2half2_rn(v10,v11);
        m0v = fmaxf(m0v, fmaxf(v00,v01));
        m1v = fmaxf(m1v, fmaxf(v10,v11));
      }
    }
    #pragma unroll
    for (int nj=0; nj<8; nj++){
      int nc = n0 + wn*64 + nj*8 + c2;
      if (nc < VOC){
        s0v += __expf(acc[im][nj][0]-m0v) + __expf(acc[im][nj][1]-m0v);
        s1v += __expf(acc[im][nj][2]-m1v) + __expf(acc[im][nj][3]-m1v);
      }
    }
    #pragma unroll
    for (int off=1; off<4; off<<=1){
      float om0 = __shfl_xor_sync(0xFFFFFFFFu, m0v, off);
      float os0 = __shfl_xor_sync(0xFFFFFFFFu, s0v, off);
      merge_ms(m0v, s0v, om0, os0);
      float om1 = __shfl_xor_sync(0xFFFFFFFFu, m1v, off);
      float os1 = __shfl_xor_sync(0xFFFFFFFFu, s1v, off);
      merge_ms(m1v, s1v, om1, os1);
    }
    if ((lane & 3) == 0){
      int rl = wm*32 + im*16 + r2;
      red_m[wn][rl]   = m0v; red_s[wn][rl]   = s0v;
      red_m[wn][rl+8] = m1v; red_s[wn][rl+8] = s1v;
    }
  }
  __syncthreads();
  if (tid < 128){
    float M = red_m[0][tid], S = red_s[0][tid];
    merge_ms(M, S, red_m[1][tid], red_s[1][tid]);
    pm[(long)blockIdx.y*TB + m0 + tid] = M;
    ps[(long)blockIdx.y*TB + m0 + tid] = S;
  }
}

/* -------- cat[:,0:1024] = [h,y_emb] (fp32 + fp16) + h16 ------------------ */
__global__ void cat_copy(const float* __restrict__ h, const float* __restrict__ y){
  int i = blockIdx.x*blockDim.x + threadIdx.x;
  if (i >= TB*(HID/4)) return;
  int row = i / (HID/4);
  int c   = i % (HID/4);
  const float4 hv = ((const float4*)h)[i];
  const float4 yv = ((const float4*)y)[i];
  float4* cat4 = (float4*)g_cat;
  cat4[(long)row*(H3/4) + c]           = hv;
  cat4[(long)row*(H3/4) + (HID/4) + c] = yv;
  __half2* c16 = (__half2*)g_cat16;
  long b = (long)row*(H3/2);
  __half2 h01 = __floats2half2_rn(hv.x, hv.y);
  __half2 h23 = __floats2half2_rn(hv.z, hv.w);
  c16[b + c*2]               = h01;
  c16[b + c*2 + 1]           = h23;
  c16[b + (HID/2) + c*2]     = __floats2half2_rn(yv.x, yv.y);
  c16[b + (HID/2) + c*2 + 1] = __floats2half2_rn(yv.z, yv.w);
  __half2* h16 = (__half2*)g_h16;
  h16[i*2]   = h01;
  h16[i*2+1] = h23;
}

/* ------ softmax over S; writes w16 (B,T,S) + dists fp32 (T,B,S) ---------- */
__global__ void softmax_s(float* __restrict__ dists, const unsigned char* __restrict__ mask){
  int bt = blockIdx.x;                  /* b*T + t */
  int b = bt / T_LEN, t = bt % T_LEN;
  float* row = g_w + (long)bt*SEQ;
  const unsigned char* mrow = mask + (long)b*SEQ;
  int tid = threadIdx.x;                /* 128 */
  __shared__ float red[128];
  float mx = -1e30f;
  for (int s=tid; s<SEQ; s+=128){
    float x = mrow[s] ? -1e9f : row[s];
    mx = fmaxf(mx, x);
  }
  red[tid]=mx; __syncthreads();
  for (int off=64; off>0; off>>=1){ if (tid<off) red[tid]=fmaxf(red[tid],red[tid+off]); __syncthreads(); }
  mx = red[0]; __syncthreads();
  float sum=0.f;
  for (int s=tid; s<SEQ; s+=128){
    float x = mrow[s] ? -1e9f : row[s];
    sum += __expf(x-mx);
  }
  red[tid]=sum; __syncthreads();
  for (int off=64; off>0; off>>=1){ if (tid<off) red[tid]+=red[tid+off]; __syncthreads(); }
  float inv = 1.f/red[0];
  for (int s=tid; s<SEQ; s+=128){
    float x = mrow[s] ? -1e9f : row[s];
    float wv = __expf(x-mx)*inv;
    g_w16[(long)bt*SEQ + s] = __float2half_rn(wv);
    dists[((long)t*BATCH + b)*SEQ + s] = wv;
  }
}

/* -------- fused: gate + final softmax (from partials) + scatter ---------- */
__global__ void softmax_v(float* __restrict__ out, const float* __restrict__ dists,
                          const int* __restrict__ xids,
                          const float* __restrict__ vv, const float* __restrict__ bvv){
  int rid = blockIdx.x;                 /* t*B + b */
  int b = rid % BATCH, t = rid / BATCH;
  float* row = out + (long)rid*VE;
  int tid = threadIdx.x;                /* 512 */
  __shared__ float rm[512], rs[512];
  __shared__ float gsh;

  /* gate = sigmoid(cat[rid] . v + bv) */
  const float* cr = g_cat + (long)rid*H3;
  float s0 = 0.f;
  for (int j=tid; j<H3; j+=512) s0 += cr[j]*vv[j];
  rm[tid]=s0; __syncthreads();
  for (int off=256; off>0; off>>=1){ if (tid<off) rm[tid]+=rm[tid+off]; __syncthreads(); }
  if (tid==0) gsh = 1.f/(1.f+__expf(-(rm[0]+bvv[0])));
  __syncthreads();
  float g = gsh;

  /* combine per-stripe (m,s) partials (NSTRIPE=392 <= 512) */
  float m = -1e30f, s = 0.f;
  if (tid < NSTRIPE){
    m = g_pm[(long)tid*TB + rid];
    s = g_ps[(long)tid*TB + rid];
  }
  rm[tid]=m; rs[tid]=s; __syncthreads();
  for (int off=256; off>0; off>>=1){
    if (tid<off){
      float m2=rm[tid+off], s2=rs[tid+off];
      float M=fmaxf(rm[tid],m2);
      rs[tid]=rs[tid]*__expf(rm[tid]-M)+s2*__expf(m2-M);
      rm[tid]=M;
    }
    __syncthreads();
  }
  float M = rm[0];
  float gscale = g/rs[0];

  /* single pass: fp16 logit -> fp32 prob */
  const __half* lrow = g_l16 + (long)rid*VPAD;
  for (int j=tid; j<VOC; j+=512)
    row[j] = __expf(__half2float(lrow[j]) - M)*gscale;
  for (int j=VOC+tid; j<VE; j+=512) row[j] = 0.f;

  __threadfence(); __syncthreads();

  float omg = 1.f - g;
  const float* drow = dists + ((long)t*BATCH + b)*SEQ;
  for (int si=tid; si<SEQ; si+=512){
    int col = xids[(long)si*BATCH + b];
    atomicAdd(row + col, omg*drow[si]);
  }
}

/* ------------------------------- host ----------------------------------- */
template<int BMT, int DUAL>
static inline void launch_h16(const GH& p, int batches){
  constexpr int SM = 3*((BMT+BN)*128);
  static bool done = false;
  if (!done){
    cudaFuncSetAttribute(gemm_h16<BMT,DUAL>,
                         cudaFuncAttributeMaxDynamicSharedMemorySize, SM);
    done = true;
  }
  dim3 grid((p.M+BMT-1)/BMT, (p.N+BN-1)/BN, batches);
  gemm_h16<BMT,DUAL><<<grid, 256, SM>>>(p);
}

extern "C" void kernel_launch(void* const* d_in, const int* in_sizes, int n_in,
                              void* d_out, int out_size){
  const float* h    = (const float*)d_in[0];
  const float* yemb = (const float*)d_in[1];
  const float* mem  = (const float*)d_in[2];
  const unsigned char* mask = (const unsigned char*)d_in[3];
  const int* xids   = (const int*)d_in[4];
  int wb = 5;
  if (n_in >= 18 && in_sizes[5] == 1) wb = 6;
  const float* Wq = (const float*)d_in[wb+0];
  const float* bq = (const float*)d_in[wb+1];
  const float* Wk = (const float*)d_in[wb+2];
  const float* bk = (const float*)d_in[wb+3];
  const float* Wv = (const float*)d_in[wb+4];
  const float* bva= (const float*)d_in[wb+5];
  const float* Wo = (const float*)d_in[wb+6];
  const float* bo = (const float*)d_in[wb+7];
  const float* Wp = (const float*)d_in[wb+8];
  const float* bp = (const float*)d_in[wb+9];
  const float* vv = (const float*)d_in[wb+10];
  const float* bv = (const float*)d_in[wb+11];

  float* out   = (float*)d_out;
  float* dists = out + (long)TB*VE;

  cudaFuncSetAttribute(gemm_wp16, cudaFuncAttributeMaxDynamicSharedMemorySize, WSMEM);

  void *wbuf, *catp, *cat16p, *wp16p, *h16p, *mem16p, *w4p;
  void *q16p, *k16p, *valT16p, *w16p, *atts16p, *l16p, *pmp, *psp;
  cudaGetSymbolAddress(&wbuf, g_w);
  cudaGetSymbolAddress(&catp, g_cat);
  cudaGetSymbolAddress(&cat16p, g_cat16);
  cudaGetSymbolAddress(&wp16p, g_wp16);
  cudaGetSymbolAddress(&h16p, g_h16);
  cudaGetSymbolAddress(&mem16p, g_mem16);
  cudaGetSymbolAddress(&w4p, g_W416);
  cudaGetSymbolAddress(&q16p, g_q16);
  cudaGetSymbolAddress(&k16p, g_k16);
  cudaGetSymbolAddress(&valT16p, g_valT16);
  cudaGetSymbolAddress(&w16p, g_w16);
  cudaGetSymbolAddress(&atts16p, g_atts16);
  cudaGetSymbolAddress(&l16p, g_l16);
  cudaGetSymbolAddress(&pmp, g_pm);
  cudaGetSymbolAddress(&psp, g_ps);

  const __half* W16 = (const __half*)w4p;
  const __half* Wq16 = W16;
  const __half* Wk16 = W16 + (long)HID*HID;
  const __half* Wv16 = W16 + 2L*HID*HID;
  const __half* Wo16 = W16 + 3L*HID*HID;

  float scale = 1.0f/sqrtf((float)HID);

  /* conversions */
  {
    long tot = (long)VPAD*(H3/4);
    conv_wp16<<<(int)((tot + 255)/256), 256>>>(Wp);
  }
  {
    long tot = (long)SEQ*BATCH*(HID/2);
    conv_mem16<<<(int)((tot+255)/256), 256>>>(mem);
  }
  conv_wts16<<<(4*HID*HID/2+255)/256, 256>>>(Wq, Wk, Wv, Wo);

  /* cat[:,0:1024] = [h, y_emb] (fp32 + fp16) + h16 */
  cat_copy<<<(TB*(HID/4)+255)/256, 256>>>(h, yemb);

  GH p;

  /* q16 = (h16@Wq16^T + bq)*scale -> (B,T,H) fp16 */
  p = GH{};
  p.A = (const __half*)h16p; p.B = Wq16; p.Ch = (__half*)q16p;
  p.lda = HID; p.ldb = HID; p.ldc = HID;
  p.M = TB; p.N = HID; p.K = HID;
  p.bias = bq; p.alpha = scale;
  p.mode = 1; p.D1 = BATCH; p.D2 = T_LEN;
  launch_h16<64,0>(p, 1);

  /* fused k & val projection -> k16 (B,S,H), valT16 (B,H,S) */
  p = GH{};
  p.A = (const __half*)mem16p; p.B = Wk16; p.B2 = Wv16;
  p.Ch = (__half*)k16p; p.Ch2 = (__half*)valT16p;
  p.lda = HID; p.ldb = HID;
  p.M = SEQ*BATCH; p.N = 2*HID; p.K = HID;
  p.bias = bk; p.bias2 = bva;
  p.mode = 3;
  launch_h16<128,1>(p, 1);

  /* scores[b]: (T,S) = q16_b @ k16_b^T -> fp32 g_w */
  p = GH{};
  p.A = (const __half*)q16p; p.B = (const __half*)k16p; p.Cf = (float*)wbuf;
  p.lda = HID; p.ldb = HID; p.ldc = SEQ;
  p.sA = (long)T_LEN*HID; p.sB = (long)SEQ*HID; p.sC = (long)T_LEN*SEQ;
  p.M = T_LEN; p.N = SEQ; p.K = HID;
  p.mode = 0;
  launch_h16<64,0>(p, BATCH);

  softmax_s<<<BATCH*T_LEN, 128>>>(dists, mask);

  /* atts16[b]: (T,H) = w16_b @ valT16_b^T -> fp16 */
  p = GH{};
  p.A = (const __half*)w16p; p.B = (const __half*)valT16p; p.Ch = (__half*)atts16p;
  p.lda = SEQ; p.ldb = SEQ; p.ldc = HID;
  p.sA = (long)T_LEN*SEQ; p.sB = (long)HID*SEQ; p.sC = (long)T_LEN*HID;
  p.M = T_LEN; p.N = HID; p.K = SEQ;
  p.mode = 4;
  launch_h16<64,0>(p, BATCH);

  /* cat[:,1024:1536] = atts16@Wo16^T + bo (writes fp32 cat + fp16 cat16) */
  p = GH{};
  p.A = (const __half*)atts16p; p.B = Wo16;
  p.Cf = (float*)catp; p.Ch = (__half*)cat16p;
  p.lda = HID; p.ldb = HID; p.ldc = H3;
  p.M = TB; p.N = HID; p.K = HID;
  p.bias = bo;
  p.mode = 5; p.D1 = T_LEN; p.D2 = BATCH; p.col_off = 1024;
  launch_h16<64,0>(p, 1);

  /* logits = cat16@Wp16^T + bp -> fp16 l16 + per-stripe (m,s) partials */
  gemm_wp16<<<dim3(TB/WBM, VPAD/WBN2), 256, WSMEM>>>(
      (const __half*)cat16p, (const __half*)wp16p, bp,
      (__half*)l16p, (float*)pmp, (float*)psp);

  /* fused gate + final softmax + ext zero + scatter */
  softmax_v<<<TB, 512>>>(out, dists, xids, vv, bv);

  (void)out_size; (void)n_in;
}

// round 12
// speedup vs baseline: 1.1432x; 1.0107x over previous
#include <cuda_runtime.h>
#include <cuda_fp16.h>
#include <math.h>
#include <stdint.h>

#define T_LEN 64
#define BATCH 32
#define SEQ   400
#define HID   512
#define VOC   50000
#define EXTD  400
#define VE    (VOC+EXTD)
#define TB    (T_LEN*BATCH)     /* 2048 */
#define H3    (3*HID)           /* 1536 */
#define VPAD  50176             /* VOC padded to 256 */
#define NSTRIPE (VPAD/128)      /* 392 */

/* ---------------- scratch (device globals: allocation-free) -------------- */
__device__ float  g_cat [TB*H3];              /* (T*B,3H) fp32 (gate)        */
__device__ float  g_w   [BATCH*T_LEN*SEQ];    /* scores fp32 (B,T,S)         */
__device__ __half g_cat16[TB*H3];
__device__ __half g_wp16 [(long)VPAD*H3];
__device__ __half g_h16  [TB*HID];
__device__ __half g_mem16[SEQ*BATCH*HID];
__device__ __half g_W416 [4*HID*HID];         /* Wq,Wk,Wv,Wo                 */
__device__ __half g_q16  [BATCH*T_LEN*HID];   /* (B,T,H)                     */
__device__ __half g_k16  [BATCH*SEQ*HID];     /* (B,S,H)                     */
__device__ __half g_valT16[BATCH*HID*SEQ];    /* (B,H,S)                     */
__device__ __half g_w16  [BATCH*T_LEN*SEQ];   /* attn weights fp16           */
__device__ __half g_atts16[TB*HID];           /* (B,T,H) rows b*T+t          */
__device__ __half g_l16  [(long)TB*VPAD];     /* fp16 logits                 */
__device__ float  g_pm   [NSTRIPE*TB];        /* per-stripe softmax max      */
__device__ float  g_ps   [NSTRIPE*TB];        /* per-stripe softmax sum      */

#define BN 128

__device__ __forceinline__ void cpa16u(unsigned dst, const void* src, int bytes){
  asm volatile("cp.async.cg.shared.global [%0], [%1], 16, %2;\n"
               :: "r"(dst), "l"(src), "r"(bytes));
}
#define CPA_COMMIT() asm volatile("cp.async.commit_group;\n")
#define CPA_WAIT2()  asm volatile("cp.async.wait_group 2;\n")

#define LDSM_X4(r0,r1,r2,r3,addr) \
  asm volatile("ldmatrix.sync.aligned.m8n8.x4.shared.b16 {%0,%1,%2,%3}, [%4];" \
               : "=r"(r0), "=r"(r1), "=r"(r2), "=r"(r3) : "r"(addr))

#define MMA16(d, a0,a1,a2,a3, b0,b1) \
  asm volatile("mma.sync.aligned.m16n8k16.row.col.f32.f16.f16.f32 " \
               "{%0,%1,%2,%3}, {%4,%5,%6,%7}, {%8,%9}, {%0,%1,%2,%3};\n" \
               : "+f"((d)[0]), "+f"((d)[1]), "+f"((d)[2]), "+f"((d)[3]) \
               : "r"(a0), "r"(a1), "r"(a2), "r"(a3), "r"(b0), "r"(b1))

/* ---------------- generic fp16 MMA GEMM --------------------------------- */
struct GH {
  const __half* A; const __half* B; const __half* B2;
  float* Cf; __half* Ch; __half* Ch2;
  long lda, ldb, ldc;
  long sA, sB, sC;
  int  M, N, K;
  const float* bias; const float* bias2;
  float alpha;
  int  mode, D1, D2;
  long col_off;
};

__device__ __forceinline__ void epih(const GH& p, float* Cf, __half* Ch,
                                     int m, int n, float v){
  if (m >= p.M || n >= p.N) return;
  if (p.mode == 0){                           /* scores fp32 flat            */
    Cf[(long)m*p.ldc + n] = v; return;
  }
  if (p.mode == 1){                           /* q fp16 permuted + bias*alpha*/
    long idx = ((long)(m % p.D1)*p.D2 + m/p.D1)*p.ldc + n;
    Ch[idx] = __float2half_rn(p.alpha*(v + p.bias[n])); return;
  }
  if (p.mode == 3){                           /* dual k/val fp16             */
    int s = m / BATCH, b = m % BATCH;
    if (n < HID)
      p.Ch[((long)b*SEQ + s)*HID + n] = __float2half_rn(v + p.bias[n]);
    else {
      int nn = n - HID;
      p.Ch2[((long)b*HID + nn)*SEQ + s] = __float2half_rn(v + p.bias2[nn]);
    }
    return;
  }
  if (p.mode == 4){                           /* atts fp16 flat              */
    Ch[(long)m*p.ldc + n] = __float2half_rn(v); return;
  }
  /* mode 5: wo -> cat fp32 + cat16, permuted, col_off                       */
  long idx = ((long)(m % p.D1)*p.D2 + m/p.D1)*p.ldc + p.col_off + n;
  float o = v + p.bias[n];
  Cf[idx] = o;
  Ch[idx] = __float2half_rn(o);
}

template<int BMT, int DUAL>
__global__ __launch_bounds__(256,2) void gemm_h16(GH p){
  constexpr int WM   = BMT/32;
  constexpr int NCOL = BN/(8/WM);
  constexpr int NFR  = NCOL/8;
  constexpr int NBL  = NCOL/16;
  constexpr int ABYT = BMT*128;
  constexpr int SBYT = ABYT + BN*128;
  constexpr int GT   = (BMT+BN)*8;

  extern __shared__ float smf[];
  uint32_t sbase = (uint32_t)__cvta_generic_to_shared(smf);
  const __half* A  = p.A + (long)blockIdx.z * p.sA;
  const __half* Bg = p.B + (long)blockIdx.z * p.sB;
  float*  Cf = p.Cf ? p.Cf + (long)blockIdx.z * p.sC : (float*)0;
  __half* Ch = p.Ch ? p.Ch + (long)blockIdx.z * p.sC : (__half*)0;

  int tid = threadIdx.x;
  int lane = tid & 31, warp = tid >> 5;
  int wm = warp % WM, wn = warp / WM;
  int m0 = blockIdx.x * BMT, n0 = blockIdx.y * BN;

  float acc[2][NFR][4];
  #pragma unroll
  for (int i=0;i<2;i++)
    #pragma unroll
    for (int j=0;j<NFR;j++){ acc[i][j][0]=0.f; acc[i][j][1]=0.f; acc[i][j][2]=0.f; acc[i][j][3]=0.f; }

  int ktiles = (p.K + 63)/64;

  auto load = [&](int st, int k0){
    uint32_t ab = sbase + st*SBYT;
    uint32_t bb = ab + ABYT;
    #pragma unroll
    for (int i=0;i<GT/256;i++){
      int g = tid + i*256;
      int r = g >> 3, gc = g & 7;
      int kcol = k0 + gc*8;
      int kb = (kcol < p.K) ? 16 : 0;
      if (r < BMT){
        uint32_t soff = (uint32_t)(r*128 + ((gc ^ (r&7))<<4));
        int gm = m0 + r;
        cpa16u(ab + soff, A + (long)gm*p.lda + kcol, (gm < p.M) ? kb : 0);
      } else {
        int rb = r - BMT;
        uint32_t soff = (uint32_t)(rb*128 + ((gc ^ (rb&7))<<4));
        int gn = n0 + rb;
        const __half* src;
        if (DUAL && gn >= HID) src = p.B2 + (long)(gn-HID)*p.ldb + kcol;
        else                   src = Bg  + (long)gn*p.ldb + kcol;
        cpa16u(bb + soff, src, (gn < p.N) ? kb : 0);
      }
    }
  };

  load(0, 0); CPA_COMMIT();
  load(1, 64); CPA_COMMIT();

  int mi1 = (lane >> 3) & 1;
  int kg2 = lane >> 4;
  int ri  = lane & 7;
  int marow = wm*32 + mi1*8 + ri;
  int nbrow = wn*NCOL + mi1*8 + ri;
  int maxor = (marow & 7);
  int nbxor = (nbrow & 7);

  for (int kt = 0; kt < ktiles; kt++){
    if (kt + 2 < ktiles) load((kt+2)%3, (kt+2)*64);
    CPA_COMMIT();
    CPA_WAIT2();
    __syncthreads();

    uint32_t ab = sbase + (kt%3)*SBYT;
    uint32_t aA = ab + marow*128;
    uint32_t aB = ab + ABYT + nbrow*128;

    #pragma unroll
    for (int kk=0; kk<4; kk++){
      uint32_t asw = (uint32_t)(((kk*2 + kg2) ^ maxor) << 4);
      uint32_t bsw = (uint32_t)(((kk*2 + kg2) ^ nbxor) << 4);
      unsigned af0[4], af1[4], bf[NBL][4];
      LDSM_X4(af0[0],af0[1],af0[2],af0[3], aA + asw);
      LDSM_X4(af1[0],af1[1],af1[2],af1[3], aA + asw + 16*128);
      #pragma unroll
      for (int jp=0; jp<NBL; jp++)
        LDSM_X4(bf[jp][0],bf[jp][1],bf[jp][2],bf[jp][3], aB + bsw + jp*16*128);
      #pragma unroll
      for (int jp=0; jp<NBL; jp++){
        MMA16(acc[0][2*jp  ], af0[0],af0[1],af0[2],af0[3], bf[jp][0], bf[jp][2]);
        MMA16(acc[0][2*jp+1], af0[0],af0[1],af0[2],af0[3], bf[jp][1], bf[jp][3]);
        MMA16(acc[1][2*jp  ], af1[0],af1[1],af1[2],af1[3], bf[jp][0], bf[jp][2]);
        MMA16(acc[1][2*jp+1], af1[0],af1[1],af1[2],af1[3], bf[jp][1], bf[jp][3]);
      }
    }
    __syncthreads();
  }

  int r = lane >> 2, c2 = (lane & 3)*2;
  #pragma unroll
  for (int im=0; im<2; im++)
    #pragma unroll
    for (int jn=0; jn<NFR; jn++){
      int mr = m0 + wm*32 + im*16 + r;
      int nc = n0 + wn*NCOL + jn*8 + c2;
      epih(p, Cf, Ch, mr,   nc,   acc[im][jn][0]);
      epih(p, Cf, Ch, mr,   nc+1, acc[im][jn][1]);
      epih(p, Cf, Ch, mr+8, nc,   acc[im][jn][2]);
      epih(p, Cf, Ch, mr+8, nc+1, acc[im][jn][3]);
    }
}

/* ---------------- fp16 converters (MLP=4: 4 independent float4/thread) --- */
#define WP_TOT4  ((long)VPAD*(H3/4))          /* 19,267,584 = 18816*256*4    */
#define WP_GRID  18816
#define WP_STRIDE ((long)WP_GRID*256)
__global__ void conv_wp16(const float* __restrict__ Wp){
  long i0 = (long)blockIdx.x*256 + threadIdx.x;
  float4 v[4];
  long idx[4];
  #pragma unroll
  for (int u=0; u<4; u++){
    long i = i0 + (long)u*WP_STRIDE;
    idx[u] = i;
    long row = i / (H3/4);
    long c4  = i % (H3/4);
    v[u] = (row < VOC) ? *(const float4*)(Wp + row*H3 + c4*4)
                       : make_float4(0.f,0.f,0.f,0.f);
  }
  __half2* dst = (__half2*)g_wp16;
  #pragma unroll
  for (int u=0; u<4; u++){
    dst[idx[u]*2]   = __floats2half2_rn(v[u].x, v[u].y);
    dst[idx[u]*2+1] = __floats2half2_rn(v[u].z, v[u].w);
  }
}
#define MEM_TOT4 ((long)SEQ*BATCH*HID/4)      /* 1,638,400 = 1600*256*4      */
#define MEM_GRID 1600
#define MEM_STRIDE ((long)MEM_GRID*256)
__global__ void conv_mem16(const float* __restrict__ mem){
  long i0 = (long)blockIdx.x*256 + threadIdx.x;
  float4 v[4];
  #pragma unroll
  for (int u=0; u<4; u++) v[u] = *(const float4*)(mem + (i0 + (long)u*MEM_STRIDE)*4);
  __half2* dst = (__half2*)g_mem16;
  #pragma unroll
  for (int u=0; u<4; u++){
    long i = i0 + (long)u*MEM_STRIDE;
    dst[i*2]   = __floats2half2_rn(v[u].x, v[u].y);
    dst[i*2+1] = __floats2half2_rn(v[u].z, v[u].w);
  }
}
#define WTS_TOT4 (4*HID*HID/4)                /* 262,144 = 256*256*4         */
#define WTS_GRID 256
#define WTS_STRIDE (WTS_GRID*256)
__global__ void conv_wts16(const float* __restrict__ Wq, const float* __restrict__ Wk,
                           const float* __restrict__ Wv, const float* __restrict__ Wo){
  int i0 = blockIdx.x*256 + threadIdx.x;
  const int per = HID*HID/4;
  float4 v[4];
  #pragma unroll
  for (int u=0; u<4; u++){
    int i = i0 + u*WTS_STRIDE;
    int seg = i / per, off = i % per;
    const float* src = (seg==0)?Wq:(seg==1)?Wk:(seg==2)?Wv:Wo;
    v[u] = *(const float4*)(src + (long)off*4);
  }
  __half2* dst = (__half2*)g_W416;
  #pragma unroll
  for (int u=0; u<4; u++){
    int i = i0 + u*WTS_STRIDE;
    dst[i*2]   = __floats2half2_rn(v[u].x, v[u].y);
    dst[i*2+1] = __floats2half2_rn(v[u].z, v[u].w);
  }
}

/* == fp16 Wp GEMM: 128x128 CTA, 256 thr, 2 CTA/SM, fused softmax stats === */
#define WBM 128
#define WBN2 128
#define WABY (WBM*128)                  /* 16384 */
#define WSBY (WABY + WBN2*128)          /* 32768 per stage */
#define WSMEM (3*WSBY)                  /* 98304 -> 2 CTAs/SM */

__device__ __forceinline__ void merge_ms(float& m, float& s, float m2, float s2){
  float M = fmaxf(m, m2);
  s = s*__expf(m-M) + s2*__expf(m2-M);
  m = M;
}

__global__ __launch_bounds__(256,2) void gemm_wp16(
    const __half* __restrict__ A, const __half* __restrict__ B,
    const float* __restrict__ bias, __half* __restrict__ l16,
    float* __restrict__ pm, float* __restrict__ ps)
{
  extern __shared__ float smf[];
  __shared__ float red_m[2][128], red_s[2][128];
  uint32_t sbase = (uint32_t)__cvta_generic_to_shared(smf);
  int tid = threadIdx.x;
  int lane = tid & 31, warp = tid >> 5;
  int wm = warp & 3, wn = warp >> 2;     /* 4 x 2 warp grid, 32x64 tiles     */
  int m0 = blockIdx.x * WBM, n0 = blockIdx.y * WBN2;

  float acc[2][8][4];
  #pragma unroll
  for (int i=0;i<2;i++)
    #pragma unroll
    for (int j=0;j<8;j++){ acc[i][j][0]=0.f; acc[i][j][1]=0.f; acc[i][j][2]=0.f; acc[i][j][3]=0.f; }

  const int ktiles = H3/64;              /* 24 */

  auto load = [&](int st, int k0){
    uint32_t ab = sbase + st*WSBY;
    uint32_t bb = ab + WABY;
    #pragma unroll
    for (int i=0;i<8;i++){               /* (128+128)*8 / 256 granules       */
      int g = tid + i*256;
      int r = g >> 3, gc = g & 7;
      int kcol = k0 + gc*8;
      if (r < WBM){
        uint32_t soff = (uint32_t)(r*128 + ((gc ^ (r&7))<<4));
        cpa16u(ab + soff, A + (long)(m0 + r)*H3 + kcol, 16);
      } else {
        int rb = r - WBM;
        uint32_t soff = (uint32_t)(rb*128 + ((gc ^ (rb&7))<<4));
        cpa16u(bb + soff, B + (long)(n0 + rb)*H3 + kcol, 16);
      }
    }
  };

  load(0, 0); CPA_COMMIT();
  load(1, 64); CPA_COMMIT();

  int mi1 = (lane >> 3) & 1;
  int kg2 = lane >> 4;
  int ri  = lane & 7;
  int marow = wm*32 + mi1*8 + ri;
  int nbrow = wn*64 + mi1*8 + ri;
  int maxor = (marow & 7);
  int nbxor = (nbrow & 7);

  for (int kt = 0; kt < ktiles; kt++){
    if (kt + 2 < ktiles) load((kt+2)%3, (kt+2)*64);
    CPA_COMMIT();
    CPA_WAIT2();
    __syncthreads();

    uint32_t ab = sbase + (kt%3)*WSBY;
    uint32_t aA = ab + marow*128;
    uint32_t aB = ab + WABY + nbrow*128;

    #pragma unroll
    for (int kk=0; kk<4; kk++){
      uint32_t asw = (uint32_t)(((kk*2 + kg2) ^ maxor) << 4);
      uint32_t bsw = (uint32_t)(((kk*2 + kg2) ^ nbxor) << 4);
      unsigned af0[4], af1[4], bf[4][4];
      LDSM_X4(af0[0],af0[1],af0[2],af0[3], aA + asw);
      LDSM_X4(af1[0],af1[1],af1[2],af1[3], aA + asw + 16*128);
      #pragma unroll
      for (int jb=0; jb<4; jb++)
        LDSM_X4(bf[jb][0],bf[jb][1],bf[jb][2],bf[jb][3], aB + bsw + jb*16*128);
      #pragma unroll
      for (int jb=0; jb<4; jb++){
        MMA16(acc[0][2*jb  ], af0[0],af0[1],af0[2],af0[3], bf[jb][0], bf[jb][2]);
        MMA16(acc[0][2*jb+1], af0[0],af0[1],af0[2],af0[3], bf[jb][1], bf[jb][3]);
        MMA16(acc[1][2*jb  ], af1[0],af1[1],af1[2],af1[3], bf[jb][0], bf[jb][2]);
        MMA16(acc[1][2*jb+1], af1[0],af1[1],af1[2],af1[3], bf[jb][1], bf[jb][3]);
      }
    }
    __syncthreads();
  }

  /* epilogue: add bias, write fp16 logits, accumulate (max, sumexp) per row */
  int r2 = lane >> 2, c2 = (lane & 3)*2;
  #pragma unroll
  for (int im=0; im<2; im++){
    int mr = m0 + wm*32 + im*16 + r2;
    float m0v=-1e30f, m1v=-1e30f, s0v=0.f, s1v=0.f;
    #pragma unroll
    for (int nj=0; nj<8; nj++){
      int nc = n0 + wn*64 + nj*8 + c2;
      if (nc < VOC){
        float b0 = bias[nc], b1 = bias[nc+1];
        float v00 = acc[im][nj][0]+b0, v01 = acc[im][nj][1]+b1;
        float v10 = acc[im][nj][2]+b0, v11 = acc[im][nj][3]+b1;
        acc[im][nj][0]=v00; acc[im][nj][1]=v01;
        acc[im][nj][2]=v10; acc[im][nj][3]=v11;
        *(__half2*)(l16 + (long)mr*VPAD + nc)     = __floats2half2_rn(v00,v01);
        *(__half2*)(l16 + (long)(mr+8)*VPAD + nc) = __floats2half2_rn(v10,v11);
        m0v = fmaxf(m0v, fmaxf(v00,v01));
        m1v = fmaxf(m1v, fmaxf(v10,v11));
      }
    }
    #pragma unroll
    for (int nj=0; nj<8; nj++){
      int nc = n0 + wn*64 + nj*8 + c2;
      if (nc < VOC){
        s0v += __expf(acc[im][nj][0]-m0v) + __expf(acc[im][nj][1]-m0v);
        s1v += __expf(acc[im][nj][2]-m1v) + __expf(acc[im][nj][3]-m1v);
      }
    }
    #pragma unroll
    for (int off=1; off<4; off<<=1){
      float om0 = __shfl_xor_sync(0xFFFFFFFFu, m0v, off);
      float os0 = __shfl_xor_sync(0xFFFFFFFFu, s0v, off);
      merge_ms(m0v, s0v, om0, os0);
      float om1 = __shfl_xor_sync(0xFFFFFFFFu, m1v, off);
      float os1 = __shfl_xor_sync(0xFFFFFFFFu, s1v, off);
      merge_ms(m1v, s1v, om1, os1);
    }
    if ((lane & 3) == 0){
      int rl = wm*32 + im*16 + r2;
      red_m[wn][rl]   = m0v; red_s[wn][rl]   = s0v;
      red_m[wn][rl+8] = m1v; red_s[wn][rl+8] = s1v;
    }
  }
  __syncthreads();
  if (tid < 128){
    float M = red_m[0][tid], S = red_s[0][tid];
    merge_ms(M, S, red_m[1][tid], red_s[1][tid]);
    pm[(long)blockIdx.y*TB + m0 + tid] = M;
    ps[(long)blockIdx.y*TB + m0 + tid] = S;
  }
}

/* -------- cat[:,0:1024] = [h,y_emb] (fp32 + fp16) + h16 ------------------ */
__global__ void cat_copy(const float* __restrict__ h, const float* __restrict__ y){
  int i = blockIdx.x*blockDim.x + threadIdx.x;
  if (i >= TB*(HID/4)) return;
  int row = i / (HID/4);
  int c   = i % (HID/4);
  const float4 hv = ((const float4*)h)[i];
  const float4 yv = ((const float4*)y)[i];
  float4* cat4 = (float4*)g_cat;
  cat4[(long)row*(H3/4) + c]           = hv;
  cat4[(long)row*(H3/4) + (HID/4) + c] = yv;
  __half2* c16 = (__half2*)g_cat16;
  long b = (long)row*(H3/2);
  __half2 h01 = __floats2half2_rn(hv.x, hv.y);
  __half2 h23 = __floats2half2_rn(hv.z, hv.w);
  c16[b + c*2]               = h01;
  c16[b + c*2 + 1]           = h23;
  c16[b + (HID/2) + c*2]     = __floats2half2_rn(yv.x, yv.y);
  c16[b + (HID/2) + c*2 + 1] = __floats2half2_rn(yv.z, yv.w);
  __half2* h16 = (__half2*)g_h16;
  h16[i*2]   = h01;
  h16[i*2+1] = h23;
}

/* ------ softmax over S; writes w16 (B,T,S) + dists fp32 (T,B,S) ---------- */
__global__ void softmax_s(float* __restrict__ dists, const unsigned char* __restrict__ mask){
  int bt = blockIdx.x;                  /* b*T + t */
  int b = bt / T_LEN, t = bt % T_LEN;
  float* row = g_w + (long)bt*SEQ;
  const unsigned char* mrow = mask + (long)b*SEQ;
  int tid = threadIdx.x;                /* 128 */
  __shared__ float red[128];
  float mx = -1e30f;
  for (int s=tid; s<SEQ; s+=128){
    float x = mrow[s] ? -1e9f : row[s];
    mx = fmaxf(mx, x);
  }
  red[tid]=mx; __syncthreads();
  for (int off=64; off>0; off>>=1){ if (tid<off) red[tid]=fmaxf(red[tid],red[tid+off]); __syncthreads(); }
  mx = red[0]; __syncthreads();
  float sum=0.f;
  for (int s=tid; s<SEQ; s+=128){
    float x = mrow[s] ? -1e9f : row[s];
    sum += __expf(x-mx);
  }
  red[tid]=sum; __syncthreads();
  for (int off=64; off>0; off>>=1){ if (tid<off) red[tid]+=red[tid+off]; __syncthreads(); }
  float inv = 1.f/red[0];
  for (int s=tid; s<SEQ; s+=128){
    float x = mrow[s] ? -1e9f : row[s];
    float wv = __expf(x-mx)*inv;
    g_w16[(long)bt*SEQ + s] = __float2half_rn(wv);
    dists[((long)t*BATCH + b)*SEQ + s] = wv;
  }
}

/* -------- fused: gate + final softmax (from partials) + scatter ---------- */
__global__ void softmax_v(float* __restrict__ out, const float* __restrict__ dists,
                          const int* __restrict__ xids,
                          const float* __restrict__ vv, const float* __restrict__ bvv){
  int rid = blockIdx.x;                 /* t*B + b */
  int b = rid % BATCH, t = rid / BATCH;
  float* row = out + (long)rid*VE;
  int tid = threadIdx.x;                /* 512 */
  __shared__ float rm[512], rs[512];
  __shared__ float gsh;

  /* gate = sigmoid(cat[rid] . v + bv) */
  const float* cr = g_cat + (long)rid*H3;
  float s0 = 0.f;
  for (int j=tid; j<H3; j+=512) s0 += cr[j]*vv[j];
  rm[tid]=s0; __syncthreads();
  for (int off=256; off>0; off>>=1){ if (tid<off) rm[tid]+=rm[tid+off]; __syncthreads(); }
  if (tid==0) gsh = 1.f/(1.f+__expf(-(rm[0]+bvv[0])));
  __syncthreads();
  float g = gsh;

  /* combine per-stripe (m,s) partials (NSTRIPE=392 <= 512) */
  float m = -1e30f, s = 0.f;
  if (tid < NSTRIPE){
    m = g_pm[(long)tid*TB + rid];
    s = g_ps[(long)tid*TB + rid];
  }
  rm[tid]=m; rs[tid]=s; __syncthreads();
  for (int off=256; off>0; off>>=1){
    if (tid<off){
      float m2=rm[tid+off], s2=rs[tid+off];
      float M=fmaxf(rm[tid],m2);
      rs[tid]=rs[tid]*__expf(rm[tid]-M)+s2*__expf(m2-M);
      rm[tid]=M;
    }
    __syncthreads();
  }
  float M = rm[0];
  float gscale = g/rs[0];

  /* single pass: fp16 logit -> fp32 prob */
  const __half* lrow = g_l16 + (long)rid*VPAD;
  for (int j=tid; j<VOC; j+=512)
    row[j] = __expf(__half2float(lrow[j]) - M)*gscale;
  for (int j=VOC+tid; j<VE; j+=512) row[j] = 0.f;

  __threadfence(); __syncthreads();

  float omg = 1.f - g;
  const float* drow = dists + ((long)t*BATCH + b)*SEQ;
  for (int si=tid; si<SEQ; si+=512){
    int col = xids[(long)si*BATCH + b];
    atomicAdd(row + col, omg*drow[si]);
  }
}

/* ------------------------------- host ----------------------------------- */
template<int BMT, int DUAL>
static inline void launch_h16(const GH& p, int batches){
  constexpr int SM = 3*((BMT+BN)*128);
  static bool done = false;
  if (!done){
    cudaFuncSetAttribute(gemm_h16<BMT,DUAL>,
                         cudaFuncAttributeMaxDynamicSharedMemorySize, SM);
    done = true;
  }
  dim3 grid((p.M+BMT-1)/BMT, (p.N+BN-1)/BN, batches);
  gemm_h16<BMT,DUAL><<<grid, 256, SM>>>(p);
}

extern "C" void kernel_launch(void* const* d_in, const int* in_sizes, int n_in,
                              void* d_out, int out_size){
  const float* h    = (const float*)d_in[0];
  const float* yemb = (const float*)d_in[1];
  const float* mem  = (const float*)d_in[2];
  const unsigned char* mask = (const unsigned char*)d_in[3];
  const int* xids   = (const int*)d_in[4];
  int wb = 5;
  if (n_in >= 18 && in_sizes[5] == 1) wb = 6;
  const float* Wq = (const float*)d_in[wb+0];
  const float* bq = (const float*)d_in[wb+1];
  const float* Wk = (const float*)d_in[wb+2];
  const float* bk = (const float*)d_in[wb+3];
  const float* Wv = (const float*)d_in[wb+4];
  const float* bva= (const float*)d_in[wb+5];
  const float* Wo = (const float*)d_in[wb+6];
  const float* bo = (const float*)d_in[wb+7];
  const float* Wp = (const float*)d_in[wb+8];
  const float* bp = (const float*)d_in[wb+9];
  const float* vv = (const float*)d_in[wb+10];
  const float* bv = (const float*)d_in[wb+11];

  float* out   = (float*)d_out;
  float* dists = out + (long)TB*VE;

  cudaFuncSetAttribute(gemm_wp16, cudaFuncAttributeMaxDynamicSharedMemorySize, WSMEM);

  void *wbuf, *catp, *cat16p, *wp16p, *h16p, *mem16p, *w4p;
  void *q16p, *k16p, *valT16p, *w16p, *atts16p, *l16p, *pmp, *psp;
  cudaGetSymbolAddress(&wbuf, g_w);
  cudaGetSymbolAddress(&catp, g_cat);
  cudaGetSymbolAddress(&cat16p, g_cat16);
  cudaGetSymbolAddress(&wp16p, g_wp16);
  cudaGetSymbolAddress(&h16p, g_h16);
  cudaGetSymbolAddress(&mem16p, g_mem16);
  cudaGetSymbolAddress(&w4p, g_W416);
  cudaGetSymbolAddress(&q16p, g_q16);
  cudaGetSymbolAddress(&k16p, g_k16);
  cudaGetSymbolAddress(&valT16p, g_valT16);
  cudaGetSymbolAddress(&w16p, g_w16);
  cudaGetSymbolAddress(&atts16p, g_atts16);
  cudaGetSymbolAddress(&l16p, g_l16);
  cudaGetSymbolAddress(&pmp, g_pm);
  cudaGetSymbolAddress(&psp, g_ps);

  const __half* W16 = (const __half*)w4p;
  const __half* Wq16 = W16;
  const __half* Wk16 = W16 + (long)HID*HID;
  const __half* Wv16 = W16 + 2L*HID*HID;
  const __half* Wo16 = W16 + 3L*HID*HID;

  float scale = 1.0f/sqrtf((float)HID);

  /* conversions (MLP=4) */
  conv_wp16<<<WP_GRID, 256>>>(Wp);
  conv_mem16<<<MEM_GRID, 256>>>(mem);
  conv_wts16<<<WTS_GRID, 256>>>(Wq, Wk, Wv, Wo);

  /* cat[:,0:1024] = [h, y_emb] (fp32 + fp16) + h16 */
  cat_copy<<<(TB*(HID/4)+255)/256, 256>>>(h, yemb);

  GH p;

  /* q16 = (h16@Wq16^T + bq)*scale -> (B,T,H) fp16 */
  p = GH{};
  p.A = (const __half*)h16p; p.B = Wq16; p.Ch = (__half*)q16p;
  p.lda = HID; p.ldb = HID; p.ldc = HID;
  p.M = TB; p.N = HID; p.K = HID;
  p.bias = bq; p.alpha = scale;
  p.mode = 1; p.D1 = BATCH; p.D2 = T_LEN;
  launch_h16<64,0>(p, 1);

  /* fused k & val projection -> k16 (B,S,H), valT16 (B,H,S) */
  p = GH{};
  p.A = (const __half*)mem16p; p.B = Wk16; p.B2 = Wv16;
  p.Ch = (__half*)k16p; p.Ch2 = (__half*)valT16p;
  p.lda = HID; p.ldb = HID;
  p.M = SEQ*BATCH; p.N = 2*HID; p.K = HID;
  p.bias = bk; p.bias2 = bva;
  p.mode = 3;
  launch_h16<128,1>(p, 1);

  /* scores[b]: (T,S) = q16_b @ k16_b^T -> fp32 g_w */
  p = GH{};
  p.A = (const __half*)q16p; p.B = (const __half*)k16p; p.Cf = (float*)wbuf;
  p.lda = HID; p.ldb = HID; p.ldc = SEQ;
  p.sA = (long)T_LEN*HID; p.sB = (long)SEQ*HID; p.sC = (long)T_LEN*SEQ;
  p.M = T_LEN; p.N = SEQ; p.K = HID;
  p.mode = 0;
  launch_h16<64,0>(p, BATCH);

  softmax_s<<<BATCH*T_LEN, 128>>>(dists, mask);

  /* atts16[b]: (T,H) = w16_b @ valT16_b^T -> fp16 */
  p = GH{};
  p.A = (const __half*)w16p; p.B = (const __half*)valT16p; p.Ch = (__half*)atts16p;
  p.lda = SEQ; p.ldb = SEQ; p.ldc = HID;
  p.sA = (long)T_LEN*SEQ; p.sB = (long)HID*SEQ; p.sC = (long)T_LEN*HID;
  p.M = T_LEN; p.N = HID; p.K = SEQ;
  p.mode = 4;
  launch_h16<64,0>(p, BATCH);

  /* cat[:,1024:1536] = atts16@Wo16^T + bo (writes fp32 cat + fp16 cat16) */
  p = GH{};
  p.A = (const __half*)atts16p; p.B = Wo16;
  p.Cf = (float*)catp; p.Ch = (__half*)cat16p;
  p.lda = HID; p.ldb = HID; p.ldc = H3;
  p.M = TB; p.N = HID; p.K = HID;
  p.bias = bo;
  p.mode = 5; p.D1 = T_LEN; p.D2 = BATCH; p.col_off = 1024;
  launch_h16<64,0>(p, 1);

  /* logits = cat16@Wp16^T + bp -> fp16 l16 + per-stripe (m,s) partials */
  gemm_wp16<<<dim3(TB/WBM, VPAD/WBN2), 256, WSMEM>>>(
      (const __half*)cat16p, (const __half*)wp16p, bp,
      (__half*)l16p, (float*)pmp, (float*)psp);

  /* fused gate + final softmax + ext zero + scatter */
  softmax_v<<<TB, 512>>>(out, dists, xids, vv, bv);

  (void)out_size; (void)n_in;
}

// round 13
// speedup vs baseline: 1.1456x; 1.0021x over previous
#include <cuda_runtime.h>
#include <cuda_fp16.h>
#include <math.h>
#include <stdint.h>

#define T_LEN 64
#define BATCH 32
#define SEQ   400
#define HID   512
#define VOC   50000
#define EXTD  400
#define VE    (VOC+EXTD)
#define TB    (T_LEN*BATCH)     /* 2048 */
#define H3    (3*HID)           /* 1536 */
#define VPAD  50176             /* VOC padded to 256 */
#define NSTRIPE (VPAD/128)      /* 392 */

/* ---------------- scratch (device globals: allocation-free) -------------- */
__device__ float  g_cat [TB*H3];              /* (T*B,3H) fp32 (gate)        */
__device__ float  g_w   [BATCH*T_LEN*SEQ];    /* scores fp32 (B,T,S)         */
__device__ __half g_cat16[TB*H3];
__device__ __half g_wp16 [(long)VPAD*H3];
__device__ __half g_h16  [TB*HID];
__device__ __half g_mem16[SEQ*BATCH*HID];
__device__ __half g_W416 [4*HID*HID];         /* Wq,Wk,Wv,Wo                 */
__device__ __half g_q16  [BATCH*T_LEN*HID];   /* (B,T,H)                     */
__device__ __half g_k16  [BATCH*SEQ*HID];     /* (B,S,H)                     */
__device__ __half g_valT16[BATCH*HID*SEQ];    /* (B,H,S)                     */
__device__ __half g_w16  [BATCH*T_LEN*SEQ];   /* attn weights fp16           */
__device__ __half g_atts16[TB*HID];           /* (B,T,H) rows b*T+t          */
__device__ __half g_l16  [(long)TB*VPAD];     /* fp16 logits                 */
__device__ float  g_pm   [NSTRIPE*TB];        /* per-stripe softmax max      */
__device__ float  g_ps   [NSTRIPE*TB];        /* per-stripe softmax sum      */

#define BN 128

__device__ __forceinline__ void cpa16u(unsigned dst, const void* src, int bytes){
  asm volatile("cp.async.cg.shared.global [%0], [%1], 16, %2;\n"
               :: "r"(dst), "l"(src), "r"(bytes));
}
#define CPA_COMMIT() asm volatile("cp.async.commit_group;\n")
#define CPA_WAIT2()  asm volatile("cp.async.wait_group 2;\n")

#define LDSM_X4(r0,r1,r2,r3,addr) \
  asm volatile("ldmatrix.sync.aligned.m8n8.x4.shared.b16 {%0,%1,%2,%3}, [%4];" \
               : "=r"(r0), "=r"(r1), "=r"(r2), "=r"(r3) : "r"(addr))

#define MMA16(d, a0,a1,a2,a3, b0,b1) \
  asm volatile("mma.sync.aligned.m16n8k16.row.col.f32.f16.f16.f32 " \
               "{%0,%1,%2,%3}, {%4,%5,%6,%7}, {%8,%9}, {%0,%1,%2,%3};\n" \
               : "+f"((d)[0]), "+f"((d)[1]), "+f"((d)[2]), "+f"((d)[3]) \
               : "r"(a0), "r"(a1), "r"(a2), "r"(a3), "r"(b0), "r"(b1))

/* ---------------- generic fp16 MMA GEMM --------------------------------- */
struct GH {
  const __half* A; const __half* B; const __half* B2;
  float* Cf; __half* Ch; __half* Ch2;
  long lda, ldb, ldc;
  long sA, sB, sC;
  int  M, N, K;
  const float* bias; const float* bias2;
  float alpha;
  int  mode, D1, D2;
  long col_off;
};

__device__ __forceinline__ void epih(const GH& p, float* Cf, __half* Ch,
                                     int m, int n, float v){
  if (m >= p.M || n >= p.N) return;
  if (p.mode == 0){                           /* scores fp32 flat            */
    Cf[(long)m*p.ldc + n] = v; return;
  }
  if (p.mode == 1){                           /* q fp16 permuted + bias*alpha*/
    long idx = ((long)(m % p.D1)*p.D2 + m/p.D1)*p.ldc + n;
    Ch[idx] = __float2half_rn(p.alpha*(v + p.bias[n])); return;
  }
  if (p.mode == 3){                           /* dual k/val fp16             */
    int s = m / BATCH, b = m % BATCH;
    if (n < HID)
      p.Ch[((long)b*SEQ + s)*HID + n] = __float2half_rn(v + p.bias[n]);
    else {
      int nn = n - HID;
      p.Ch2[((long)b*HID + nn)*SEQ + s] = __float2half_rn(v + p.bias2[nn]);
    }
    return;
  }
  if (p.mode == 4){                           /* atts fp16 flat              */
    Ch[(long)m*p.ldc + n] = __float2half_rn(v); return;
  }
  /* mode 5: wo -> cat fp32 + cat16, permuted, col_off                       */
  long idx = ((long)(m % p.D1)*p.D2 + m/p.D1)*p.ldc + p.col_off + n;
  float o = v + p.bias[n];
  Cf[idx] = o;
  Ch[idx] = __float2half_rn(o);
}

template<int BMT, int DUAL>
__global__ __launch_bounds__(256,2) void gemm_h16(GH p){
  constexpr int WM   = BMT/32;
  constexpr int NCOL = BN/(8/WM);
  constexpr int NFR  = NCOL/8;
  constexpr int NBL  = NCOL/16;
  constexpr int ABYT = BMT*128;
  constexpr int SBYT = ABYT + BN*128;
  constexpr int GT   = (BMT+BN)*8;

  extern __shared__ float smf[];
  uint32_t sbase = (uint32_t)__cvta_generic_to_shared(smf);
  const __half* A  = p.A + (long)blockIdx.z * p.sA;
  const __half* Bg = p.B + (long)blockIdx.z * p.sB;
  float*  Cf = p.Cf ? p.Cf + (long)blockIdx.z * p.sC : (float*)0;
  __half* Ch = p.Ch ? p.Ch + (long)blockIdx.z * p.sC : (__half*)0;

  int tid = threadIdx.x;
  int lane = tid & 31, warp = tid >> 5;
  int wm = warp % WM, wn = warp / WM;
  int m0 = blockIdx.x * BMT, n0 = blockIdx.y * BN;

  float acc[2][NFR][4];
  #pragma unroll
  for (int i=0;i<2;i++)
    #pragma unroll
    for (int j=0;j<NFR;j++){ acc[i][j][0]=0.f; acc[i][j][1]=0.f; acc[i][j][2]=0.f; acc[i][j][3]=0.f; }

  int ktiles = (p.K + 63)/64;

  auto load = [&](int st, int k0){
    uint32_t ab = sbase + st*SBYT;
    uint32_t bb = ab + ABYT;
    #pragma unroll
    for (int i=0;i<GT/256;i++){
      int g = tid + i*256;
      int r = g >> 3, gc = g & 7;
      int kcol = k0 + gc*8;
      int kb = (kcol < p.K) ? 16 : 0;
      if (r < BMT){
        uint32_t soff = (uint32_t)(r*128 + ((gc ^ (r&7))<<4));
        int gm = m0 + r;
        cpa16u(ab + soff, A + (long)gm*p.lda + kcol, (gm < p.M) ? kb : 0);
      } else {
        int rb = r - BMT;
        uint32_t soff = (uint32_t)(rb*128 + ((gc ^ (rb&7))<<4));
        int gn = n0 + rb;
        const __half* src;
        if (DUAL && gn >= HID) src = p.B2 + (long)(gn-HID)*p.ldb + kcol;
        else                   src = Bg  + (long)gn*p.ldb + kcol;
        cpa16u(bb + soff, src, (gn < p.N) ? kb : 0);
      }
    }
  };

  load(0, 0); CPA_COMMIT();
  load(1, 64); CPA_COMMIT();

  int mi1 = (lane >> 3) & 1;
  int kg2 = lane >> 4;
  int ri  = lane & 7;
  int marow = wm*32 + mi1*8 + ri;
  int nbrow = wn*NCOL + mi1*8 + ri;
  int maxor = (marow & 7);
  int nbxor = (nbrow & 7);

  for (int kt = 0; kt < ktiles; kt++){
    if (kt + 2 < ktiles) load((kt+2)%3, (kt+2)*64);
    CPA_COMMIT();
    CPA_WAIT2();
    __syncthreads();

    uint32_t ab = sbase + (kt%3)*SBYT;
    uint32_t aA = ab + marow*128;
    uint32_t aB = ab + ABYT + nbrow*128;

    #pragma unroll
    for (int kk=0; kk<4; kk++){
      uint32_t asw = (uint32_t)(((kk*2 + kg2) ^ maxor) << 4);
      uint32_t bsw = (uint32_t)(((kk*2 + kg2) ^ nbxor) << 4);
      unsigned af0[4], af1[4], bf[NBL][4];
      LDSM_X4(af0[0],af0[1],af0[2],af0[3], aA + asw);
      LDSM_X4(af1[0],af1[1],af1[2],af1[3], aA + asw + 16*128);
      #pragma unroll
      for (int jp=0; jp<NBL; jp++)
        LDSM_X4(bf[jp][0],bf[jp][1],bf[jp][2],bf[jp][3], aB + bsw + jp*16*128);
      #pragma unroll
      for (int jp=0; jp<NBL; jp++){
        MMA16(acc[0][2*jp  ], af0[0],af0[1],af0[2],af0[3], bf[jp][0], bf[jp][2]);
        MMA16(acc[0][2*jp+1], af0[0],af0[1],af0[2],af0[3], bf[jp][1], bf[jp][3]);
        MMA16(acc[1][2*jp  ], af1[0],af1[1],af1[2],af1[3], bf[jp][0], bf[jp][2]);
        MMA16(acc[1][2*jp+1], af1[0],af1[1],af1[2],af1[3], bf[jp][1], bf[jp][3]);
      }
    }
    __syncthreads();
  }

  int r = lane >> 2, c2 = (lane & 3)*2;
  #pragma unroll
  for (int im=0; im<2; im++)
    #pragma unroll
    for (int jn=0; jn<NFR; jn++){
      int mr = m0 + wm*32 + im*16 + r;
      int nc = n0 + wn*NCOL + jn*8 + c2;
      epih(p, Cf, Ch, mr,   nc,   acc[im][jn][0]);
      epih(p, Cf, Ch, mr,   nc+1, acc[im][jn][1]);
      epih(p, Cf, Ch, mr+8, nc,   acc[im][jn][2]);
      epih(p, Cf, Ch, mr+8, nc+1, acc[im][jn][3]);
    }
}

/* ---------------- fp16 converters (MLP=4: 4 independent float4/thread) --- */
#define WP_TOT4  ((long)VPAD*(H3/4))
#define WP_GRID  18816
#define WP_STRIDE ((long)WP_GRID*256)
__global__ void conv_wp16(const float* __restrict__ Wp){
  long i0 = (long)blockIdx.x*256 + threadIdx.x;
  float4 v[4];
  long idx[4];
  #pragma unroll
  for (int u=0; u<4; u++){
    long i = i0 + (long)u*WP_STRIDE;
    idx[u] = i;
    long row = i / (H3/4);
    long c4  = i % (H3/4);
    v[u] = (row < VOC) ? *(const float4*)(Wp + row*H3 + c4*4)
                       : make_float4(0.f,0.f,0.f,0.f);
  }
  __half2* dst = (__half2*)g_wp16;
  #pragma unroll
  for (int u=0; u<4; u++){
    dst[idx[u]*2]   = __floats2half2_rn(v[u].x, v[u].y);
    dst[idx[u]*2+1] = __floats2half2_rn(v[u].z, v[u].w);
  }
}
#define MEM_GRID 1600
#define MEM_STRIDE ((long)MEM_GRID*256)
__global__ void conv_mem16(const float* __restrict__ mem){
  long i0 = (long)blockIdx.x*256 + threadIdx.x;
  float4 v[4];
  #pragma unroll
  for (int u=0; u<4; u++) v[u] = *(const float4*)(mem + (i0 + (long)u*MEM_STRIDE)*4);
  __half2* dst = (__half2*)g_mem16;
  #pragma unroll
  for (int u=0; u<4; u++){
    long i = i0 + (long)u*MEM_STRIDE;
    dst[i*2]   = __floats2half2_rn(v[u].x, v[u].y);
    dst[i*2+1] = __floats2half2_rn(v[u].z, v[u].w);
  }
}
#define WTS_GRID 256
#define WTS_STRIDE (WTS_GRID*256)
__global__ void conv_wts16(const float* __restrict__ Wq, const float* __restrict__ Wk,
                           const float* __restrict__ Wv, const float* __restrict__ Wo){
  int i0 = blockIdx.x*256 + threadIdx.x;
  const int per = HID*HID/4;
  float4 v[4];
  #pragma unroll
  for (int u=0; u<4; u++){
    int i = i0 + u*WTS_STRIDE;
    int seg = i / per, off = i % per;
    const float* src = (seg==0)?Wq:(seg==1)?Wk:(seg==2)?Wv:Wo;
    v[u] = *(const float4*)(src + (long)off*4);
  }
  __half2* dst = (__half2*)g_W416;
  #pragma unroll
  for (int u=0; u<4; u++){
    int i = i0 + u*WTS_STRIDE;
    dst[i*2]   = __floats2half2_rn(v[u].x, v[u].y);
    dst[i*2+1] = __floats2half2_rn(v[u].z, v[u].w);
  }
}

/* == fp16 Wp GEMM: 128x128 CTA, 256 thr, 2 CTA/SM, fused softmax stats === */
#define WBM 128
#define WBN2 128
#define WABY (WBM*128)
#define WSBY (WABY + WBN2*128)
#define WSMEM (3*WSBY)

__device__ __forceinline__ void merge_ms(float& m, float& s, float m2, float s2){
  float M = fmaxf(m, m2);
  s = s*__expf(m-M) + s2*__expf(m2-M);
  m = M;
}

__global__ __launch_bounds__(256,2) void gemm_wp16(
    const __half* __restrict__ A, const __half* __restrict__ B,
    const float* __restrict__ bias, __half* __restrict__ l16,
    float* __restrict__ pm, float* __restrict__ ps)
{
  extern __shared__ float smf[];
  __shared__ float red_m[2][128], red_s[2][128];
  uint32_t sbase = (uint32_t)__cvta_generic_to_shared(smf);
  int tid = threadIdx.x;
  int lane = tid & 31, warp = tid >> 5;
  int wm = warp & 3, wn = warp >> 2;
  int m0 = blockIdx.x * WBM, n0 = blockIdx.y * WBN2;

  float acc[2][8][4];
  #pragma unroll
  for (int i=0;i<2;i++)
    #pragma unroll
    for (int j=0;j<8;j++){ acc[i][j][0]=0.f; acc[i][j][1]=0.f; acc[i][j][2]=0.f; acc[i][j][3]=0.f; }

  const int ktiles = H3/64;

  auto load = [&](int st, int k0){
    uint32_t ab = sbase + st*WSBY;
    uint32_t bb = ab + WABY;
    #pragma unroll
    for (int i=0;i<8;i++){
      int g = tid + i*256;
      int r = g >> 3, gc = g & 7;
      int kcol = k0 + gc*8;
      if (r < WBM){
        uint32_t soff = (uint32_t)(r*128 + ((gc ^ (r&7))<<4));
        cpa16u(ab + soff, A + (long)(m0 + r)*H3 + kcol, 16);
      } else {
        int rb = r - WBM;
        uint32_t soff = (uint32_t)(rb*128 + ((gc ^ (rb&7))<<4));
        cpa16u(bb + soff, B + (long)(n0 + rb)*H3 + kcol, 16);
      }
    }
  };

  load(0, 0); CPA_COMMIT();
  load(1, 64); CPA_COMMIT();

  int mi1 = (lane >> 3) & 1;
  int kg2 = lane >> 4;
  int ri  = lane & 7;
  int marow = wm*32 + mi1*8 + ri;
  int nbrow = wn*64 + mi1*8 + ri;
  int maxor = (marow & 7);
  int nbxor = (nbrow & 7);

  for (int kt = 0; kt < ktiles; kt++){
    if (kt + 2 < ktiles) load((kt+2)%3, (kt+2)*64);
    CPA_COMMIT();
    CPA_WAIT2();
    __syncthreads();

    uint32_t ab = sbase + (kt%3)*WSBY;
    uint32_t aA = ab + marow*128;
    uint32_t aB = ab + WABY + nbrow*128;

    #pragma unroll
    for (int kk=0; kk<4; kk++){
      uint32_t asw = (uint32_t)(((kk*2 + kg2) ^ maxor) << 4);
      uint32_t bsw = (uint32_t)(((kk*2 + kg2) ^ nbxor) << 4);
      unsigned af0[4], af1[4], bf[4][4];
      LDSM_X4(af0[0],af0[1],af0[2],af0[3], aA + asw);
      LDSM_X4(af1[0],af1[1],af1[2],af1[3], aA + asw + 16*128);
      #pragma unroll
      for (int jb=0; jb<4; jb++)
        LDSM_X4(bf[jb][0],bf[jb][1],bf[jb][2],bf[jb][3], aB + bsw + jb*16*128);
      #pragma unroll
      for (int jb=0; jb<4; jb++){
        MMA16(acc[0][2*jb  ], af0[0],af0[1],af0[2],af0[3], bf[jb][0], bf[jb][2]);
        MMA16(acc[0][2*jb+1], af0[0],af0[1],af0[2],af0[3], bf[jb][1], bf[jb][3]);
        MMA16(acc[1][2*jb  ], af1[0],af1[1],af1[2],af1[3], bf[jb][0], bf[jb][2]);
        MMA16(acc[1][2*jb+1], af1[0],af1[1],af1[2],af1[3], bf[jb][1], bf[jb][3]);
      }
    }
    __syncthreads();
  }

  int r2 = lane >> 2, c2 = (lane & 3)*2;
  #pragma unroll
  for (int im=0; im<2; im++){
    int mr = m0 + wm*32 + im*16 + r2;
    float m0v=-1e30f, m1v=-1e30f, s0v=0.f, s1v=0.f;
    #pragma unroll
    for (int nj=0; nj<8; nj++){
      int nc = n0 + wn*64 + nj*8 + c2;
      if (nc < VOC){
        float b0 = bias[nc], b1 = bias[nc+1];
        float v00 = acc[im][nj][0]+b0, v01 = acc[im][nj][1]+b1;
        float v10 = acc[im][nj][2]+b0, v11 = acc[im][nj][3]+b1;
        acc[im][nj][0]=v00; acc[im][nj][1]=v01;
        acc[im][nj][2]=v10; acc[im][nj][3]=v11;
        *(__half2*)(l16 + (long)mr*VPAD + nc)     = __floats2half2_rn(v00,v01);
        *(__half2*)(l16 + (long)(mr+8)*VPAD + nc) = __floats2half2_rn(v10,v11);
        m0v = fmaxf(m0v, fmaxf(v00,v01));
        m1v = fmaxf(m1v, fmaxf(v10,v11));
      }
    }
    #pragma unroll
    for (int nj=0; nj<8; nj++){
      int nc = n0 + wn*64 + nj*8 + c2;
      if (nc < VOC){
        s0v += __expf(acc[im][nj][0]-m0v) + __expf(acc[im][nj][1]-m0v);
        s1v += __expf(acc[im][nj][2]-m1v) + __expf(acc[im][nj][3]-m1v);
      }
    }
    #pragma unroll
    for (int off=1; off<4; off<<=1){
      float om0 = __shfl_xor_sync(0xFFFFFFFFu, m0v, off);
      float os0 = __shfl_xor_sync(0xFFFFFFFFu, s0v, off);
      merge_ms(m0v, s0v, om0, os0);
      float om1 = __shfl_xor_sync(0xFFFFFFFFu, m1v, off);
      float os1 = __shfl_xor_sync(0xFFFFFFFFu, s1v, off);
      merge_ms(m1v, s1v, om1, os1);
    }
    if ((lane & 3) == 0){
      int rl = wm*32 + im*16 + r2;
      red_m[wn][rl]   = m0v; red_s[wn][rl]   = s0v;
      red_m[wn][rl+8] = m1v; red_s[wn][rl+8] = s1v;
    }
  }
  __syncthreads();
  if (tid < 128){
    float M = red_m[0][tid], S = red_s[0][tid];
    merge_ms(M, S, red_m[1][tid], red_s[1][tid]);
    pm[(long)blockIdx.y*TB + m0 + tid] = M;
    ps[(long)blockIdx.y*TB + m0 + tid] = S;
  }
}

/* -------- cat[:,0:1024] = [h,y_emb] (fp32 + fp16) + h16 ------------------ */
__global__ void cat_copy(const float* __restrict__ h, const float* __restrict__ y){
  int i = blockIdx.x*blockDim.x + threadIdx.x;
  if (i >= TB*(HID/4)) return;
  int row = i / (HID/4);
  int c   = i % (HID/4);
  const float4 hv = ((const float4*)h)[i];
  const float4 yv = ((const float4*)y)[i];
  float4* cat4 = (float4*)g_cat;
  cat4[(long)row*(H3/4) + c]           = hv;
  cat4[(long)row*(H3/4) + (HID/4) + c] = yv;
  __half2* c16 = (__half2*)g_cat16;
  long b = (long)row*(H3/2);
  __half2 h01 = __floats2half2_rn(hv.x, hv.y);
  __half2 h23 = __floats2half2_rn(hv.z, hv.w);
  c16[b + c*2]               = h01;
  c16[b + c*2 + 1]           = h23;
  c16[b + (HID/2) + c*2]     = __floats2half2_rn(yv.x, yv.y);
  c16[b + (HID/2) + c*2 + 1] = __floats2half2_rn(yv.z, yv.w);
  __half2* h16 = (__half2*)g_h16;
  h16[i*2]   = h01;
  h16[i*2+1] = h23;
}

/* ------ softmax over S; writes w16 (B,T,S) + dists fp32 (T,B,S) ---------- */
__global__ void softmax_s(float* __restrict__ dists, const unsigned char* __restrict__ mask){
  int bt = blockIdx.x;
  int b = bt / T_LEN, t = bt % T_LEN;
  float* row = g_w + (long)bt*SEQ;
  const unsigned char* mrow = mask + (long)b*SEQ;
  int tid = threadIdx.x;
  __shared__ float red[128];
  float mx = -1e30f;
  for (int s=tid; s<SEQ; s+=128){
    float x = mrow[s] ? -1e9f : row[s];
    mx = fmaxf(mx, x);
  }
  red[tid]=mx; __syncthreads();
  for (int off=64; off>0; off>>=1){ if (tid<off) red[tid]=fmaxf(red[tid],red[tid+off]); __syncthreads(); }
  mx = red[0]; __syncthreads();
  float sum=0.f;
  for (int s=tid; s<SEQ; s+=128){
    float x = mrow[s] ? -1e9f : row[s];
    sum += __expf(x-mx);
  }
  red[tid]=sum; __syncthreads();
  for (int off=64; off>0; off>>=1){ if (tid<off) red[tid]+=red[tid+off]; __syncthreads(); }
  float inv = 1.f/red[0];
  for (int s=tid; s<SEQ; s+=128){
    float x = mrow[s] ? -1e9f : row[s];
    float wv = __expf(x-mx)*inv;
    g_w16[(long)bt*SEQ + s] = __float2half_rn(wv);
    dists[((long)t*BATCH + b)*SEQ + s] = wv;
  }
}

/* -------- fused: gate + final softmax (from partials) + scatter ---------- */
__global__ void softmax_v(float* __restrict__ out, const float* __restrict__ dists,
                          const int* __restrict__ xids,
                          const float* __restrict__ vv, const float* __restrict__ bvv){
  int rid = blockIdx.x;
  int b = rid % BATCH, t = rid / BATCH;
  float* row = out + (long)rid*VE;
  int tid = threadIdx.x;
  __shared__ float rm[512], rs[512];
  __shared__ float gsh;

  const float* cr = g_cat + (long)rid*H3;
  float s0 = 0.f;
  for (int j=tid; j<H3; j+=512) s0 += cr[j]*vv[j];
  rm[tid]=s0; __syncthreads();
  for (int off=256; off>0; off>>=1){ if (tid<off) rm[tid]+=rm[tid+off]; __syncthreads(); }
  if (tid==0) gsh = 1.f/(1.f+__expf(-(rm[0]+bvv[0])));
  __syncthreads();
  float g = gsh;

  float m = -1e30f, s = 0.f;
  if (tid < NSTRIPE){
    m = g_pm[(long)tid*TB + rid];
    s = g_ps[(long)tid*TB + rid];
  }
  rm[tid]=m; rs[tid]=s; __syncthreads();
  for (int off=256; off>0; off>>=1){
    if (tid<off){
      float m2=rm[tid+off], s2=rs[tid+off];
      float M=fmaxf(rm[tid],m2);
      rs[tid]=rs[tid]*__expf(rm[tid]-M)+s2*__expf(m2-M);
      rm[tid]=M;
    }
    __syncthreads();
  }
  float M = rm[0];
  float gscale = g/rs[0];

  const __half* lrow = g_l16 + (long)rid*VPAD;
  for (int j=tid; j<VOC; j+=512)
    row[j] = __expf(__half2float(lrow[j]) - M)*gscale;
  for (int j=VOC+tid; j<VE; j+=512) row[j] = 0.f;

  __threadfence(); __syncthreads();

  float omg = 1.f - g;
  const float* drow = dists + ((long)t*BATCH + b)*SEQ;
  for (int si=tid; si<SEQ; si+=512){
    int col = xids[(long)si*BATCH + b];
    atomicAdd(row + col, omg*drow[si]);
  }
}

/* ------------------------------- host ----------------------------------- */
template<int BMT, int DUAL>
static inline void launch_h16(const GH& p, int batches, cudaStream_t st){
  constexpr int SM = 3*((BMT+BN)*128);
  static bool done = false;
  if (!done){
    cudaFuncSetAttribute(gemm_h16<BMT,DUAL>,
                         cudaFuncAttributeMaxDynamicSharedMemorySize, SM);
    done = true;
  }
  dim3 grid((p.M+BMT-1)/BMT, (p.N+BN-1)/BN, batches);
  gemm_h16<BMT,DUAL><<<grid, 256, SM, st>>>(p);
}

extern "C" void kernel_launch(void* const* d_in, const int* in_sizes, int n_in,
                              void* d_out, int out_size){
  const float* h    = (const float*)d_in[0];
  const float* yemb = (const float*)d_in[1];
  const float* mem  = (const float*)d_in[2];
  const unsigned char* mask = (const unsigned char*)d_in[3];
  const int* xids   = (const int*)d_in[4];
  int wb = 5;
  if (n_in >= 18 && in_sizes[5] == 1) wb = 6;
  const float* Wq = (const float*)d_in[wb+0];
  const float* bq = (const float*)d_in[wb+1];
  const float* Wk = (const float*)d_in[wb+2];
  const float* bk = (const float*)d_in[wb+3];
  const float* Wv = (const float*)d_in[wb+4];
  const float* bva= (const float*)d_in[wb+5];
  const float* Wo = (const float*)d_in[wb+6];
  const float* bo = (const float*)d_in[wb+7];
  const float* Wp = (const float*)d_in[wb+8];
  const float* bp = (const float*)d_in[wb+9];
  const float* vv = (const float*)d_in[wb+10];
  const float* bv = (const float*)d_in[wb+11];

  float* out   = (float*)d_out;
  float* dists = out + (long)TB*VE;

  cudaFuncSetAttribute(gemm_wp16, cudaFuncAttributeMaxDynamicSharedMemorySize, WSMEM);

  /* side stream + events (created once; host-side objects only) */
  static cudaStream_t s1 = 0;
  static cudaEvent_t evF = 0, evJ = 0, evF2 = 0, evJ2 = 0;
  if (!s1){
    cudaStreamCreateWithFlags(&s1, cudaStreamNonBlocking);
    cudaEventCreateWithFlags(&evF,  cudaEventDisableTiming);
    cudaEventCreateWithFlags(&evJ,  cudaEventDisableTiming);
    cudaEventCreateWithFlags(&evF2, cudaEventDisableTiming);
    cudaEventCreateWithFlags(&evJ2, cudaEventDisableTiming);
  }

  void *wbuf, *catp, *cat16p, *wp16p, *h16p, *mem16p, *w4p;
  void *q16p, *k16p, *valT16p, *w16p, *atts16p, *l16p, *pmp, *psp;
  cudaGetSymbolAddress(&wbuf, g_w);
  cudaGetSymbolAddress(&catp, g_cat);
  cudaGetSymbolAddress(&cat16p, g_cat16);
  cudaGetSymbolAddress(&wp16p, g_wp16);
  cudaGetSymbolAddress(&h16p, g_h16);
  cudaGetSymbolAddress(&mem16p, g_mem16);
  cudaGetSymbolAddress(&w4p, g_W416);
  cudaGetSymbolAddress(&q16p, g_q16);
  cudaGetSymbolAddress(&k16p, g_k16);
  cudaGetSymbolAddress(&valT16p, g_valT16);
  cudaGetSymbolAddress(&w16p, g_w16);
  cudaGetSymbolAddress(&atts16p, g_atts16);
  cudaGetSymbolAddress(&l16p, g_l16);
  cudaGetSymbolAddress(&pmp, g_pm);
  cudaGetSymbolAddress(&psp, g_ps);

  const __half* W16 = (const __half*)w4p;
  const __half* Wq16 = W16;
  const __half* Wk16 = W16 + (long)HID*HID;
  const __half* Wv16 = W16 + 2L*HID*HID;
  const __half* Wo16 = W16 + 3L*HID*HID;

  float scale = 1.0f/sqrtf((float)HID);

  /* ---- fork: conv_wp16 runs on s1, overlapping the whole attention chain */
  cudaEventRecord(evF, 0);
  cudaStreamWaitEvent(s1, evF, 0);
  conv_wp16<<<WP_GRID, 256, 0, s1>>>(Wp);
  cudaEventRecord(evJ, s1);

  /* ---- main chain on the default stream */
  conv_mem16<<<MEM_GRID, 256>>>(mem);
  conv_wts16<<<WTS_GRID, 256>>>(Wq, Wk, Wv, Wo);
  cat_copy<<<(TB*(HID/4)+255)/256, 256>>>(h, yemb);

  GH p;

  /* fork q to s1's logical successor? q needs h16+Wq16 (cat_copy, conv_wts16)
     -> fork point is here, after both. q runs concurrently with k/v.        */
  cudaEventRecord(evF2, 0);
  cudaStreamWaitEvent(s1, evF2, 0);
  p = GH{};
  p.A = (const __half*)h16p; p.B = Wq16; p.Ch = (__half*)q16p;
  p.lda = HID; p.ldb = HID; p.ldc = HID;
  p.M = TB; p.N = HID; p.K = HID;
  p.bias = bq; p.alpha = scale;
  p.mode = 1; p.D1 = BATCH; p.D2 = T_LEN;
  launch_h16<64,0>(p, 1, s1);
  cudaEventRecord(evJ2, s1);

  /* fused k & val projection -> k16 (B,S,H), valT16 (B,H,S) */
  p = GH{};
  p.A = (const __half*)mem16p; p.B = Wk16; p.B2 = Wv16;
  p.Ch = (__half*)k16p; p.Ch2 = (__half*)valT16p;
  p.lda = HID; p.ldb = HID;
  p.M = SEQ*BATCH; p.N = 2*HID; p.K = HID;
  p.bias = bk; p.bias2 = bva;
  p.mode = 3;
  launch_h16<128,1>(p, 1, 0);

  /* join q before scores */
  cudaStreamWaitEvent(0, evJ2, 0);

  /* scores[b]: (T,S) = q16_b @ k16_b^T -> fp32 g_w */
  p = GH{};
  p.A = (const __half*)q16p; p.B = (const __half*)k16p; p.Cf = (float*)wbuf;
  p.lda = HID; p.ldb = HID; p.ldc = SEQ;
  p.sA = (long)T_LEN*HID; p.sB = (long)SEQ*HID; p.sC = (long)T_LEN*SEQ;
  p.M = T_LEN; p.N = SEQ; p.K = HID;
  p.mode = 0;
  launch_h16<64,0>(p, BATCH, 0);

  softmax_s<<<BATCH*T_LEN, 128>>>(dists, mask);

  /* atts16[b]: (T,H) = w16_b @ valT16_b^T -> fp16 */
  p = GH{};
  p.A = (const __half*)w16p; p.B = (const __half*)valT16p; p.Ch = (__half*)atts16p;
  p.lda = SEQ; p.ldb = SEQ; p.ldc = HID;
  p.sA = (long)T_LEN*SEQ; p.sB = (long)HID*SEQ; p.sC = (long)T_LEN*HID;
  p.M = T_LEN; p.N = HID; p.K = SEQ;
  p.mode = 4;
  launch_h16<64,0>(p, BATCH, 0);

  /* cat[:,1024:1536] = atts16@Wo16^T + bo (writes fp32 cat + fp16 cat16) */
  p = GH{};
  p.A = (const __half*)atts16p; p.B = Wo16;
  p.Cf = (float*)catp; p.Ch = (__half*)cat16p;
  p.lda = HID; p.ldb = HID; p.ldc = H3;
  p.M = TB; p.N = HID; p.K = HID;
  p.bias = bo;
  p.mode = 5; p.D1 = T_LEN; p.D2 = BATCH; p.col_off = 1024;
  launch_h16<64,0>(p, 1, 0);

  /* join conv_wp16 before the big GEMM */
  cudaStreamWaitEvent(0, evJ, 0);

  /* logits = cat16@Wp16^T + bp -> fp16 l16 + per-stripe (m,s) partials */
  gemm_wp16<<<dim3(TB/WBM, VPAD/WBN2), 256, WSMEM>>>(
      (const __half*)cat16p, (const __half*)wp16p, bp,
      (__half*)l16p, (float*)pmp, (float*)psp);

  /* fused gate + final softmax + ext zero + scatter */
  softmax_v<<<TB, 512>>>(out, dists, xids, vv, bv);

  (void)out_size; (void)n_in;
}

// round 14
// speedup vs baseline: 1.2027x; 1.0498x over previous
#include <cuda_runtime.h>
#include <cuda_fp16.h>
#include <math.h>
#include <stdint.h>

#define T_LEN 64
#define BATCH 32
#define SEQ   400
#define HID   512
#define VOC   50000
#define EXTD  400
#define VE    (VOC+EXTD)
#define TB    (T_LEN*BATCH)     /* 2048 */
#define H3    (3*HID)           /* 1536 */
#define VPAD  50176             /* VOC padded to 256 */
#define NSTRIPE (VPAD/128)      /* 392 */

/* ---------------- scratch (device globals: allocation-free) -------------- */
__device__ float  g_cat [TB*H3];              /* (T*B,3H) fp32 (gate)        */
__device__ float  g_w   [BATCH*T_LEN*SEQ];    /* scores fp32 (B,T,S)         */
__device__ __half g_cat16[TB*H3];
__device__ __half g_wp16 [(long)VPAD*H3];
__device__ __half g_h16  [TB*HID];
__device__ __half g_mem16[SEQ*BATCH*HID];
__device__ __half g_W416 [4*HID*HID];         /* Wq,Wk,Wv,Wo                 */
__device__ __half g_q16  [BATCH*T_LEN*HID];   /* (B,T,H)                     */
__device__ __half g_k16  [BATCH*SEQ*HID];     /* (B,S,H)                     */
__device__ __half g_valT16[BATCH*HID*SEQ];    /* (B,H,S)                     */
__device__ __half g_w16  [BATCH*T_LEN*SEQ];   /* attn weights fp16           */
__device__ __half g_atts16[TB*HID];           /* (B,T,H) rows b*T+t          */
__device__ __half g_l16  [(long)TB*VPAD];     /* fp16 logits                 */
__device__ float  g_pm   [NSTRIPE*TB];        /* per-stripe softmax max      */
__device__ float  g_ps   [NSTRIPE*TB];        /* per-stripe softmax sum      */
__device__ float  g_gscale[TB];               /* g / sumexp                  */
__device__ float  g_M    [TB];                /* row max                     */
__device__ float  g_omg  [TB];                /* 1 - g                       */

#define BN 128

__device__ __forceinline__ void cpa16u(unsigned dst, const void* src, int bytes){
  asm volatile("cp.async.cg.shared.global [%0], [%1], 16, %2;\n"
               :: "r"(dst), "l"(src), "r"(bytes));
}
#define CPA_COMMIT() asm volatile("cp.async.commit_group;\n")
#define CPA_WAIT2()  asm volatile("cp.async.wait_group 2;\n")

#define LDSM_X4(r0,r1,r2,r3,addr) \
  asm volatile("ldmatrix.sync.aligned.m8n8.x4.shared.b16 {%0,%1,%2,%3}, [%4];" \
               : "=r"(r0), "=r"(r1), "=r"(r2), "=r"(r3) : "r"(addr))

#define MMA16(d, a0,a1,a2,a3, b0,b1) \
  asm volatile("mma.sync.aligned.m16n8k16.row.col.f32.f16.f16.f32 " \
               "{%0,%1,%2,%3}, {%4,%5,%6,%7}, {%8,%9}, {%0,%1,%2,%3};\n" \
               : "+f"((d)[0]), "+f"((d)[1]), "+f"((d)[2]), "+f"((d)[3]) \
               : "r"(a0), "r"(a1), "r"(a2), "r"(a3), "r"(b0), "r"(b1))

/* ---------------- generic fp16 MMA GEMM --------------------------------- */
struct GH {
  const __half* A; const __half* B; const __half* B2;
  float* Cf; __half* Ch; __half* Ch2;
  long lda, ldb, ldc;
  long sA, sB, sC;
  int  M, N, K;
  const float* bias; const float* bias2;
  float alpha;
  int  mode, D1, D2;
  long col_off;
};

__device__ __forceinline__ void epih(const GH& p, float* Cf, __half* Ch,
                                     int m, int n, float v){
  if (m >= p.M || n >= p.N) return;
  if (p.mode == 0){                           /* scores fp32 flat            */
    Cf[(long)m*p.ldc + n] = v; return;
  }
  if (p.mode == 1){                           /* q fp16 permuted + bias*alpha*/
    long idx = ((long)(m % p.D1)*p.D2 + m/p.D1)*p.ldc + n;
    Ch[idx] = __float2half_rn(p.alpha*(v + p.bias[n])); return;
  }
  if (p.mode == 3){                           /* dual k/val fp16             */
    int s = m / BATCH, b = m % BATCH;
    if (n < HID)
      p.Ch[((long)b*SEQ + s)*HID + n] = __float2half_rn(v + p.bias[n]);
    else {
      int nn = n - HID;
      p.Ch2[((long)b*HID + nn)*SEQ + s] = __float2half_rn(v + p.bias2[nn]);
    }
    return;
  }
  if (p.mode == 4){                           /* atts fp16 flat              */
    Ch[(long)m*p.ldc + n] = __float2half_rn(v); return;
  }
  /* mode 5: wo -> cat fp32 + cat16, permuted, col_off                       */
  long idx = ((long)(m % p.D1)*p.D2 + m/p.D1)*p.ldc + p.col_off + n;
  float o = v + p.bias[n];
  Cf[idx] = o;
  Ch[idx] = __float2half_rn(o);
}

template<int BMT, int DUAL>
__global__ __launch_bounds__(256,2) void gemm_h16(GH p){
  constexpr int WM   = BMT/32;
  constexpr int NCOL = BN/(8/WM);
  constexpr int NFR  = NCOL/8;
  constexpr int NBL  = NCOL/16;
  constexpr int ABYT = BMT*128;
  constexpr int SBYT = ABYT + BN*128;
  constexpr int GT   = (BMT+BN)*8;

  extern __shared__ float smf[];
  uint32_t sbase = (uint32_t)__cvta_generic_to_shared(smf);
  const __half* A  = p.A + (long)blockIdx.z * p.sA;
  const __half* Bg = p.B + (long)blockIdx.z * p.sB;
  float*  Cf = p.Cf ? p.Cf + (long)blockIdx.z * p.sC : (float*)0;
  __half* Ch = p.Ch ? p.Ch + (long)blockIdx.z * p.sC : (__half*)0;

  int tid = threadIdx.x;
  int lane = tid & 31, warp = tid >> 5;
  int wm = warp % WM, wn = warp / WM;
  int m0 = blockIdx.x * BMT, n0 = blockIdx.y * BN;

  float acc[2][NFR][4];
  #pragma unroll
  for (int i=0;i<2;i++)
    #pragma unroll
    for (int j=0;j<NFR;j++){ acc[i][j][0]=0.f; acc[i][j][1]=0.f; acc[i][j][2]=0.f; acc[i][j][3]=0.f; }

  int ktiles = (p.K + 63)/64;

  auto load = [&](int st, int k0){
    uint32_t ab = sbase + st*SBYT;
    uint32_t bb = ab + ABYT;
    #pragma unroll
    for (int i=0;i<GT/256;i++){
      int g = tid + i*256;
      int r = g >> 3, gc = g & 7;
      int kcol = k0 + gc*8;
      int kb = (kcol < p.K) ? 16 : 0;
      if (r < BMT){
        uint32_t soff = (uint32_t)(r*128 + ((gc ^ (r&7))<<4));
        int gm = m0 + r;
        cpa16u(ab + soff, A + (long)gm*p.lda + kcol, (gm < p.M) ? kb : 0);
      } else {
        int rb = r - BMT;
        uint32_t soff = (uint32_t)(rb*128 + ((gc ^ (rb&7))<<4));
        int gn = n0 + rb;
        const __half* src;
        if (DUAL && gn >= HID) src = p.B2 + (long)(gn-HID)*p.ldb + kcol;
        else                   src = Bg  + (long)gn*p.ldb + kcol;
        cpa16u(bb + soff, src, (gn < p.N) ? kb : 0);
      }
    }
  };

  load(0, 0); CPA_COMMIT();
  load(1, 64); CPA_COMMIT();

  int mi1 = (lane >> 3) & 1;
  int kg2 = lane >> 4;
  int ri  = lane & 7;
  int marow = wm*32 + mi1*8 + ri;
  int nbrow = wn*NCOL + mi1*8 + ri;
  int maxor = (marow & 7);
  int nbxor = (nbrow & 7);

  for (int kt = 0; kt < ktiles; kt++){
    if (kt + 2 < ktiles) load((kt+2)%3, (kt+2)*64);
    CPA_COMMIT();
    CPA_WAIT2();
    __syncthreads();

    uint32_t ab = sbase + (kt%3)*SBYT;
    uint32_t aA = ab + marow*128;
    uint32_t aB = ab + ABYT + nbrow*128;

    #pragma unroll
    for (int kk=0; kk<4; kk++){
      uint32_t asw = (uint32_t)(((kk*2 + kg2) ^ maxor) << 4);
      uint32_t bsw = (uint32_t)(((kk*2 + kg2) ^ nbxor) << 4);
      unsigned af0[4], af1[4], bf[NBL][4];
      LDSM_X4(af0[0],af0[1],af0[2],af0[3], aA + asw);
      LDSM_X4(af1[0],af1[1],af1[2],af1[3], aA + asw + 16*128);
      #pragma unroll
      for (int jp=0; jp<NBL; jp++)
        LDSM_X4(bf[jp][0],bf[jp][1],bf[jp][2],bf[jp][3], aB + bsw + jp*16*128);
      #pragma unroll
      for (int jp=0; jp<NBL; jp++){
        MMA16(acc[0][2*jp  ], af0[0],af0[1],af0[2],af0[3], bf[jp][0], bf[jp][2]);
        MMA16(acc[0][2*jp+1], af0[0],af0[1],af0[2],af0[3], bf[jp][1], bf[jp][3]);
        MMA16(acc[1][2*jp  ], af1[0],af1[1],af1[2],af1[3], bf[jp][0], bf[jp][2]);
        MMA16(acc[1][2*jp+1], af1[0],af1[1],af1[2],af1[3], bf[jp][1], bf[jp][3]);
      }
    }
    __syncthreads();
  }

  int r = lane >> 2, c2 = (lane & 3)*2;
  #pragma unroll
  for (int im=0; im<2; im++)
    #pragma unroll
    for (int jn=0; jn<NFR; jn++){
      int mr = m0 + wm*32 + im*16 + r;
      int nc = n0 + wn*NCOL + jn*8 + c2;
      epih(p, Cf, Ch, mr,   nc,   acc[im][jn][0]);
      epih(p, Cf, Ch, mr,   nc+1, acc[im][jn][1]);
      epih(p, Cf, Ch, mr+8, nc,   acc[im][jn][2]);
      epih(p, Cf, Ch, mr+8, nc+1, acc[im][jn][3]);
    }
}

/* ---------------- fp16 converters (MLP=4) -------------------------------- */
#define WP_GRID  18816
#define WP_STRIDE ((long)WP_GRID*256)
__global__ void conv_wp16(const float* __restrict__ Wp){
  long i0 = (long)blockIdx.x*256 + threadIdx.x;
  float4 v[4];
  long idx[4];
  #pragma unroll
  for (int u=0; u<4; u++){
    long i = i0 + (long)u*WP_STRIDE;
    idx[u] = i;
    long row = i / (H3/4);
    long c4  = i % (H3/4);
    v[u] = (row < VOC) ? *(const float4*)(Wp + row*H3 + c4*4)
                       : make_float4(0.f,0.f,0.f,0.f);
  }
  __half2* dst = (__half2*)g_wp16;
  #pragma unroll
  for (int u=0; u<4; u++){
    dst[idx[u]*2]   = __floats2half2_rn(v[u].x, v[u].y);
    dst[idx[u]*2+1] = __floats2half2_rn(v[u].z, v[u].w);
  }
}

/* ---- merged head: mem16 + W416 + cat/cat16/h16, section-dispatched ------ */
#define MEM_GRID 1600
#define MEM_STRIDE ((long)MEM_GRID*256)
#define WTS_GRID 256
#define WTS_STRIDE (WTS_GRID*256)
#define CAT_GRID 1024
#define HEAD_GRID (MEM_GRID + WTS_GRID + CAT_GRID)
__global__ void conv_head(const float* __restrict__ mem,
                          const float* __restrict__ Wq, const float* __restrict__ Wk,
                          const float* __restrict__ Wv, const float* __restrict__ Wo,
                          const float* __restrict__ h, const float* __restrict__ y){
  int bx = blockIdx.x;
  int tid = threadIdx.x;
  if (bx < MEM_GRID){
    long i0 = (long)bx*256 + tid;
    float4 v[4];
    #pragma unroll
    for (int u=0; u<4; u++) v[u] = *(const float4*)(mem + (i0 + (long)u*MEM_STRIDE)*4);
    __half2* dst = (__half2*)g_mem16;
    #pragma unroll
    for (int u=0; u<4; u++){
      long i = i0 + (long)u*MEM_STRIDE;
      dst[i*2]   = __floats2half2_rn(v[u].x, v[u].y);
      dst[i*2+1] = __floats2half2_rn(v[u].z, v[u].w);
    }
    return;
  }
  bx -= MEM_GRID;
  if (bx < WTS_GRID){
    int i0 = bx*256 + tid;
    const int per = HID*HID/4;
    float4 v[4];
    #pragma unroll
    for (int u=0; u<4; u++){
      int i = i0 + u*WTS_STRIDE;
      int seg = i / per, off = i % per;
      const float* src = (seg==0)?Wq:(seg==1)?Wk:(seg==2)?Wv:Wo;
      v[u] = *(const float4*)(src + (long)off*4);
    }
    __half2* dst = (__half2*)g_W416;
    #pragma unroll
    for (int u=0; u<4; u++){
      int i = i0 + u*WTS_STRIDE;
      dst[i*2]   = __floats2half2_rn(v[u].x, v[u].y);
      dst[i*2+1] = __floats2half2_rn(v[u].z, v[u].w);
    }
    return;
  }
  bx -= WTS_GRID;
  {
    int i = bx*256 + tid;               /* < TB*(HID/4) = 262144 exactly     */
    int row = i / (HID/4);
    int c   = i % (HID/4);
    const float4 hv = ((const float4*)h)[i];
    const float4 yv = ((const float4*)y)[i];
    float4* cat4 = (float4*)g_cat;
    cat4[(long)row*(H3/4) + c]           = hv;
    cat4[(long)row*(H3/4) + (HID/4) + c] = yv;
    __half2* c16 = (__half2*)g_cat16;
    long b = (long)row*(H3/2);
    __half2 h01 = __floats2half2_rn(hv.x, hv.y);
    __half2 h23 = __floats2half2_rn(hv.z, hv.w);
    c16[b + c*2]               = h01;
    c16[b + c*2 + 1]           = h23;
    c16[b + (HID/2) + c*2]     = __floats2half2_rn(yv.x, yv.y);
    c16[b + (HID/2) + c*2 + 1] = __floats2half2_rn(yv.z, yv.w);
    __half2* h16 = (__half2*)g_h16;
    h16[i*2]   = h01;
    h16[i*2+1] = h23;
  }
}

/* == fp16 Wp GEMM: 128x128 CTA, 256 thr, 2 CTA/SM, fused softmax stats === */
#define WBM 128
#define WBN2 128
#define WABY (WBM*128)
#define WSBY (WABY + WBN2*128)
#define WSMEM (3*WSBY)

__device__ __forceinline__ void merge_ms(float& m, float& s, float m2, float s2){
  float M = fmaxf(m, m2);
  s = s*__expf(m-M) + s2*__expf(m2-M);
  m = M;
}

__global__ __launch_bounds__(256,2) void gemm_wp16(
    const __half* __restrict__ A, const __half* __restrict__ B,
    const float* __restrict__ bias, __half* __restrict__ l16,
    float* __restrict__ pm, float* __restrict__ ps)
{
  extern __shared__ float smf[];
  __shared__ float red_m[2][128], red_s[2][128];
  uint32_t sbase = (uint32_t)__cvta_generic_to_shared(smf);
  int tid = threadIdx.x;
  int lane = tid & 31, warp = tid >> 5;
  int wm = warp & 3, wn = warp >> 2;
  int m0 = blockIdx.x * WBM, n0 = blockIdx.y * WBN2;

  float acc[2][8][4];
  #pragma unroll
  for (int i=0;i<2;i++)
    #pragma unroll
    for (int j=0;j<8;j++){ acc[i][j][0]=0.f; acc[i][j][1]=0.f; acc[i][j][2]=0.f; acc[i][j][3]=0.f; }

  const int ktiles = H3/64;

  auto load = [&](int st, int k0){
    uint32_t ab = sbase + st*WSBY;
    uint32_t bb = ab + WABY;
    #pragma unroll
    for (int i=0;i<8;i++){
      int g = tid + i*256;
      int r = g >> 3, gc = g & 7;
      int kcol = k0 + gc*8;
      if (r < WBM){
        uint32_t soff = (uint32_t)(r*128 + ((gc ^ (r&7))<<4));
        cpa16u(ab + soff, A + (long)(m0 + r)*H3 + kcol, 16);
      } else {
        int rb = r - WBM;
        uint32_t soff = (uint32_t)(rb*128 + ((gc ^ (rb&7))<<4));
        cpa16u(bb + soff, B + (long)(n0 + rb)*H3 + kcol, 16);
      }
    }
  };

  load(0, 0); CPA_COMMIT();
  load(1, 64); CPA_COMMIT();

  int mi1 = (lane >> 3) & 1;
  int kg2 = lane >> 4;
  int ri  = lane & 7;
  int marow = wm*32 + mi1*8 + ri;
  int nbrow = wn*64 + mi1*8 + ri;
  int maxor = (marow & 7);
  int nbxor = (nbrow & 7);

  for (int kt = 0; kt < ktiles; kt++){
    if (kt + 2 < ktiles) load((kt+2)%3, (kt+2)*64);
    CPA_COMMIT();
    CPA_WAIT2();
    __syncthreads();

    uint32_t ab = sbase + (kt%3)*WSBY;
    uint32_t aA = ab + marow*128;
    uint32_t aB = ab + WABY + nbrow*128;

    #pragma unroll
    for (int kk=0; kk<4; kk++){
      uint32_t asw = (uint32_t)(((kk*2 + kg2) ^ maxor) << 4);
      uint32_t bsw = (uint32_t)(((kk*2 + kg2) ^ nbxor) << 4);
      unsigned af0[4], af1[4], bf[4][4];
      LDSM_X4(af0[0],af0[1],af0[2],af0[3], aA + asw);
      LDSM_X4(af1[0],af1[1],af1[2],af1[3], aA + asw + 16*128);
      #pragma unroll
      for (int jb=0; jb<4; jb++)
        LDSM_X4(bf[jb][0],bf[jb][1],bf[jb][2],bf[jb][3], aB + bsw + jb*16*128);
      #pragma unroll
      for (int jb=0; jb<4; jb++){
        MMA16(acc[0][2*jb  ], af0[0],af0[1],af0[2],af0[3], bf[jb][0], bf[jb][2]);
        MMA16(acc[0][2*jb+1], af0[0],af0[1],af0[2],af0[3], bf[jb][1], bf[jb][3]);
        MMA16(acc[1][2*jb  ], af1[0],af1[1],af1[2],af1[3], bf[jb][0], bf[jb][2]);
        MMA16(acc[1][2*jb+1], af1[0],af1[1],af1[2],af1[3], bf[jb][1], bf[jb][3]);
      }
    }
    __syncthreads();
  }

  int r2 = lane >> 2, c2 = (lane & 3)*2;
  #pragma unroll
  for (int im=0; im<2; im++){
    int mr = m0 + wm*32 + im*16 + r2;
    float m0v=-1e30f, m1v=-1e30f, s0v=0.f, s1v=0.f;
    #pragma unroll
    for (int nj=0; nj<8; nj++){
      int nc = n0 + wn*64 + nj*8 + c2;
      if (nc < VOC){
        float b0 = bias[nc], b1 = bias[nc+1];
        float v00 = acc[im][nj][0]+b0, v01 = acc[im][nj][1]+b1;
        float v10 = acc[im][nj][2]+b0, v11 = acc[im][nj][3]+b1;
        acc[im][nj][0]=v00; acc[im][nj][1]=v01;
        acc[im][nj][2]=v10; acc[im][nj][3]=v11;
        *(__half2*)(l16 + (long)mr*VPAD + nc)     = __floats2half2_rn(v00,v01);
        *(__half2*)(l16 + (long)(mr+8)*VPAD + nc) = __floats2half2_rn(v10,v11);
        m0v = fmaxf(m0v, fmaxf(v00,v01));
        m1v = fmaxf(m1v, fmaxf(v10,v11));
      }
    }
    #pragma unroll
    for (int nj=0; nj<8; nj++){
      int nc = n0 + wn*64 + nj*8 + c2;
      if (nc < VOC){
        s0v += __expf(acc[im][nj][0]-m0v) + __expf(acc[im][nj][1]-m0v);
        s1v += __expf(acc[im][nj][2]-m1v) + __expf(acc[im][nj][3]-m1v);
      }
    }
    #pragma unroll
    for (int off=1; off<4; off<<=1){
      float om0 = __shfl_xor_sync(0xFFFFFFFFu, m0v, off);
      float os0 = __shfl_xor_sync(0xFFFFFFFFu, s0v, off);
      merge_ms(m0v, s0v, om0, os0);
      float om1 = __shfl_xor_sync(0xFFFFFFFFu, m1v, off);
      float os1 = __shfl_xor_sync(0xFFFFFFFFu, s1v, off);
      merge_ms(m1v, s1v, om1, os1);
    }
    if ((lane & 3) == 0){
      int rl = wm*32 + im*16 + r2;
      red_m[wn][rl]   = m0v; red_s[wn][rl]   = s0v;
      red_m[wn][rl+8] = m1v; red_s[wn][rl+8] = s1v;
    }
  }
  __syncthreads();
  if (tid < 128){
    float M = red_m[0][tid], S = red_s[0][tid];
    merge_ms(M, S, red_m[1][tid], red_s[1][tid]);
    pm[(long)blockIdx.y*TB + m0 + tid] = M;
    ps[(long)blockIdx.y*TB + m0 + tid] = S;
  }
}

/* ------ softmax over S; writes w16 (B,T,S) + dists fp32 (T,B,S) ---------- */
__global__ void softmax_s(float* __restrict__ dists, const unsigned char* __restrict__ mask){
  int bt = blockIdx.x;
  int b = bt / T_LEN, t = bt % T_LEN;
  float* row = g_w + (long)bt*SEQ;
  const unsigned char* mrow = mask + (long)b*SEQ;
  int tid = threadIdx.x;
  __shared__ float red[128];
  float mx = -1e30f;
  for (int s=tid; s<SEQ; s+=128){
    float x = mrow[s] ? -1e9f : row[s];
    mx = fmaxf(mx, x);
  }
  red[tid]=mx; __syncthreads();
  for (int off=64; off>0; off>>=1){ if (tid<off) red[tid]=fmaxf(red[tid],red[tid+off]); __syncthreads(); }
  mx = red[0]; __syncthreads();
  float sum=0.f;
  for (int s=tid; s<SEQ; s+=128){
    float x = mrow[s] ? -1e9f : row[s];
    sum += __expf(x-mx);
  }
  red[tid]=sum; __syncthreads();
  for (int off=64; off>0; off>>=1){ if (tid<off) red[tid]+=red[tid+off]; __syncthreads(); }
  float inv = 1.f/red[0];
  for (int s=tid; s<SEQ; s+=128){
    float x = mrow[s] ? -1e9f : row[s];
    float wv = __expf(x-mx)*inv;
    g_w16[(long)bt*SEQ + s] = __float2half_rn(wv);
    dists[((long)t*BATCH + b)*SEQ + s] = wv;
  }
}

/* -------- gate + stats merge + ext zero (per row) ------------------------ */
__global__ void gate_stats(float* __restrict__ out,
                           const float* __restrict__ vv, const float* __restrict__ bvv){
  int rid = blockIdx.x;
  float* row = out + (long)rid*VE;
  int tid = threadIdx.x;                /* 512 */
  __shared__ float rm[512], rs[512];
  __shared__ float gsh;

  const float* cr = g_cat + (long)rid*H3;
  float s0 = 0.f;
  for (int j=tid; j<H3; j+=512) s0 += cr[j]*vv[j];
  rm[tid]=s0; __syncthreads();
  for (int off=256; off>0; off>>=1){ if (tid<off) rm[tid]+=rm[tid+off]; __syncthreads(); }
  if (tid==0) gsh = 1.f/(1.f+__expf(-(rm[0]+bvv[0])));
  __syncthreads();
  float g = gsh;

  float m = -1e30f, s = 0.f;
  if (tid < NSTRIPE){
    m = g_pm[(long)tid*TB + rid];
    s = g_ps[(long)tid*TB + rid];
  }
  rm[tid]=m; rs[tid]=s; __syncthreads();
  for (int off=256; off>0; off>>=1){
    if (tid<off){
      float m2=rm[tid+off], s2=rs[tid+off];
      float M=fmaxf(rm[tid],m2);
      rs[tid]=rs[tid]*__expf(rm[tid]-M)+s2*__expf(m2-M);
      rm[tid]=M;
    }
    __syncthreads();
  }
  if (tid == 0){
    g_M[rid]      = rm[0];
    g_gscale[rid] = g/rs[0];
    g_omg[rid]    = 1.f - g;
  }
  /* zero the ext region */
  for (int j=VOC+tid; j<VE; j+=512) row[j] = 0.f;
}

/* -------- probs: streaming fp16 logit -> fp32 prob ----------------------- */
#define PROB_BX 98                       /* 98*512 = 50176 cols >= VOC       */
__global__ void probs_k(float* __restrict__ out){
  int rid = blockIdx.y;
  int col = blockIdx.x*512 + threadIdx.x*2;
  if (col >= VOC) return;
  float M = g_M[rid];
  float gs = g_gscale[rid];
  __half2 lv = *(const __half2*)(g_l16 + (long)rid*VPAD + col);
  float2 lf = __half22float2(lv);
  float2 o;
  o.x = __expf(lf.x - M)*gs;
  o.y = __expf(lf.y - M)*gs;
  *(float2*)(out + (long)rid*VE + col) = o;
}

/* -------- scatter: out[rid, xids[s,b]] += (1-g)*dists -------------------- */
__global__ void scatter_k(float* __restrict__ out, const float* __restrict__ dists,
                          const int* __restrict__ xids){
  long i = (long)blockIdx.x*256 + threadIdx.x;
  if (i >= (long)TB*SEQ) return;
  int rid = (int)(i / SEQ);             /* t*B + b */
  int s   = (int)(i % SEQ);
  int b = rid % BATCH, t = rid / BATCH;
  float wv = dists[((long)t*BATCH + b)*SEQ + s];
  int col = xids[(long)s*BATCH + b];
  atomicAdd(out + (long)rid*VE + col, g_omg[rid]*wv);
}

/* ------------------------------- host ----------------------------------- */
template<int BMT, int DUAL>
static inline void launch_h16(const GH& p, int batches, cudaStream_t st){
  constexpr int SM = 3*((BMT+BN)*128);
  static bool done = false;
  if (!done){
    cudaFuncSetAttribute(gemm_h16<BMT,DUAL>,
                         cudaFuncAttributeMaxDynamicSharedMemorySize, SM);
    done = true;
  }
  dim3 grid((p.M+BMT-1)/BMT, (p.N+BN-1)/BN, batches);
  gemm_h16<BMT,DUAL><<<grid, 256, SM, st>>>(p);
}

extern "C" void kernel_launch(void* const* d_in, const int* in_sizes, int n_in,
                              void* d_out, int out_size){
  const float* h    = (const float*)d_in[0];
  const float* yemb = (const float*)d_in[1];
  const float* mem  = (const float*)d_in[2];
  const unsigned char* mask = (const unsigned char*)d_in[3];
  const int* xids   = (const int*)d_in[4];
  int wb = 5;
  if (n_in >= 18 && in_sizes[5] == 1) wb = 6;
  const float* Wq = (const float*)d_in[wb+0];
  const float* bq = (const float*)d_in[wb+1];
  const float* Wk = (const float*)d_in[wb+2];
  const float* bk = (const float*)d_in[wb+3];
  const float* Wv = (const float*)d_in[wb+4];
  const float* bva= (const float*)d_in[wb+5];
  const float* Wo = (const float*)d_in[wb+6];
  const float* bo = (const float*)d_in[wb+7];
  const float* Wp = (const float*)d_in[wb+8];
  const float* bp = (const float*)d_in[wb+9];
  const float* vv = (const float*)d_in[wb+10];
  const float* bv = (const float*)d_in[wb+11];

  float* out   = (float*)d_out;
  float* dists = out + (long)TB*VE;

  cudaFuncSetAttribute(gemm_wp16, cudaFuncAttributeMaxDynamicSharedMemorySize, WSMEM);

  static cudaStream_t s1 = 0;
  static cudaEvent_t evF = 0, evJ = 0, evF2 = 0, evJ2 = 0;
  if (!s1){
    cudaStreamCreateWithFlags(&s1, cudaStreamNonBlocking);
    cudaEventCreateWithFlags(&evF,  cudaEventDisableTiming);
    cudaEventCreateWithFlags(&evJ,  cudaEventDisableTiming);
    cudaEventCreateWithFlags(&evF2, cudaEventDisableTiming);
    cudaEventCreateWithFlags(&evJ2, cudaEventDisableTiming);
  }

  void *wbuf, *catp, *cat16p, *wp16p, *h16p, *mem16p, *w4p;
  void *q16p, *k16p, *valT16p, *w16p, *atts16p, *l16p, *pmp, *psp;
  cudaGetSymbolAddress(&wbuf, g_w);
  cudaGetSymbolAddress(&catp, g_cat);
  cudaGetSymbolAddress(&cat16p, g_cat16);
  cudaGetSymbolAddress(&wp16p, g_wp16);
  cudaGetSymbolAddress(&h16p, g_h16);
  cudaGetSymbolAddress(&mem16p, g_mem16);
  cudaGetSymbolAddress(&w4p, g_W416);
  cudaGetSymbolAddress(&q16p, g_q16);
  cudaGetSymbolAddress(&k16p, g_k16);
  cudaGetSymbolAddress(&valT16p, g_valT16);
  cudaGetSymbolAddress(&w16p, g_w16);
  cudaGetSymbolAddress(&atts16p, g_atts16);
  cudaGetSymbolAddress(&l16p, g_l16);
  cudaGetSymbolAddress(&pmp, g_pm);
  cudaGetSymbolAddress(&psp, g_ps);

  const __half* W16 = (const __half*)w4p;
  const __half* Wq16 = W16;
  const __half* Wk16 = W16 + (long)HID*HID;
  const __half* Wv16 = W16 + 2L*HID*HID;
  const __half* Wo16 = W16 + 3L*HID*HID;

  float scale = 1.0f/sqrtf((float)HID);

  /* fork: conv_wp16 on s1 overlaps the attention chain */
  cudaEventRecord(evF, 0);
  cudaStreamWaitEvent(s1, evF, 0);
  conv_wp16<<<WP_GRID, 256, 0, s1>>>(Wp);
  cudaEventRecord(evJ, s1);

  /* merged head converters */
  conv_head<<<HEAD_GRID, 256>>>(mem, Wq, Wk, Wv, Wo, h, yemb);

  GH p;

  /* fork q on s1 (needs h16 + Wq16 from conv_head) */
  cudaEventRecord(evF2, 0);
  cudaStreamWaitEvent(s1, evF2, 0);
  p = GH{};
  p.A = (const __half*)h16p; p.B = Wq16; p.Ch = (__half*)q16p;
  p.lda = HID; p.ldb = HID; p.ldc = HID;
  p.M = TB; p.N = HID; p.K = HID;
  p.bias = bq; p.alpha = scale;
  p.mode = 1; p.D1 = BATCH; p.D2 = T_LEN;
  launch_h16<64,0>(p, 1, s1);
  cudaEventRecord(evJ2, s1);

  /* fused k & val projection */
  p = GH{};
  p.A = (const __half*)mem16p; p.B = Wk16; p.B2 = Wv16;
  p.Ch = (__half*)k16p; p.Ch2 = (__half*)valT16p;
  p.lda = HID; p.ldb = HID;
  p.M = SEQ*BATCH; p.N = 2*HID; p.K = HID;
  p.bias = bk; p.bias2 = bva;
  p.mode = 3;
  launch_h16<128,1>(p, 1, 0);

  cudaStreamWaitEvent(0, evJ2, 0);

  /* scores */
  p = GH{};
  p.A = (const __half*)q16p; p.B = (const __half*)k16p; p.Cf = (float*)wbuf;
  p.lda = HID; p.ldb = HID; p.ldc = SEQ;
  p.sA = (long)T_LEN*HID; p.sB = (long)SEQ*HID; p.sC = (long)T_LEN*SEQ;
  p.M = T_LEN; p.N = SEQ; p.K = HID;
  p.mode = 0;
  launch_h16<64,0>(p, BATCH, 0);

  softmax_s<<<BATCH*T_LEN, 128>>>(dists, mask);

  /* atts */
  p = GH{};
  p.A = (const __half*)w16p; p.B = (const __half*)valT16p; p.Ch = (__half*)atts16p;
  p.lda = SEQ; p.ldb = SEQ; p.ldc = HID;
  p.sA = (long)T_LEN*SEQ; p.sB = (long)HID*SEQ; p.sC = (long)T_LEN*HID;
  p.M = T_LEN; p.N = HID; p.K = SEQ;
  p.mode = 4;
  launch_h16<64,0>(p, BATCH, 0);

  /* wo -> cat + cat16 */
  p = GH{};
  p.A = (const __half*)atts16p; p.B = Wo16;
  p.Cf = (float*)catp; p.Ch = (__half*)cat16p;
  p.lda = HID; p.ldb = HID; p.ldc = H3;
  p.M = TB; p.N = HID; p.K = HID;
  p.bias = bo;
  p.mode = 5; p.D1 = T_LEN; p.D2 = BATCH; p.col_off = 1024;
  launch_h16<64,0>(p, 1, 0);

  cudaStreamWaitEvent(0, evJ, 0);

  /* logits + per-stripe stats */
  gemm_wp16<<<dim3(TB/WBM, VPAD/WBN2), 256, WSMEM>>>(
      (const __half*)cat16p, (const __half*)wp16p, bp,
      (__half*)l16p, (float*)pmp, (float*)psp);

  /* tail: gate/stats -> streaming probs -> scatter */
  gate_stats<<<TB, 512>>>(out, vv, bv);
  probs_k<<<dim3(PROB_BX, TB), 256>>>(out);
  scatter_k<<<(int)(((long)TB*SEQ + 255)/256), 256>>>(out, dists, xids);

  (void)out_size; (void)n_in;
}

// round 15
// speedup vs baseline: 1.2839x; 1.0675x over previous
#include <cuda_runtime.h>
#include <cuda_fp16.h>
#include <math.h>
#include <stdint.h>

#define T_LEN 64
#define BATCH 32
#define SEQ   400
#define HID   512
#define VOC   50000
#define EXTD  400
#define VE    (VOC+EXTD)
#define TB    (T_LEN*BATCH)     /* 2048 */
#define H3    (3*HID)           /* 1536 */
#define VPAD  50176             /* VOC padded to 256 */
#define NSTRIPE (VPAD/128)      /* 392 */

/* ---------------- scratch (device globals: allocation-free) -------------- */
__device__ float  g_cat [TB*H3];              /* (T*B,3H) fp32 (gate)        */
__device__ float  g_w   [BATCH*T_LEN*SEQ];    /* scores fp32 (B,T,S)         */
__device__ __half g_cat16[TB*H3];
__device__ __half g_wp16 [(long)VPAD*H3];
__device__ __half g_h16  [TB*HID];
__device__ __half g_mem16[SEQ*BATCH*HID];
__device__ __half g_W416 [4*HID*HID];         /* Wq,Wk,Wv,Wo                 */
__device__ __half g_q16  [BATCH*T_LEN*HID];   /* (B,T,H)                     */
__device__ __half g_kv   [(long)SEQ*BATCH*1024]; /* (S,B,[k(512)|v(512)])    */
__device__ __half g_valT16[BATCH*HID*SEQ];    /* (B,H,S)                     */
__device__ __half g_w16  [BATCH*T_LEN*SEQ];   /* attn weights fp16           */
__device__ __half g_atts16[TB*HID];           /* (B,T,H) rows b*T+t          */
__device__ __half g_l16  [(long)TB*VPAD];     /* fp16 logits                 */
__device__ float  g_pm   [NSTRIPE*TB];        /* per-stripe softmax max      */
__device__ float  g_ps   [NSTRIPE*TB];        /* per-stripe softmax sum      */
__device__ float  g_gscale[TB];               /* g / sumexp                  */
__device__ float  g_M    [TB];                /* row max                     */
__device__ float  g_omg  [TB];                /* 1 - g                       */

#define BN 128

__device__ __forceinline__ void cpa16u(unsigned dst, const void* src, int bytes){
  asm volatile("cp.async.cg.shared.global [%0], [%1], 16, %2;\n"
               :: "r"(dst), "l"(src), "r"(bytes));
}
#define CPA_COMMIT() asm volatile("cp.async.commit_group;\n")
#define CPA_WAIT2()  asm volatile("cp.async.wait_group 2;\n")

#define LDSM_X4(r0,r1,r2,r3,addr) \
  asm volatile("ldmatrix.sync.aligned.m8n8.x4.shared.b16 {%0,%1,%2,%3}, [%4];" \
               : "=r"(r0), "=r"(r1), "=r"(r2), "=r"(r3) : "r"(addr))

#define MMA16(d, a0,a1,a2,a3, b0,b1) \
  asm volatile("mma.sync.aligned.m16n8k16.row.col.f32.f16.f16.f32 " \
               "{%0,%1,%2,%3}, {%4,%5,%6,%7}, {%8,%9}, {%0,%1,%2,%3};\n" \
               : "+f"((d)[0]), "+f"((d)[1]), "+f"((d)[2]), "+f"((d)[3]) \
               : "r"(a0), "r"(a1), "r"(a2), "r"(a3), "r"(b0), "r"(b1))

/* ---------------- generic fp16 MMA GEMM --------------------------------- */
struct GH {
  const __half* A; const __half* B; const __half* B2;
  float* Cf; __half* Ch; __half* Ch2;
  long lda, ldb, ldc;
  long sA, sB, sC;
  int  M, N, K;
  const float* bias; const float* bias2;
  float alpha;
  int  mode, D1, D2;
  long col_off;
};

__device__ __forceinline__ void epih(const GH& p, float* Cf, __half* Ch,
                                     int m, int n, float v){
  if (m >= p.M || n >= p.N) return;
  if (p.mode == 0){                           /* scores fp32 flat            */
    Cf[(long)m*p.ldc + n] = v; return;
  }
  if (p.mode == 1){                           /* q fp16 permuted + bias*alpha*/
    long idx = ((long)(m % p.D1)*p.D2 + m/p.D1)*p.ldc + n;
    Ch[idx] = __float2half_rn(p.alpha*(v + p.bias[n])); return;
  }
  if (p.mode == 4){                           /* atts fp16 flat              */
    Ch[(long)m*p.ldc + n] = __float2half_rn(v); return;
  }
  /* mode 5: wo -> cat fp32 + cat16, permuted, col_off                       */
  long idx = ((long)(m % p.D1)*p.D2 + m/p.D1)*p.ldc + p.col_off + n;
  float o = v + p.bias[n];
  Cf[idx] = o;
  Ch[idx] = __float2half_rn(o);
}

template<int BMT, int DUAL>
__global__ __launch_bounds__(256,2) void gemm_h16(GH p){
  constexpr int WM   = BMT/32;
  constexpr int NCOL = BN/(8/WM);
  constexpr int NFR  = NCOL/8;
  constexpr int NBL  = NCOL/16;
  constexpr int ABYT = BMT*128;
  constexpr int SBYT = ABYT + BN*128;
  constexpr int GT   = (BMT+BN)*8;

  extern __shared__ float smf[];
  uint32_t sbase = (uint32_t)__cvta_generic_to_shared(smf);
  const __half* A  = p.A + (long)blockIdx.z * p.sA;
  const __half* Bg = p.B + (long)blockIdx.z * p.sB;
  float*  Cf = p.Cf ? p.Cf + (long)blockIdx.z * p.sC : (float*)0;
  __half* Ch = p.Ch ? p.Ch + (long)blockIdx.z * p.sC : (__half*)0;

  int tid = threadIdx.x;
  int lane = tid & 31, warp = tid >> 5;
  int wm = warp % WM, wn = warp / WM;
  int m0 = blockIdx.x * BMT, n0 = blockIdx.y * BN;

  float acc[2][NFR][4];
  #pragma unroll
  for (int i=0;i<2;i++)
    #pragma unroll
    for (int j=0;j<NFR;j++){ acc[i][j][0]=0.f; acc[i][j][1]=0.f; acc[i][j][2]=0.f; acc[i][j][3]=0.f; }

  int ktiles = (p.K + 63)/64;

  auto load = [&](int st, int k0){
    uint32_t ab = sbase + st*SBYT;
    uint32_t bb = ab + ABYT;
    #pragma unroll
    for (int i=0;i<GT/256;i++){
      int g = tid + i*256;
      int r = g >> 3, gc = g & 7;
      int kcol = k0 + gc*8;
      int kb = (kcol < p.K) ? 16 : 0;
      if (r < BMT){
        uint32_t soff = (uint32_t)(r*128 + ((gc ^ (r&7))<<4));
        int gm = m0 + r;
        cpa16u(ab + soff, A + (long)gm*p.lda + kcol, (gm < p.M) ? kb : 0);
      } else {
        int rb = r - BMT;
        uint32_t soff = (uint32_t)(rb*128 + ((gc ^ (rb&7))<<4));
        int gn = n0 + rb;
        const __half* src;
        if (DUAL && gn >= HID) src = p.B2 + (long)(gn-HID)*p.ldb + kcol;
        else                   src = Bg  + (long)gn*p.ldb + kcol;
        cpa16u(bb + soff, src, (gn < p.N) ? kb : 0);
      }
    }
  };

  load(0, 0); CPA_COMMIT();
  load(1, 64); CPA_COMMIT();

  int mi1 = (lane >> 3) & 1;
  int kg2 = lane >> 4;
  int ri  = lane & 7;
  int marow = wm*32 + mi1*8 + ri;
  int nbrow = wn*NCOL + mi1*8 + ri;
  int maxor = (marow & 7);
  int nbxor = (nbrow & 7);

  for (int kt = 0; kt < ktiles; kt++){
    if (kt + 2 < ktiles) load((kt+2)%3, (kt+2)*64);
    CPA_COMMIT();
    CPA_WAIT2();
    __syncthreads();

    uint32_t ab = sbase + (kt%3)*SBYT;
    uint32_t aA = ab + marow*128;
    uint32_t aB = ab + ABYT + nbrow*128;

    #pragma unroll
    for (int kk=0; kk<4; kk++){
      uint32_t asw = (uint32_t)(((kk*2 + kg2) ^ maxor) << 4);
      uint32_t bsw = (uint32_t)(((kk*2 + kg2) ^ nbxor) << 4);
      unsigned af0[4], af1[4], bf[NBL][4];
      LDSM_X4(af0[0],af0[1],af0[2],af0[3], aA + asw);
      LDSM_X4(af1[0],af1[1],af1[2],af1[3], aA + asw + 16*128);
      #pragma unroll
      for (int jp=0; jp<NBL; jp++)
        LDSM_X4(bf[jp][0],bf[jp][1],bf[jp][2],bf[jp][3], aB + bsw + jp*16*128);
      #pragma unroll
      for (int jp=0; jp<NBL; jp++){
        MMA16(acc[0][2*jp  ], af0[0],af0[1],af0[2],af0[3], bf[jp][0], bf[jp][2]);
        MMA16(acc[0][2*jp+1], af0[0],af0[1],af0[2],af0[3], bf[jp][1], bf[jp][3]);
        MMA16(acc[1][2*jp  ], af1[0],af1[1],af1[2],af1[3], bf[jp][0], bf[jp][2]);
        MMA16(acc[1][2*jp+1], af1[0],af1[1],af1[2],af1[3], bf[jp][1], bf[jp][3]);
      }
    }
    __syncthreads();
  }

  if (DUAL){
    /* staged coalesced epilogue: smem tile + bias, then uint4 rows to kv    */
    constexpr int TP = 136;                 /* padded row, halves            */
    __half* tile = (__half*)smf;            /* 128 x 136 halves = 34816 B    */
    const float* bptr = (n0 < HID) ? p.bias : p.bias2;
    int nb0 = (n0 < HID) ? n0 : n0 - HID;
    int r = lane >> 2, c2v = (lane & 3)*2;
    #pragma unroll
    for (int im=0; im<2; im++)
      #pragma unroll
      for (int jn=0; jn<NFR; jn++){
        int ml = wm*32 + im*16 + r;
        int nl = wn*NCOL + jn*8 + c2v;
        float b0 = bptr[nb0 + nl], b1 = bptr[nb0 + nl + 1];
        tile[ ml   *TP + nl    ] = __float2half_rn(acc[im][jn][0] + b0);
        tile[ ml   *TP + nl + 1] = __float2half_rn(acc[im][jn][1] + b1);
        tile[(ml+8)*TP + nl    ] = __float2half_rn(acc[im][jn][2] + b0);
        tile[(ml+8)*TP + nl + 1] = __float2half_rn(acc[im][jn][3] + b1);
      }
    __syncthreads();
    #pragma unroll
    for (int i2=0; i2<8; i2++){
      int i = tid + i2*256;                 /* 2048 = 128 rows x 16 chunks   */
      int rr = i >> 4, cc = (i & 15)*8;
      uint4 v = *(uint4*)&tile[rr*TP + cc];
      *(uint4*)(p.Ch + (long)(m0 + rr)*1024 + n0 + cc) = v;
    }
    return;
  }

  int r = lane >> 2, c2 = (lane & 3)*2;
  #pragma unroll
  for (int im=0; im<2; im++)
    #pragma unroll
    for (int jn=0; jn<NFR; jn++){
      int mr = m0 + wm*32 + im*16 + r;
      int nc = n0 + wn*NCOL + jn*8 + c2;
      epih(p, Cf, Ch, mr,   nc,   acc[im][jn][0]);
      epih(p, Cf, Ch, mr,   nc+1, acc[im][jn][1]);
      epih(p, Cf, Ch, mr+8, nc,   acc[im][jn][2]);
      epih(p, Cf, Ch, mr+8, nc+1, acc[im][jn][3]);
    }
}

/* ---- transpose: kv val-half (S,B,512) -> valT (B,H,S) ------------------- */
__global__ void transpose_v(){
  __shared__ __half tile[32][33];
  int b  = blockIdx.z;
  int h0 = blockIdx.y * 32;
  int s0 = blockIdx.x * 32;
  int x = threadIdx.x, y = threadIdx.y;     /* 32 x 8 */
  #pragma unroll
  for (int k2=0;k2<4;k2++){
    int s = s0 + y + k2*8;
    if (s < SEQ)
      tile[y+k2*8][x] = g_kv[((long)s*BATCH + b)*1024 + 512 + h0 + x];
  }
  __syncthreads();
  int s = s0 + x;
  if (s < SEQ){
    #pragma unroll
    for (int k2=0;k2<4;k2++){
      int hh = h0 + y + k2*8;
      g_valT16[((long)b*HID + hh)*SEQ + s] = tile[x][y+k2*8];
    }
  }
}

/* ---------------- fp16 converters (MLP=4) -------------------------------- */
#define WP_GRID  18816
#define WP_STRIDE ((long)WP_GRID*256)
__global__ void conv_wp16(const float* __restrict__ Wp){
  long i0 = (long)blockIdx.x*256 + threadIdx.x;
  float4 v[4];
  long idx[4];
  #pragma unroll
  for (int u=0; u<4; u++){
    long i = i0 + (long)u*WP_STRIDE;
    idx[u] = i;
    long row = i / (H3/4);
    long c4  = i % (H3/4);
    v[u] = (row < VOC) ? *(const float4*)(Wp + row*H3 + c4*4)
                       : make_float4(0.f,0.f,0.f,0.f);
  }
  __half2* dst = (__half2*)g_wp16;
  #pragma unroll
  for (int u=0; u<4; u++){
    dst[idx[u]*2]   = __floats2half2_rn(v[u].x, v[u].y);
    dst[idx[u]*2+1] = __floats2half2_rn(v[u].z, v[u].w);
  }
}

/* ---- merged head: mem16 + W416 + cat/cat16/h16, section-dispatched ------ */
#define MEM_GRID 1600
#define MEM_STRIDE ((long)MEM_GRID*256)
#define WTS_GRID 256
#define WTS_STRIDE (WTS_GRID*256)
#define CAT_GRID 1024
#define HEAD_GRID (MEM_GRID + WTS_GRID + CAT_GRID)
__global__ void conv_head(const float* __restrict__ mem,
                          const float* __restrict__ Wq, const float* __restrict__ Wk,
                          const float* __restrict__ Wv, const float* __restrict__ Wo,
                          const float* __restrict__ h, const float* __restrict__ y){
  int bx = blockIdx.x;
  int tid = threadIdx.x;
  if (bx < MEM_GRID){
    long i0 = (long)bx*256 + tid;
    float4 v[4];
    #pragma unroll
    for (int u=0; u<4; u++) v[u] = *(const float4*)(mem + (i0 + (long)u*MEM_STRIDE)*4);
    __half2* dst = (__half2*)g_mem16;
    #pragma unroll
    for (int u=0; u<4; u++){
      long i = i0 + (long)u*MEM_STRIDE;
      dst[i*2]   = __floats2half2_rn(v[u].x, v[u].y);
      dst[i*2+1] = __floats2half2_rn(v[u].z, v[u].w);
    }
    return;
  }
  bx -= MEM_GRID;
  if (bx < WTS_GRID){
    int i0 = bx*256 + tid;
    const int per = HID*HID/4;
    float4 v[4];
    #pragma unroll
    for (int u=0; u<4; u++){
      int i = i0 + u*WTS_STRIDE;
      int seg = i / per, off = i % per;
      const float* src = (seg==0)?Wq:(seg==1)?Wk:(seg==2)?Wv:Wo;
      v[u] = *(const float4*)(src + (long)off*4);
    }
    __half2* dst = (__half2*)g_W416;
    #pragma unroll
    for (int u=0; u<4; u++){
      int i = i0 + u*WTS_STRIDE;
      dst[i*2]   = __floats2half2_rn(v[u].x, v[u].y);
      dst[i*2+1] = __floats2half2_rn(v[u].z, v[u].w);
    }
    return;
  }
  bx -= WTS_GRID;
  {
    int i = bx*256 + tid;
    int row = i / (HID/4);
    int c   = i % (HID/4);
    const float4 hv = ((const float4*)h)[i];
    const float4 yv = ((const float4*)y)[i];
    float4* cat4 = (float4*)g_cat;
    cat4[(long)row*(H3/4) + c]           = hv;
    cat4[(long)row*(H3/4) + (HID/4) + c] = yv;
    __half2* c16 = (__half2*)g_cat16;
    long b = (long)row*(H3/2);
    __half2 h01 = __floats2half2_rn(hv.x, hv.y);
    __half2 h23 = __floats2half2_rn(hv.z, hv.w);
    c16[b + c*2]               = h01;
    c16[b + c*2 + 1]           = h23;
    c16[b + (HID/2) + c*2]     = __floats2half2_rn(yv.x, yv.y);
    c16[b + (HID/2) + c*2 + 1] = __floats2half2_rn(yv.z, yv.w);
    __half2* h16 = (__half2*)g_h16;
    h16[i*2]   = h01;
    h16[i*2+1] = h23;
  }
}

/* == fp16 Wp GEMM: 128x128 CTA, 256 thr, 2 CTA/SM, fused softmax stats === */
#define WBM 128
#define WBN2 128
#define WABY (WBM*128)
#define WSBY (WABY + WBN2*128)
#define WSMEM (3*WSBY)

__device__ __forceinline__ void merge_ms(float& m, float& s, float m2, float s2){
  float M = fmaxf(m, m2);
  s = s*__expf(m-M) + s2*__expf(m2-M);
  m = M;
}

__global__ __launch_bounds__(256,2) void gemm_wp16(
    const __half* __restrict__ A, const __half* __restrict__ B,
    const float* __restrict__ bias, __half* __restrict__ l16,
    float* __restrict__ pm, float* __restrict__ ps)
{
  extern __shared__ float smf[];
  __shared__ float red_m[2][128], red_s[2][128];
  uint32_t sbase = (uint32_t)__cvta_generic_to_shared(smf);
  int tid = threadIdx.x;
  int lane = tid & 31, warp = tid >> 5;
  int wm = warp & 3, wn = warp >> 2;
  int m0 = blockIdx.x * WBM, n0 = blockIdx.y * WBN2;

  float acc[2][8][4];
  #pragma unroll
  for (int i=0;i<2;i++)
    #pragma unroll
    for (int j=0;j<8;j++){ acc[i][j][0]=0.f; acc[i][j][1]=0.f; acc[i][j][2]=0.f; acc[i][j][3]=0.f; }

  const int ktiles = H3/64;

  auto load = [&](int st, int k0){
    uint32_t ab = sbase + st*WSBY;
    uint32_t bb = ab + WABY;
    #pragma unroll
    for (int i=0;i<8;i++){
      int g = tid + i*256;
      int r = g >> 3, gc = g & 7;
      int kcol = k0 + gc*8;
      if (r < WBM){
        uint32_t soff = (uint32_t)(r*128 + ((gc ^ (r&7))<<4));
        cpa16u(ab + soff, A + (long)(m0 + r)*H3 + kcol, 16);
      } else {
        int rb = r - WBM;
        uint32_t soff = (uint32_t)(rb*128 + ((gc ^ (rb&7))<<4));
        cpa16u(bb + soff, B + (long)(n0 + rb)*H3 + kcol, 16);
      }
    }
  };

  load(0, 0); CPA_COMMIT();
  load(1, 64); CPA_COMMIT();

  int mi1 = (lane >> 3) & 1;
  int kg2 = lane >> 4;
  int ri  = lane & 7;
  int marow = wm*32 + mi1*8 + ri;
  int nbrow = wn*64 + mi1*8 + ri;
  int maxor = (marow & 7);
  int nbxor = (nbrow & 7);

  for (int kt = 0; kt < ktiles; kt++){
    if (kt + 2 < ktiles) load((kt+2)%3, (kt+2)*64);
    CPA_COMMIT();
    CPA_WAIT2();
    __syncthreads();

    uint32_t ab = sbase + (kt%3)*WSBY;
    uint32_t aA = ab + marow*128;
    uint32_t aB = ab + WABY + nbrow*128;

    #pragma unroll
    for (int kk=0; kk<4; kk++){
      uint32_t asw = (uint32_t)(((kk*2 + kg2) ^ maxor) << 4);
      uint32_t bsw = (uint32_t)(((kk*2 + kg2) ^ nbxor) << 4);
      unsigned af0[4], af1[4], bf[4][4];
      LDSM_X4(af0[0],af0[1],af0[2],af0[3], aA + asw);
      LDSM_X4(af1[0],af1[1],af1[2],af1[3], aA + asw + 16*128);
      #pragma unroll
      for (int jb=0; jb<4; jb++)
        LDSM_X4(bf[jb][0],bf[jb][1],bf[jb][2],bf[jb][3], aB + bsw + jb*16*128);
      #pragma unroll
      for (int jb=0; jb<4; jb++){
        MMA16(acc[0][2*jb  ], af0[0],af0[1],af0[2],af0[3], bf[jb][0], bf[jb][2]);
        MMA16(acc[0][2*jb+1], af0[0],af0[1],af0[2],af0[3], bf[jb][1], bf[jb][3]);
        MMA16(acc[1][2*jb  ], af1[0],af1[1],af1[2],af1[3], bf[jb][0], bf[jb][2]);
        MMA16(acc[1][2*jb+1], af1[0],af1[1],af1[2],af1[3], bf[jb][1], bf[jb][3]);
      }
    }
    __syncthreads();
  }

  int r2 = lane >> 2, c2 = (lane & 3)*2;
  #pragma unroll
  for (int im=0; im<2; im++){
    int mr = m0 + wm*32 + im*16 + r2;
    float m0v=-1e30f, m1v=-1e30f, s0v=0.f, s1v=0.f;
    #pragma unroll
    for (int nj=0; nj<8; nj++){
      int nc = n0 + wn*64 + nj*8 + c2;
      if (nc < VOC){
        float b0 = bias[nc], b1 = bias[nc+1];
        float v00 = acc[im][nj][0]+b0, v01 = acc[im][nj][1]+b1;
        float v10 = acc[im][nj][2]+b0, v11 = acc[im][nj][3]+b1;
        acc[im][nj][0]=v00; acc[im][nj][1]=v01;
        acc[im][nj][2]=v10; acc[im][nj][3]=v11;
        *(__half2*)(l16 + (long)mr*VPAD + nc)     = __floats2half2_rn(v00,v01);
        *(__half2*)(l16 + (long)(mr+8)*VPAD + nc) = __floats2half2_rn(v10,v11);
        m0v = fmaxf(m0v, fmaxf(v00,v01));
        m1v = fmaxf(m1v, fmaxf(v10,v11));
      }
    }
    #pragma unroll
    for (int nj=0; nj<8; nj++){
      int nc = n0 + wn*64 + nj*8 + c2;
      if (nc < VOC){
        s0v += __expf(acc[im][nj][0]-m0v) + __expf(acc[im][nj][1]-m0v);
        s1v += __expf(acc[im][nj][2]-m1v) + __expf(acc[im][nj][3]-m1v);
      }
    }
    #pragma unroll
    for (int off=1; off<4; off<<=1){
      float om0 = __shfl_xor_sync(0xFFFFFFFFu, m0v, off);
      float os0 = __shfl_xor_sync(0xFFFFFFFFu, s0v, off);
      merge_ms(m0v, s0v, om0, os0);
      float om1 = __shfl_xor_sync(0xFFFFFFFFu, m1v, off);
      float os1 = __shfl_xor_sync(0xFFFFFFFFu, s1v, off);
      merge_ms(m1v, s1v, om1, os1);
    }
    if ((lane & 3) == 0){
      int rl = wm*32 + im*16 + r2;
      red_m[wn][rl]   = m0v; red_s[wn][rl]   = s0v;
      red_m[wn][rl+8] = m1v; red_s[wn][rl+8] = s1v;
    }
  }
  __syncthreads();
  if (tid < 128){
    float M = red_m[0][tid], S = red_s[0][tid];
    merge_ms(M, S, red_m[1][tid], red_s[1][tid]);
    pm[(long)blockIdx.y*TB + m0 + tid] = M;
    ps[(long)blockIdx.y*TB + m0 + tid] = S;
  }
}

/* ------ softmax over S; writes w16 (B,T,S) + dists fp32 (T,B,S) ---------- */
__global__ void softmax_s(float* __restrict__ dists, const unsigned char* __restrict__ mask){
  int bt = blockIdx.x;
  int b = bt / T_LEN, t = bt % T_LEN;
  float* row = g_w + (long)bt*SEQ;
  const unsigned char* mrow = mask + (long)b*SEQ;
  int tid = threadIdx.x;
  __shared__ float red[128];
  float mx = -1e30f;
  for (int s=tid; s<SEQ; s+=128){
    float x = mrow[s] ? -1e9f : row[s];
    mx = fmaxf(mx, x);
  }
  red[tid]=mx; __syncthreads();
  for (int off=64; off>0; off>>=1){ if (tid<off) red[tid]=fmaxf(red[tid],red[tid+off]); __syncthreads(); }
  mx = red[0]; __syncthreads();
  float sum=0.f;
  for (int s=tid; s<SEQ; s+=128){
    float x = mrow[s] ? -1e9f : row[s];
    sum += __expf(x-mx);
  }
  red[tid]=sum; __syncthreads();
  for (int off=64; off>0; off>>=1){ if (tid<off) red[tid]+=red[tid+off]; __syncthreads(); }
  float inv = 1.f/red[0];
  for (int s=tid; s<SEQ; s+=128){
    float x = mrow[s] ? -1e9f : row[s];
    float wv = __expf(x-mx)*inv;
    g_w16[(long)bt*SEQ + s] = __float2half_rn(wv);
    dists[((long)t*BATCH + b)*SEQ + s] = wv;
  }
}

/* -------- gate + stats merge + ext zero (per row) ------------------------ */
__global__ void gate_stats(float* __restrict__ out,
                           const float* __restrict__ vv, const float* __restrict__ bvv){
  int rid = blockIdx.x;
  float* row = out + (long)rid*VE;
  int tid = threadIdx.x;
  __shared__ float rm[512], rs[512];
  __shared__ float gsh;

  const float* cr = g_cat + (long)rid*H3;
  float s0 = 0.f;
  for (int j=tid; j<H3; j+=512) s0 += cr[j]*vv[j];
  rm[tid]=s0; __syncthreads();
  for (int off=256; off>0; off>>=1){ if (tid<off) rm[tid]+=rm[tid+off]; __syncthreads(); }
  if (tid==0) gsh = 1.f/(1.f+__expf(-(rm[0]+bvv[0])));
  __syncthreads();
  float g = gsh;

  float m = -1e30f, s = 0.f;
  if (tid < NSTRIPE){
    m = g_pm[(long)tid*TB + rid];
    s = g_ps[(long)tid*TB + rid];
  }
  rm[tid]=m; rs[tid]=s; __syncthreads();
  for (int off=256; off>0; off>>=1){
    if (tid<off){
      float m2=rm[tid+off], s2=rs[tid+off];
      float M=fmaxf(rm[tid],m2);
      rs[tid]=rs[tid]*__expf(rm[tid]-M)+s2*__expf(m2-M);
      rm[tid]=M;
    }
    __syncthreads();
  }
  if (tid == 0){
    g_M[rid]      = rm[0];
    g_gscale[rid] = g/rs[0];
    g_omg[rid]    = 1.f - g;
  }
  for (int j=VOC+tid; j<VE; j+=512) row[j] = 0.f;
}

/* -------- probs: streaming fp16 logit -> fp32 prob ----------------------- */
#define PROB_BX 98
__global__ void probs_k(float* __restrict__ out){
  int rid = blockIdx.y;
  int col = blockIdx.x*512 + threadIdx.x*2;
  if (col >= VOC) return;
  float M = g_M[rid];
  float gs = g_gscale[rid];
  __half2 lv = *(const __half2*)(g_l16 + (long)rid*VPAD + col);
  float2 lf = __half22float2(lv);
  float2 o;
  o.x = __expf(lf.x - M)*gs;
  o.y = __expf(lf.y - M)*gs;
  *(float2*)(out + (long)rid*VE + col) = o;
}

/* -------- scatter: out[rid, xids[s,b]] += (1-g)*dists -------------------- */
__global__ void scatter_k(float* __restrict__ out, const float* __restrict__ dists,
                          const int* __restrict__ xids){
  long i = (long)blockIdx.x*256 + threadIdx.x;
  if (i >= (long)TB*SEQ) return;
  int rid = (int)(i / SEQ);
  int s   = (int)(i % SEQ);
  int b = rid % BATCH, t = rid / BATCH;
  float wv = dists[((long)t*BATCH + b)*SEQ + s];
  int col = xids[(long)s*BATCH + b];
  atomicAdd(out + (long)rid*VE + col, g_omg[rid]*wv);
}

/* ------------------------------- host ----------------------------------- */
template<int BMT, int DUAL>
static inline void launch_h16(const GH& p, int batches, cudaStream_t st){
  constexpr int SM = 3*((BMT+BN)*128);
  static bool done = false;
  if (!done){
    cudaFuncSetAttribute(gemm_h16<BMT,DUAL>,
                         cudaFuncAttributeMaxDynamicSharedMemorySize, SM);
    done = true;
  }
  dim3 grid((p.M+BMT-1)/BMT, (p.N+BN-1)/BN, batches);
  gemm_h16<BMT,DUAL><<<grid, 256, SM, st>>>(p);
}

extern "C" void kernel_launch(void* const* d_in, const int* in_sizes, int n_in,
                              void* d_out, int out_size){
  const float* h    = (const float*)d_in[0];
  const float* yemb = (const float*)d_in[1];
  const float* mem  = (const float*)d_in[2];
  const unsigned char* mask = (const unsigned char*)d_in[3];
  const int* xids   = (const int*)d_in[4];
  int wb = 5;
  if (n_in >= 18 && in_sizes[5] == 1) wb = 6;
  const float* Wq = (const float*)d_in[wb+0];
  const float* bq = (const float*)d_in[wb+1];
  const float* Wk = (const float*)d_in[wb+2];
  const float* bk = (const float*)d_in[wb+3];
  const float* Wv = (const float*)d_in[wb+4];
  const float* bva= (const float*)d_in[wb+5];
  const float* Wo = (const float*)d_in[wb+6];
  const float* bo = (const float*)d_in[wb+7];
  const float* Wp = (const float*)d_in[wb+8];
  const float* bp = (const float*)d_in[wb+9];
  const float* vv = (const float*)d_in[wb+10];
  const float* bv = (const float*)d_in[wb+11];

  float* out   = (float*)d_out;
  float* dists = out + (long)TB*VE;

  cudaFuncSetAttribute(gemm_wp16, cudaFuncAttributeMaxDynamicSharedMemorySize, WSMEM);

  static cudaStream_t s1 = 0;
  static cudaEvent_t evF = 0, evJ = 0, evF2 = 0, evJ2 = 0, evF3 = 0, evJ3 = 0;
  if (!s1){
    cudaStreamCreateWithFlags(&s1, cudaStreamNonBlocking);
    cudaEventCreateWithFlags(&evF,  cudaEventDisableTiming);
    cudaEventCreateWithFlags(&evJ,  cudaEventDisableTiming);
    cudaEventCreateWithFlags(&evF2, cudaEventDisableTiming);
    cudaEventCreateWithFlags(&evJ2, cudaEventDisableTiming);
    cudaEventCreateWithFlags(&evF3, cudaEventDisableTiming);
    cudaEventCreateWithFlags(&evJ3, cudaEventDisableTiming);
  }

  void *wbuf, *catp, *cat16p, *wp16p, *h16p, *mem16p, *w4p;
  void *q16p, *kvp, *valT16p, *w16p, *atts16p, *l16p, *pmp, *psp;
  cudaGetSymbolAddress(&wbuf, g_w);
  cudaGetSymbolAddress(&catp, g_cat);
  cudaGetSymbolAddress(&cat16p, g_cat16);
  cudaGetSymbolAddress(&wp16p, g_wp16);
  cudaGetSymbolAddress(&h16p, g_h16);
  cudaGetSymbolAddress(&mem16p, g_mem16);
  cudaGetSymbolAddress(&w4p, g_W416);
  cudaGetSymbolAddress(&q16p, g_q16);
  cudaGetSymbolAddress(&kvp, g_kv);
  cudaGetSymbolAddress(&valT16p, g_valT16);
  cudaGetSymbolAddress(&w16p, g_w16);
  cudaGetSymbolAddress(&atts16p, g_atts16);
  cudaGetSymbolAddress(&l16p, g_l16);
  cudaGetSymbolAddress(&pmp, g_pm);
  cudaGetSymbolAddress(&psp, g_ps);

  const __half* W16 = (const __half*)w4p;
  const __half* Wq16 = W16;
  const __half* Wk16 = W16 + (long)HID*HID;
  const __half* Wv16 = W16 + 2L*HID*HID;
  const __half* Wo16 = W16 + 3L*HID*HID;

  float scale = 1.0f/sqrtf((float)HID);

  /* fork: conv_wp16 on s1 overlaps the attention chain */
  cudaEventRecord(evF, 0);
  cudaStreamWaitEvent(s1, evF, 0);
  conv_wp16<<<WP_GRID, 256, 0, s1>>>(Wp);
  cudaEventRecord(evJ, s1);

  /* merged head converters */
  conv_head<<<HEAD_GRID, 256>>>(mem, Wq, Wk, Wv, Wo, h, yemb);

  GH p;

  /* fork q on s1 */
  cudaEventRecord(evF2, 0);
  cudaStreamWaitEvent(s1, evF2, 0);
  p = GH{};
  p.A = (const __half*)h16p; p.B = Wq16; p.Ch = (__half*)q16p;
  p.lda = HID; p.ldb = HID; p.ldc = HID;
  p.M = TB; p.N = HID; p.K = HID;
  p.bias = bq; p.alpha = scale;
  p.mode = 1; p.D1 = BATCH; p.D2 = T_LEN;
  launch_h16<64,0>(p, 1, s1);
  cudaEventRecord(evJ2, s1);

  /* fused k & val projection -> kv (S,B,1024), staged coalesced epilogue */
  p = GH{};
  p.A = (const __half*)mem16p; p.B = Wk16; p.B2 = Wv16;
  p.Ch = (__half*)kvp;
  p.lda = HID; p.ldb = HID;
  p.M = SEQ*BATCH; p.N = 2*HID; p.K = HID;
  p.bias = bk; p.bias2 = bva;
  p.mode = 3;
  launch_h16<128,1>(p, 1, 0);

  /* fork val transpose on s1 (needs kv); overlaps scores + softmax_s */
  cudaEventRecord(evF3, 0);
  cudaStreamWaitEvent(s1, evF3, 0);
  transpose_v<<<dim3((SEQ+31)/32, HID/32, BATCH), dim3(32,8), 0, s1>>>();
  cudaEventRecord(evJ3, s1);

  cudaStreamWaitEvent(0, evJ2, 0);

  /* scores: B = k half of kv; row s at kv + (s*BATCH+b)*1024 */
  p = GH{};
  p.A = (const __half*)q16p; p.B = (const __half*)kvp; p.Cf = (float*)wbuf;
  p.lda = HID; p.ldb = (long)BATCH*1024; p.ldc = SEQ;
  p.sA = (long)T_LEN*HID; p.sB = 1024; p.sC = (long)T_LEN*SEQ;
  p.M = T_LEN; p.N = SEQ; p.K = HID;
  p.mode = 0;
  launch_h16<64,0>(p, BATCH, 0);

  softmax_s<<<BATCH*T_LEN, 128>>>(dists, mask);

  cudaStreamWaitEvent(0, evJ3, 0);

  /* atts */
  p = GH{};
  p.A = (const __half*)w16p; p.B = (const __half*)valT16p; p.Ch = (__half*)atts16p;
  p.lda = SEQ; p.ldb = SEQ; p.ldc = HID;
  p.sA = (long)T_LEN*SEQ; p.sB = (long)HID*SEQ; p.sC = (long)T_LEN*HID;
  p.M = T_LEN; p.N = HID; p.K = SEQ;
  p.mode = 4;
  launch_h16<64,0>(p, BATCH, 0);

  /* wo -> cat + cat16 */
  p = GH{};
  p.A = (const __half*)atts16p; p.B = Wo16;
  p.Cf = (float*)catp; p.Ch = (__half*)cat16p;
  p.lda = HID; p.ldb = HID; p.ldc = H3;
  p.M = TB; p.N = HID; p.K = HID;
  p.bias = bo;
  p.mode = 5; p.D1 = T_LEN; p.D2 = BATCH; p.col_off = 1024;
  launch_h16<64,0>(p, 1, 0);

  cudaStreamWaitEvent(0, evJ, 0);

  /* logits + per-stripe stats */
  gemm_wp16<<<dim3(TB/WBM, VPAD/WBN2), 256, WSMEM>>>(
      (const __half*)cat16p, (const __half*)wp16p, bp,
      (__half*)l16p, (float*)pmp, (float*)psp);

  /* tail */
  gate_stats<<<TB, 512>>>(out, vv, bv);
  probs_k<<<dim3(PROB_BX, TB), 256>>>(out);
  scatter_k<<<(int)(((long)TB*SEQ + 255)/256), 256>>>(out, dists, xids);

  (void)out_size; (void)n_in;
}

// round 16
// speedup vs baseline: 1.3027x; 1.0147x over previous
#include <cuda_runtime.h>
#include <cuda_fp16.h>
#include <math.h>
#include <stdint.h>

#define T_LEN 64
#define BATCH 32
#define SEQ   400
#define HID   512
#define VOC   50000
#define EXTD  400
#define VE    (VOC+EXTD)
#define TB    (T_LEN*BATCH)     /* 2048 */
#define H3    (3*HID)           /* 1536 */
#define VPAD  50176             /* VOC padded to 256 */
#define NSTRIPE (VPAD/128)      /* 392 */

/* ---------------- scratch (device globals: allocation-free) -------------- */
__device__ float  g_cat [TB*H3];              /* (T*B,3H) fp32 (gate)        */
__device__ float  g_w   [BATCH*T_LEN*SEQ];    /* scores fp32 (B,T,S)         */
__device__ __half g_cat16[TB*H3];
__device__ __half g_wp16 [(long)VPAD*H3];
__device__ __half g_h16  [TB*HID];
__device__ __half g_mem16[SEQ*BATCH*HID];
__device__ __half g_W416 [4*HID*HID];         /* Wq,Wk,Wv,Wo                 */
__device__ __half g_q16  [BATCH*T_LEN*HID];   /* (B,T,H)                     */
__device__ __half g_kv   [(long)SEQ*BATCH*1024]; /* (S,B,[k(512)|v(512)])    */
__device__ __half g_valT16[BATCH*HID*SEQ];    /* (B,H,S)                     */
__device__ __half g_w16  [BATCH*T_LEN*SEQ];   /* attn weights fp16           */
__device__ __half g_atts16[TB*HID];           /* (B,T,H) rows b*T+t          */
__device__ __half g_l16  [(long)TB*VPAD];     /* fp16 logits                 */
__device__ float  g_pm   [NSTRIPE*TB];        /* per-stripe softmax max      */
__device__ float  g_ps   [NSTRIPE*TB];        /* per-stripe softmax sum      */
__device__ float  g_gscale[TB];               /* g / sumexp                  */
__device__ float  g_M    [TB];                /* row max                     */
__device__ float  g_omg  [TB];                /* 1 - g                       */

#define BN 128

__device__ __forceinline__ void cpa16u(unsigned dst, const void* src, int bytes){
  asm volatile("cp.async.cg.shared.global [%0], [%1], 16, %2;\n"
               :: "r"(dst), "l"(src), "r"(bytes));
}
#define CPA_COMMIT() asm volatile("cp.async.commit_group;\n")
#define CPA_WAIT2()  asm volatile("cp.async.wait_group 2;\n")

#define LDSM_X4(r0,r1,r2,r3,addr) \
  asm volatile("ldmatrix.sync.aligned.m8n8.x4.shared.b16 {%0,%1,%2,%3}, [%4];" \
               : "=r"(r0), "=r"(r1), "=r"(r2), "=r"(r3) : "r"(addr))

#define MMA16(d, a0,a1,a2,a3, b0,b1) \
  asm volatile("mma.sync.aligned.m16n8k16.row.col.f32.f16.f16.f32 " \
               "{%0,%1,%2,%3}, {%4,%5,%6,%7}, {%8,%9}, {%0,%1,%2,%3};\n" \
               : "+f"((d)[0]), "+f"((d)[1]), "+f"((d)[2]), "+f"((d)[3]) \
               : "r"(a0), "r"(a1), "r"(a2), "r"(a3), "r"(b0), "r"(b1))

/* ---------------- generic fp16 MMA GEMM --------------------------------- */
struct GH {
  const __half* A; const __half* B; const __half* B2;
  float* Cf; __half* Ch; __half* Ch2;
  long lda, ldb, ldc;
  long sA, sB, sC;
  int  M, N, K;
  const float* bias; const float* bias2;
  float alpha;
  int  mode, D1, D2;
  long col_off;
};

template<int BMT, int DUAL>
__global__ __launch_bounds__(256,2) void gemm_h16(GH p){
  constexpr int WM   = BMT/32;
  constexpr int NCOL = BN/(8/WM);
  constexpr int NFR  = NCOL/8;
  constexpr int NBL  = NCOL/16;
  constexpr int ABYT = BMT*128;
  constexpr int SBYT = ABYT + BN*128;
  constexpr int GT   = (BMT+BN)*8;

  extern __shared__ float smf[];
  uint32_t sbase = (uint32_t)__cvta_generic_to_shared(smf);
  const __half* A  = p.A + (long)blockIdx.z * p.sA;
  const __half* Bg = p.B + (long)blockIdx.z * p.sB;
  float*  Cf = p.Cf ? p.Cf + (long)blockIdx.z * p.sC : (float*)0;
  __half* Ch = p.Ch ? p.Ch + (long)blockIdx.z * p.sC : (__half*)0;

  int tid = threadIdx.x;
  int lane = tid & 31, warp = tid >> 5;
  int wm = warp % WM, wn = warp / WM;
  int m0 = blockIdx.x * BMT, n0 = blockIdx.y * BN;

  float acc[2][NFR][4];
  #pragma unroll
  for (int i=0;i<2;i++)
    #pragma unroll
    for (int j=0;j<NFR;j++){ acc[i][j][0]=0.f; acc[i][j][1]=0.f; acc[i][j][2]=0.f; acc[i][j][3]=0.f; }

  int ktiles = (p.K + 63)/64;

  auto load = [&](int st, int k0){
    uint32_t ab = sbase + st*SBYT;
    uint32_t bb = ab + ABYT;
    #pragma unroll
    for (int i=0;i<GT/256;i++){
      int g = tid + i*256;
      int r = g >> 3, gc = g & 7;
      int kcol = k0 + gc*8;
      int kb = (kcol < p.K) ? 16 : 0;
      if (r < BMT){
        uint32_t soff = (uint32_t)(r*128 + ((gc ^ (r&7))<<4));
        int gm = m0 + r;
        cpa16u(ab + soff, A + (long)gm*p.lda + kcol, (gm < p.M) ? kb : 0);
      } else {
        int rb = r - BMT;
        uint32_t soff = (uint32_t)(rb*128 + ((gc ^ (rb&7))<<4));
        int gn = n0 + rb;
        const __half* src;
        if (DUAL && gn >= HID) src = p.B2 + (long)(gn-HID)*p.ldb + kcol;
        else                   src = Bg  + (long)gn*p.ldb + kcol;
        cpa16u(bb + soff, src, (gn < p.N) ? kb : 0);
      }
    }
  };

  load(0, 0); CPA_COMMIT();
  load(1, 64); CPA_COMMIT();

  int mi1 = (lane >> 3) & 1;
  int kg2 = lane >> 4;
  int ri  = lane & 7;
  int marow = wm*32 + mi1*8 + ri;
  int nbrow = wn*NCOL + mi1*8 + ri;
  int maxor = (marow & 7);
  int nbxor = (nbrow & 7);

  for (int kt = 0; kt < ktiles; kt++){
    if (kt + 2 < ktiles) load((kt+2)%3, (kt+2)*64);
    CPA_COMMIT();
    CPA_WAIT2();
    __syncthreads();

    uint32_t ab = sbase + (kt%3)*SBYT;
    uint32_t aA = ab + marow*128;
    uint32_t aB = ab + ABYT + nbrow*128;

    #pragma unroll
    for (int kk=0; kk<4; kk++){
      uint32_t asw = (uint32_t)(((kk*2 + kg2) ^ maxor) << 4);
      uint32_t bsw = (uint32_t)(((kk*2 + kg2) ^ nbxor) << 4);
      unsigned af0[4], af1[4], bf[NBL][4];
      LDSM_X4(af0[0],af0[1],af0[2],af0[3], aA + asw);
      LDSM_X4(af1[0],af1[1],af1[2],af1[3], aA + asw + 16*128);
      #pragma unroll
      for (int jp=0; jp<NBL; jp++)
        LDSM_X4(bf[jp][0],bf[jp][1],bf[jp][2],bf[jp][3], aB + bsw + jp*16*128);
      #pragma unroll
      for (int jp=0; jp<NBL; jp++){
        MMA16(acc[0][2*jp  ], af0[0],af0[1],af0[2],af0[3], bf[jp][0], bf[jp][2]);
        MMA16(acc[0][2*jp+1], af0[0],af0[1],af0[2],af0[3], bf[jp][1], bf[jp][3]);
        MMA16(acc[1][2*jp  ], af1[0],af1[1],af1[2],af1[3], bf[jp][0], bf[jp][2]);
        MMA16(acc[1][2*jp+1], af1[0],af1[1],af1[2],af1[3], bf[jp][1], bf[jp][3]);
      }
    }
    __syncthreads();
  }

  if (DUAL){
    /* staged coalesced epilogue: smem tile + bias, then uint4 rows to kv    */
    constexpr int TP = 136;
    __half* tile = (__half*)smf;
    const float* bptr = (n0 < HID) ? p.bias : p.bias2;
    int nb0 = (n0 < HID) ? n0 : n0 - HID;
    int r = lane >> 2, c2v = (lane & 3)*2;
    #pragma unroll
    for (int im=0; im<2; im++)
      #pragma unroll
      for (int jn=0; jn<NFR; jn++){
        int ml = wm*32 + im*16 + r;
        int nl = wn*NCOL + jn*8 + c2v;
        float b0 = bptr[nb0 + nl], b1 = bptr[nb0 + nl + 1];
        tile[ ml   *TP + nl    ] = __float2half_rn(acc[im][jn][0] + b0);
        tile[ ml   *TP + nl + 1] = __float2half_rn(acc[im][jn][1] + b1);
        tile[(ml+8)*TP + nl    ] = __float2half_rn(acc[im][jn][2] + b0);
        tile[(ml+8)*TP + nl + 1] = __float2half_rn(acc[im][jn][3] + b1);
      }
    __syncthreads();
    #pragma unroll
    for (int i2=0; i2<8; i2++){
      int i = tid + i2*256;
      int rr = i >> 4, cc = (i & 15)*8;
      uint4 v = *(uint4*)&tile[rr*TP + cc];
      *(uint4*)(p.Ch + (long)(m0 + rr)*1024 + n0 + cc) = v;
    }
    return;
  }

  /* ---- staged coalesced epilogues for BMT=64 modes ---------------------- */
  int r = lane >> 2, c2 = (lane & 3)*2;

  if (p.mode == 0){
    /* scores: fp32 tile, coalesced float4 rows; N may be ragged (400)       */
    constexpr int TPF = BN + 4;
    float* tf = smf;                     /* 64 x 132 fp32 = 33792 B          */
    #pragma unroll
    for (int im=0; im<2; im++)
      #pragma unroll
      for (int jn=0; jn<NFR; jn++){
        int ml = wm*32 + im*16 + r;
        int nl = wn*NCOL + jn*8 + c2;
        tf[ ml   *TPF + nl    ] = acc[im][jn][0];
        tf[ ml   *TPF + nl + 1] = acc[im][jn][1];
        tf[(ml+8)*TPF + nl    ] = acc[im][jn][2];
        tf[(ml+8)*TPF + nl + 1] = acc[im][jn][3];
      }
    __syncthreads();
    int nvalid = p.N - n0; if (nvalid > BN) nvalid = BN;
    #pragma unroll
    for (int i2=0; i2<8; i2++){
      int i = tid + i2*256;              /* 64 rows x 32 float4 chunks       */
      int rr = i >> 5, cc = (i & 31)*4;
      if (cc < nvalid){
        float4 v = *(float4*)&tf[rr*TPF + cc];
        *(float4*)(Cf + (long)(m0 + rr)*p.ldc + n0 + cc) = v;
      }
    }
    return;
  }

  if (p.mode == 1 || p.mode == 4){
    /* fp16 tile; mode 1 applies alpha*(v+bias) and a row permute            */
    constexpr int TP = 136;
    __half* th = (__half*)smf;           /* 64 x 136 halves                  */
    #pragma unroll
    for (int im=0; im<2; im++)
      #pragma unroll
      for (int jn=0; jn<NFR; jn++){
        int ml = wm*32 + im*16 + r;
        int nl = wn*NCOL + jn*8 + c2;
        float v0 = acc[im][jn][0], v1 = acc[im][jn][1];
        float v2 = acc[im][jn][2], v3 = acc[im][jn][3];
        if (p.mode == 1){
          float b0 = p.bias[n0 + nl], b1 = p.bias[n0 + nl + 1];
          v0 = p.alpha*(v0 + b0); v1 = p.alpha*(v1 + b1);
          v2 = p.alpha*(v2 + b0); v3 = p.alpha*(v3 + b1);
        }
        th[ ml   *TP + nl    ] = __float2half_rn(v0);
        th[ ml   *TP + nl + 1] = __float2half_rn(v1);
        th[(ml+8)*TP + nl    ] = __float2half_rn(v2);
        th[(ml+8)*TP + nl + 1] = __float2half_rn(v3);
      }
    __syncthreads();
    #pragma unroll
    for (int i2=0; i2<4; i2++){
      int i = tid + i2*256;              /* 64 rows x 16 uint4 chunks        */
      int rr = i >> 4, cc = (i & 15)*8;
      int gm = m0 + rr;
      long grow = (p.mode == 1) ? ((long)(gm % p.D1)*p.D2 + gm/p.D1) : gm;
      uint4 v = *(uint4*)&th[rr*TP + cc];
      *(uint4*)(Ch + grow*p.ldc + n0 + cc) = v;
    }
    return;
  }

  /* mode 5: fp32 tile (v+bias); writer emits fp32 cat + fp16 cat16, permuted*/
  {
    constexpr int TPF = BN + 4;
    float* tf = smf;
    #pragma unroll
    for (int im=0; im<2; im++)
      #pragma unroll
      for (int jn=0; jn<NFR; jn++){
        int ml = wm*32 + im*16 + r;
        int nl = wn*NCOL + jn*8 + c2;
        float b0 = p.bias[n0 + nl], b1 = p.bias[n0 + nl + 1];
        tf[ ml   *TPF + nl    ] = acc[im][jn][0] + b0;
        tf[ ml   *TPF + nl + 1] = acc[im][jn][1] + b1;
        tf[(ml+8)*TPF + nl    ] = acc[im][jn][2] + b0;
        tf[(ml+8)*TPF + nl + 1] = acc[im][jn][3] + b1;
      }
    __syncthreads();
    #pragma unroll
    for (int i2=0; i2<4; i2++){
      int i = tid + i2*256;              /* 64 rows x 16 8-col chunks        */
      int rr = i >> 4, cc = (i & 15)*8;
      int gm = m0 + rr;
      long grow = (long)(gm % p.D1)*p.D2 + gm/p.D1;
      long base = grow*p.ldc + p.col_off + n0 + cc;
      float4 a = *(float4*)&tf[rr*TPF + cc];
      float4 b = *(float4*)&tf[rr*TPF + cc + 4];
      *(float4*)(Cf + base)     = a;
      *(float4*)(Cf + base + 4) = b;
      __half2 hh[4];
      hh[0] = __floats2half2_rn(a.x, a.y);
      hh[1] = __floats2half2_rn(a.z, a.w);
      hh[2] = __floats2half2_rn(b.x, b.y);
      hh[3] = __floats2half2_rn(b.z, b.w);
      *(uint4*)(Ch + base) = *(uint4*)hh;
    }
  }
}

/* ---- transpose: kv val-half (S,B,512) -> valT (B,H,S) ------------------- */
__global__ void transpose_v(){
  __shared__ __half tile[32][33];
  int b  = blockIdx.z;
  int h0 = blockIdx.y * 32;
  int s0 = blockIdx.x * 32;
  int x = threadIdx.x, y = threadIdx.y;
  #pragma unroll
  for (int k2=0;k2<4;k2++){
    int s = s0 + y + k2*8;
    if (s < SEQ)
      tile[y+k2*8][x] = g_kv[((long)s*BATCH + b)*1024 + 512 + h0 + x];
  }
  __syncthreads();
  int s = s0 + x;
  if (s < SEQ){
    #pragma unroll
    for (int k2=0;k2<4;k2++){
      int hh = h0 + y + k2*8;
      g_valT16[((long)b*HID + hh)*SEQ + s] = tile[x][y+k2*8];
    }
  }
}

/* ---------------- fp16 converters (MLP=4) -------------------------------- */
#define WP_GRID  18816
#define WP_STRIDE ((long)WP_GRID*256)
__global__ void conv_wp16(const float* __restrict__ Wp){
  long i0 = (long)blockIdx.x*256 + threadIdx.x;
  float4 v[4];
  long idx[4];
  #pragma unroll
  for (int u=0; u<4; u++){
    long i = i0 + (long)u*WP_STRIDE;
    idx[u] = i;
    long row = i / (H3/4);
    long c4  = i % (H3/4);
    v[u] = (row < VOC) ? *(const float4*)(Wp + row*H3 + c4*4)
                       : make_float4(0.f,0.f,0.f,0.f);
  }
  __half2* dst = (__half2*)g_wp16;
  #pragma unroll
  for (int u=0; u<4; u++){
    dst[idx[u]*2]   = __floats2half2_rn(v[u].x, v[u].y);
    dst[idx[u]*2+1] = __floats2half2_rn(v[u].z, v[u].w);
  }
}

/* ---- merged head: mem16 + W416 + cat/cat16/h16 --------------------------- */
#define MEM_GRID 1600
#define MEM_STRIDE ((long)MEM_GRID*256)
#define WTS_GRID 256
#define WTS_STRIDE (WTS_GRID*256)
#define CAT_GRID 1024
#define HEAD_GRID (MEM_GRID + WTS_GRID + CAT_GRID)
__global__ void conv_head(const float* __restrict__ mem,
                          const float* __restrict__ Wq, const float* __restrict__ Wk,
                          const float* __restrict__ Wv, const float* __restrict__ Wo,
                          const float* __restrict__ h, const float* __restrict__ y){
  int bx = blockIdx.x;
  int tid = threadIdx.x;
  if (bx < MEM_GRID){
    long i0 = (long)bx*256 + tid;
    float4 v[4];
    #pragma unroll
    for (int u=0; u<4; u++) v[u] = *(const float4*)(mem + (i0 + (long)u*MEM_STRIDE)*4);
    __half2* dst = (__half2*)g_mem16;
    #pragma unroll
    for (int u=0; u<4; u++){
      long i = i0 + (long)u*MEM_STRIDE;
      dst[i*2]   = __floats2half2_rn(v[u].x, v[u].y);
      dst[i*2+1] = __floats2half2_rn(v[u].z, v[u].w);
    }
    return;
  }
  bx -= MEM_GRID;
  if (bx < WTS_GRID){
    int i0 = bx*256 + tid;
    const int per = HID*HID/4;
    float4 v[4];
    #pragma unroll
    for (int u=0; u<4; u++){
      int i = i0 + u*WTS_STRIDE;
      int seg = i / per, off = i % per;
      const float* src = (seg==0)?Wq:(seg==1)?Wk:(seg==2)?Wv:Wo;
      v[u] = *(const float4*)(src + (long)off*4);
    }
    __half2* dst = (__half2*)g_W416;
    #pragma unroll
    for (int u=0; u<4; u++){
      int i = i0 + u*WTS_STRIDE;
      dst[i*2]   = __floats2half2_rn(v[u].x, v[u].y);
      dst[i*2+1] = __floats2half2_rn(v[u].z, v[u].w);
    }
    return;
  }
  bx -= WTS_GRID;
  {
    int i = bx*256 + tid;
    int row = i / (HID/4);
    int c   = i % (HID/4);
    const float4 hv = ((const float4*)h)[i];
    const float4 yv = ((const float4*)y)[i];
    float4* cat4 = (float4*)g_cat;
    cat4[(long)row*(H3/4) + c]           = hv;
    cat4[(long)row*(H3/4) + (HID/4) + c] = yv;
    __half2* c16 = (__half2*)g_cat16;
    long b = (long)row*(H3/2);
    __half2 h01 = __floats2half2_rn(hv.x, hv.y);
    __half2 h23 = __floats2half2_rn(hv.z, hv.w);
    c16[b + c*2]               = h01;
    c16[b + c*2 + 1]           = h23;
    c16[b + (HID/2) + c*2]     = __floats2half2_rn(yv.x, yv.y);
    c16[b + (HID/2) + c*2 + 1] = __floats2half2_rn(yv.z, yv.w);
    __half2* h16 = (__half2*)g_h16;
    h16[i*2]   = h01;
    h16[i*2+1] = h23;
  }
}

/* == fp16 Wp GEMM: 128x128 CTA, 256 thr, 2 CTA/SM, fused softmax stats === */
#define WBM 128
#define WBN2 128
#define WABY (WBM*128)
#define WSBY (WABY + WBN2*128)
#define WSMEM (3*WSBY)

__device__ __forceinline__ void merge_ms(float& m, float& s, float m2, float s2){
  float M = fmaxf(m, m2);
  s = s*__expf(m-M) + s2*__expf(m2-M);
  m = M;
}

__global__ __launch_bounds__(256,2) void gemm_wp16(
    const __half* __restrict__ A, const __half* __restrict__ B,
    const float* __restrict__ bias, __half* __restrict__ l16,
    float* __restrict__ pm, float* __restrict__ ps)
{
  extern __shared__ float smf[];
  __shared__ float red_m[2][128], red_s[2][128];
  uint32_t sbase = (uint32_t)__cvta_generic_to_shared(smf);
  int tid = threadIdx.x;
  int lane = tid & 31, warp = tid >> 5;
  int wm = warp & 3, wn = warp >> 2;
  int m0 = blockIdx.x * WBM, n0 = blockIdx.y * WBN2;

  float acc[2][8][4];
  #pragma unroll
  for (int i=0;i<2;i++)
    #pragma unroll
    for (int j=0;j<8;j++){ acc[i][j][0]=0.f; acc[i][j][1]=0.f; acc[i][j][2]=0.f; acc[i][j][3]=0.f; }

  const int ktiles = H3/64;

  auto load = [&](int st, int k0){
    uint32_t ab = sbase + st*WSBY;
    uint32_t bb = ab + WABY;
    #pragma unroll
    for (int i=0;i<8;i++){
      int g = tid + i*256;
      int r = g >> 3, gc = g & 7;
      int kcol = k0 + gc*8;
      if (r < WBM){
        uint32_t soff = (uint32_t)(r*128 + ((gc ^ (r&7))<<4));
        cpa16u(ab + soff, A + (long)(m0 + r)*H3 + kcol, 16);
      } else {
        int rb = r - WBM;
        uint32_t soff = (uint32_t)(rb*128 + ((gc ^ (rb&7))<<4));
        cpa16u(bb + soff, B + (long)(n0 + rb)*H3 + kcol, 16);
      }
    }
  };

  load(0, 0); CPA_COMMIT();
  load(1, 64); CPA_COMMIT();

  int mi1 = (lane >> 3) & 1;
  int kg2 = lane >> 4;
  int ri  = lane & 7;
  int marow = wm*32 + mi1*8 + ri;
  int nbrow = wn*64 + mi1*8 + ri;
  int maxor = (marow & 7);
  int nbxor = (nbrow & 7);

  for (int kt = 0; kt < ktiles; kt++){
    if (kt + 2 < ktiles) load((kt+2)%3, (kt+2)*64);
    CPA_COMMIT();
    CPA_WAIT2();
    __syncthreads();

    uint32_t ab = sbase + (kt%3)*WSBY;
    uint32_t aA = ab + marow*128;
    uint32_t aB = ab + WABY + nbrow*128;

    #pragma unroll
    for (int kk=0; kk<4; kk++){
      uint32_t asw = (uint32_t)(((kk*2 + kg2) ^ maxor) << 4);
      uint32_t bsw = (uint32_t)(((kk*2 + kg2) ^ nbxor) << 4);
      unsigned af0[4], af1[4], bf[4][4];
      LDSM_X4(af0[0],af0[1],af0[2],af0[3], aA + asw);
      LDSM_X4(af1[0],af1[1],af1[2],af1[3], aA + asw + 16*128);
      #pragma unroll
      for (int jb=0; jb<4; jb++)
        LDSM_X4(bf[jb][0],bf[jb][1],bf[jb][2],bf[jb][3], aB + bsw + jb*16*128);
      #pragma unroll
      for (int jb=0; jb<4; jb++){
        MMA16(acc[0][2*jb  ], af0[0],af0[1],af0[2],af0[3], bf[jb][0], bf[jb][2]);
        MMA16(acc[0][2*jb+1], af0[0],af0[1],af0[2],af0[3], bf[jb][1], bf[jb][3]);
        MMA16(acc[1][2*jb  ], af1[0],af1[1],af1[2],af1[3], bf[jb][0], bf[jb][2]);
        MMA16(acc[1][2*jb+1], af1[0],af1[1],af1[2],af1[3], bf[jb][1], bf[jb][3]);
      }
    }
    __syncthreads();
  }

  int r2 = lane >> 2, c2 = (lane & 3)*2;
  #pragma unroll
  for (int im=0; im<2; im++){
    int mr = m0 + wm*32 + im*16 + r2;
    float m0v=-1e30f, m1v=-1e30f, s0v=0.f, s1v=0.f;
    #pragma unroll
    for (int nj=0; nj<8; nj++){
      int nc = n0 + wn*64 + nj*8 + c2;
      if (nc < VOC){
        float b0 = bias[nc], b1 = bias[nc+1];
        float v00 = acc[im][nj][0]+b0, v01 = acc[im][nj][1]+b1;
        float v10 = acc[im][nj][2]+b0, v11 = acc[im][nj][3]+b1;
        acc[im][nj][0]=v00; acc[im][nj][1]=v01;
        acc[im][nj][2]=v10; acc[im][nj][3]=v11;
        *(__half2*)(l16 + (long)mr*VPAD + nc)     = __floats2half2_rn(v00,v01);
        *(__half2*)(l16 + (long)(mr+8)*VPAD + nc) = __floats2half2_rn(v10,v11);
        m0v = fmaxf(m0v, fmaxf(v00,v01));
        m1v = fmaxf(m1v, fmaxf(v10,v11));
      }
    }
    #pragma unroll
    for (int nj=0; nj<8; nj++){
      int nc = n0 + wn*64 + nj*8 + c2;
      if (nc < VOC){
        s0v += __expf(acc[im][nj][0]-m0v) + __expf(acc[im][nj][1]-m0v);
        s1v += __expf(acc[im][nj][2]-m1v) + __expf(acc[im][nj][3]-m1v);
      }
    }
    #pragma unroll
    for (int off=1; off<4; off<<=1){
      float om0 = __shfl_xor_sync(0xFFFFFFFFu, m0v, off);
      float os0 = __shfl_xor_sync(0xFFFFFFFFu, s0v, off);
      merge_ms(m0v, s0v, om0, os0);
      float om1 = __shfl_xor_sync(0xFFFFFFFFu, m1v, off);
      float os1 = __shfl_xor_sync(0xFFFFFFFFu, s1v, off);
      merge_ms(m1v, s1v, om1, os1);
    }
    if ((lane & 3) == 0){
      int rl = wm*32 + im*16 + r2;
      red_m[wn][rl]   = m0v; red_s[wn][rl]   = s0v;
      red_m[wn][rl+8] = m1v; red_s[wn][rl+8] = s1v;
    }
  }
  __syncthreads();
  if (tid < 128){
    float M = red_m[0][tid], S = red_s[0][tid];
    merge_ms(M, S, red_m[1][tid], red_s[1][tid]);
    pm[(long)blockIdx.y*TB + m0 + tid] = M;
    ps[(long)blockIdx.y*TB + m0 + tid] = S;
  }
}

/* ------ softmax over S; writes w16 (B,T,S) + dists fp32 (T,B,S) ---------- */
__global__ void softmax_s(float* __restrict__ dists, const unsigned char* __restrict__ mask){
  int bt = blockIdx.x;
  int b = bt / T_LEN, t = bt % T_LEN;
  float* row = g_w + (long)bt*SEQ;
  const unsigned char* mrow = mask + (long)b*SEQ;
  int tid = threadIdx.x;
  __shared__ float red[128];
  float mx = -1e30f;
  for (int s=tid; s<SEQ; s+=128){
    float x = mrow[s] ? -1e9f : row[s];
    mx = fmaxf(mx, x);
  }
  red[tid]=mx; __syncthreads();
  for (int off=64; off>0; off>>=1){ if (tid<off) red[tid]=fmaxf(red[tid],red[tid+off]); __syncthreads(); }
  mx = red[0]; __syncthreads();
  float sum=0.f;
  for (int s=tid; s<SEQ; s+=128){
    float x = mrow[s] ? -1e9f : row[s];
    sum += __expf(x-mx);
  }
  red[tid]=sum; __syncthreads();
  for (int off=64; off>0; off>>=1){ if (tid<off) red[tid]+=red[tid+off]; __syncthreads(); }
  float inv = 1.f/red[0];
  for (int s=tid; s<SEQ; s+=128){
    float x = mrow[s] ? -1e9f : row[s];
    float wv = __expf(x-mx)*inv;
    g_w16[(long)bt*SEQ + s] = __float2half_rn(wv);
    dists[((long)t*BATCH + b)*SEQ + s] = wv;
  }
}

/* -------- gate + stats merge + ext zero (per row) ------------------------ */
__global__ void gate_stats(float* __restrict__ out,
                           const float* __restrict__ vv, const float* __restrict__ bvv){
  int rid = blockIdx.x;
  float* row = out + (long)rid*VE;
  int tid = threadIdx.x;
  __shared__ float rm[512], rs[512];
  __shared__ float gsh;

  const float* cr = g_cat + (long)rid*H3;
  float s0 = 0.f;
  for (int j=tid; j<H3; j+=512) s0 += cr[j]*vv[j];
  rm[tid]=s0; __syncthreads();
  for (int off=256; off>0; off>>=1){ if (tid<off) rm[tid]+=rm[tid+off]; __syncthreads(); }
  if (tid==0) gsh = 1.f/(1.f+__expf(-(rm[0]+bvv[0])));
  __syncthreads();
  float g = gsh;

  float m = -1e30f, s = 0.f;
  if (tid < NSTRIPE){
    m = g_pm[(long)tid*TB + rid];
    s = g_ps[(long)tid*TB + rid];
  }
  rm[tid]=m; rs[tid]=s; __syncthreads();
  for (int off=256; off>0; off>>=1){
    if (tid<off){
      float m2=rm[tid+off], s2=rs[tid+off];
      float M=fmaxf(rm[tid],m2);
      rs[tid]=rs[tid]*__expf(rm[tid]-M)+s2*__expf(m2-M);
      rm[tid]=M;
    }
    __syncthreads();
  }
  if (tid == 0){
    g_M[rid]      = rm[0];
    g_gscale[rid] = g/rs[0];
    g_omg[rid]    = 1.f - g;
  }
  for (int j=VOC+tid; j<VE; j+=512) row[j] = 0.f;
}

/* -------- probs: streaming fp16 logit -> fp32 prob ----------------------- */
#define PROB_BX 98
__global__ void probs_k(float* __restrict__ out){
  int rid = blockIdx.y;
  int col = blockIdx.x*512 + threadIdx.x*2;
  if (col >= VOC) return;
  float M = g_M[rid];
  float gs = g_gscale[rid];
  __half2 lv = *(const __half2*)(g_l16 + (long)rid*VPAD + col);
  float2 lf = __half22float2(lv);
  float2 o;
  o.x = __expf(lf.x - M)*gs;
  o.y = __expf(lf.y - M)*gs;
  *(float2*)(out + (long)rid*VE + col) = o;
}

/* -------- scatter: out[rid, xids[s,b]] += (1-g)*dists -------------------- */
__global__ void scatter_k(float* __restrict__ out, const float* __restrict__ dists,
                          const int* __restrict__ xids){
  long i = (long)blockIdx.x*256 + threadIdx.x;
  if (i >= (long)TB*SEQ) return;
  int rid = (int)(i / SEQ);
  int s   = (int)(i % SEQ);
  int b = rid % BATCH, t = rid / BATCH;
  float wv = dists[((long)t*BATCH + b)*SEQ + s];
  int col = xids[(long)s*BATCH + b];
  atomicAdd(out + (long)rid*VE + col, g_omg[rid]*wv);
}

/* ------------------------------- host ----------------------------------- */
template<int BMT, int DUAL>
static inline void launch_h16(const GH& p, int batches, cudaStream_t st){
  constexpr int SM = 3*((BMT+BN)*128);
  static bool done = false;
  if (!done){
    cudaFuncSetAttribute(gemm_h16<BMT,DUAL>,
                         cudaFuncAttributeMaxDynamicSharedMemorySize, SM);
    done = true;
  }
  dim3 grid((p.M+BMT-1)/BMT, (p.N+BN-1)/BN, batches);
  gemm_h16<BMT,DUAL><<<grid, 256, SM, st>>>(p);
}

extern "C" void kernel_launch(void* const* d_in, const int* in_sizes, int n_in,
                              void* d_out, int out_size){
  const float* h    = (const float*)d_in[0];
  const float* yemb = (const float*)d_in[1];
  const float* mem  = (const float*)d_in[2];
  const unsigned char* mask = (const unsigned char*)d_in[3];
  const int* xids   = (const int*)d_in[4];
  int wb = 5;
  if (n_in >= 18 && in_sizes[5] == 1) wb = 6;
  const float* Wq = (const float*)d_in[wb+0];
  const float* bq = (const float*)d_in[wb+1];
  const float* Wk = (const float*)d_in[wb+2];
  const float* bk = (const float*)d_in[wb+3];
  const float* Wv = (const float*)d_in[wb+4];
  const float* bva= (const float*)d_in[wb+5];
  const float* Wo = (const float*)d_in[wb+6];
  const float* bo = (const float*)d_in[wb+7];
  const float* Wp = (const float*)d_in[wb+8];
  const float* bp = (const float*)d_in[wb+9];
  const float* vv = (const float*)d_in[wb+10];
  const float* bv = (const float*)d_in[wb+11];

  float* out   = (float*)d_out;
  float* dists = out + (long)TB*VE;

  cudaFuncSetAttribute(gemm_wp16, cudaFuncAttributeMaxDynamicSharedMemorySize, WSMEM);

  static cudaStream_t s1 = 0;
  static cudaEvent_t evF = 0, evJ = 0, evF2 = 0, evJ2 = 0, evF3 = 0, evJ3 = 0;
  if (!s1){
    cudaStreamCreateWithFlags(&s1, cudaStreamNonBlocking);
    cudaEventCreateWithFlags(&evF,  cudaEventDisableTiming);
    cudaEventCreateWithFlags(&evJ,  cudaEventDisableTiming);
    cudaEventCreateWithFlags(&evF2, cudaEventDisableTiming);
    cudaEventCreateWithFlags(&evJ2, cudaEventDisableTiming);
    cudaEventCreateWithFlags(&evF3, cudaEventDisableTiming);
    cudaEventCreateWithFlags(&evJ3, cudaEventDisableTiming);
  }

  void *wbuf, *catp, *cat16p, *wp16p, *h16p, *mem16p, *w4p;
  void *q16p, *kvp, *valT16p, *w16p, *atts16p, *l16p, *pmp, *psp;
  cudaGetSymbolAddress(&wbuf, g_w);
  cudaGetSymbolAddress(&catp, g_cat);
  cudaGetSymbolAddress(&cat16p, g_cat16);
  cudaGetSymbolAddress(&wp16p, g_wp16);
  cudaGetSymbolAddress(&h16p, g_h16);
  cudaGetSymbolAddress(&mem16p, g_mem16);
  cudaGetSymbolAddress(&w4p, g_W416);
  cudaGetSymbolAddress(&q16p, g_q16);
  cudaGetSymbolAddress(&kvp, g_kv);
  cudaGetSymbolAddress(&valT16p, g_valT16);
  cudaGetSymbolAddress(&w16p, g_w16);
  cudaGetSymbolAddress(&atts16p, g_atts16);
  cudaGetSymbolAddress(&l16p, g_l16);
  cudaGetSymbolAddress(&pmp, g_pm);
  cudaGetSymbolAddress(&psp, g_ps);

  const __half* W16 = (const __half*)w4p;
  const __half* Wq16 = W16;
  const __half* Wk16 = W16 + (long)HID*HID;
  const __half* Wv16 = W16 + 2L*HID*HID;
  const __half* Wo16 = W16 + 3L*HID*HID;

  float scale = 1.0f/sqrtf((float)HID);

  /* fork: conv_wp16 on s1 overlaps the attention chain */
  cudaEventRecord(evF, 0);
  cudaStreamWaitEvent(s1, evF, 0);
  conv_wp16<<<WP_GRID, 256, 0, s1>>>(Wp);
  cudaEventRecord(evJ, s1);

  /* merged head converters */
  conv_head<<<HEAD_GRID, 256>>>(mem, Wq, Wk, Wv, Wo, h, yemb);

  GH p;

  /* fork q on s1 */
  cudaEventRecord(evF2, 0);
  cudaStreamWaitEvent(s1, evF2, 0);
  p = GH{};
  p.A = (const __half*)h16p; p.B = Wq16; p.Ch = (__half*)q16p;
  p.lda = HID; p.ldb = HID; p.ldc = HID;
  p.M = TB; p.N = HID; p.K = HID;
  p.bias = bq; p.alpha = scale;
  p.mode = 1; p.D1 = BATCH; p.D2 = T_LEN;
  launch_h16<64,0>(p, 1, s1);
  cudaEventRecord(evJ2, s1);

  /* fused k & val projection -> kv (S,B,1024) */
  p = GH{};
  p.A = (const __half*)mem16p; p.B = Wk16; p.B2 = Wv16;
  p.Ch = (__half*)kvp;
  p.lda = HID; p.ldb = HID;
  p.M = SEQ*BATCH; p.N = 2*HID; p.K = HID;
  p.bias = bk; p.bias2 = bva;
  p.mode = 3;
  launch_h16<128,1>(p, 1, 0);

  /* fork val transpose on s1 */
  cudaEventRecord(evF3, 0);
  cudaStreamWaitEvent(s1, evF3, 0);
  transpose_v<<<dim3((SEQ+31)/32, HID/32, BATCH), dim3(32,8), 0, s1>>>();
  cudaEventRecord(evJ3, s1);

  cudaStreamWaitEvent(0, evJ2, 0);

  /* scores: B = k half of kv */
  p = GH{};
  p.A = (const __half*)q16p; p.B = (const __half*)kvp; p.Cf = (float*)wbuf;
  p.lda = HID; p.ldb = (long)BATCH*1024; p.ldc = SEQ;
  p.sA = (long)T_LEN*HID; p.sB = 1024; p.sC = (long)T_LEN*SEQ;
  p.M = T_LEN; p.N = SEQ; p.K = HID;
  p.mode = 0;
  launch_h16<64,0>(p, BATCH, 0);

  softmax_s<<<BATCH*T_LEN, 128>>>(dists, mask);

  cudaStreamWaitEvent(0, evJ3, 0);

  /* atts */
  p = GH{};
  p.A = (const __half*)w16p; p.B = (const __half*)valT16p; p.Ch = (__half*)atts16p;
  p.lda = SEQ; p.ldb = SEQ; p.ldc = HID;
  p.sA = (long)T_LEN*SEQ; p.sB = (long)HID*SEQ; p.sC = (long)T_LEN*HID;
  p.M = T_LEN; p.N = HID; p.K = SEQ;
  p.mode = 4;
  launch_h16<64,0>(p, BATCH, 0);

  /* wo -> cat + cat16 */
  p = GH{};
  p.A = (const __half*)atts16p; p.B = Wo16;
  p.Cf = (float*)catp; p.Ch = (__half*)cat16p;
  p.lda = HID; p.ldb = HID; p.ldc = H3;
  p.M = TB; p.N = HID; p.K = HID;
  p.bias = bo;
  p.mode = 5; p.D1 = T_LEN; p.D2 = BATCH; p.col_off = 1024;
  launch_h16<64,0>(p, 1, 0);

  cudaStreamWaitEvent(0, evJ, 0);

  /* logits + per-stripe stats */
  gemm_wp16<<<dim3(TB/WBM, VPAD/WBN2), 256, WSMEM>>>(
      (const __half*)cat16p, (const __half*)wp16p, bp,
      (__half*)l16p, (float*)pmp, (float*)psp);

  /* tail */
  gate_stats<<<TB, 512>>>(out, vv, bv);
  probs_k<<<dim3(PROB_BX, TB), 256>>>(out);
  scatter_k<<<(int)(((long)TB*SEQ + 255)/256), 256>>>(out, dists, xids);

  (void)out_size; (void)n_in;
}

// round 17
// speedup vs baseline: 1.3676x; 1.0498x over previous
#include <cuda_runtime.h>
#include <cuda_fp16.h>
#include <math.h>
#include <stdint.h>

#define T_LEN 64
#define BATCH 32
#define SEQ   400
#define HID   512
#define VOC   50000
#define EXTD  400
#define VE    (VOC+EXTD)
#define TB    (T_LEN*BATCH)     /* 2048 */
#define H3    (3*HID)           /* 1536 */
#define VPAD  50176             /* VOC padded to 256 */
#define NSTRIPE (VPAD/128)      /* 392 */

/* ---------------- scratch (device globals: allocation-free) -------------- */
__device__ float  g_cat [TB*H3];              /* (T*B,3H) fp32 (gate)        */
__device__ float  g_w   [BATCH*T_LEN*SEQ];    /* scores fp32 (B,T,S)         */
__device__ __half g_cat16[TB*H3];
__device__ __half g_wp16 [(long)VPAD*H3];
__device__ __half g_h16  [TB*HID];
__device__ __half g_mem16[SEQ*BATCH*HID];
__device__ __half g_W416 [4*HID*HID];         /* Wq,Wk,Wv,Wo                 */
__device__ __half g_q16  [BATCH*T_LEN*HID];   /* (B,T,H)                     */
__device__ __half g_kv   [(long)SEQ*BATCH*1024]; /* (S,B,[k(512)|v(512)])    */
__device__ __half g_valT16[BATCH*HID*SEQ];    /* (B,H,S)                     */
__device__ __half g_w16  [BATCH*T_LEN*SEQ];   /* attn weights fp16           */
__device__ __half g_atts16[TB*HID];           /* (B,T,H) rows b*T+t          */
__device__ __half g_l16  [(long)TB*VPAD];     /* fp16 logits                 */
__device__ float  g_pm   [NSTRIPE*TB];        /* per-stripe softmax max      */
__device__ float  g_ps   [NSTRIPE*TB];        /* per-stripe softmax sum      */
__device__ float  g_g    [TB];                /* gate g                      */
__device__ float  g_gscale[TB];               /* g / sumexp                  */
__device__ float  g_M    [TB];                /* row max                     */
__device__ float  g_omg  [TB];                /* 1 - g                       */

#define BN 128

__device__ __forceinline__ void cpa16u(unsigned dst, const void* src, int bytes){
  asm volatile("cp.async.cg.shared.global [%0], [%1], 16, %2;\n"
               :: "r"(dst), "l"(src), "r"(bytes));
}
#define CPA_COMMIT() asm volatile("cp.async.commit_group;\n")
#define CPA_WAIT2()  asm volatile("cp.async.wait_group 2;\n")

#define LDSM_X4(r0,r1,r2,r3,addr) \
  asm volatile("ldmatrix.sync.aligned.m8n8.x4.shared.b16 {%0,%1,%2,%3}, [%4];" \
               : "=r"(r0), "=r"(r1), "=r"(r2), "=r"(r3) : "r"(addr))

#define MMA16(d, a0,a1,a2,a3, b0,b1) \
  asm volatile("mma.sync.aligned.m16n8k16.row.col.f32.f16.f16.f32 " \
               "{%0,%1,%2,%3}, {%4,%5,%6,%7}, {%8,%9}, {%0,%1,%2,%3};\n" \
               : "+f"((d)[0]), "+f"((d)[1]), "+f"((d)[2]), "+f"((d)[3]) \
               : "r"(a0), "r"(a1), "r"(a2), "r"(a3), "r"(b0), "r"(b1))

/* ---------------- generic fp16 MMA GEMM --------------------------------- */
struct GH {
  const __half* A; const __half* B; const __half* B2;
  float* Cf; __half* Ch; __half* Ch2;
  long lda, ldb, ldc;
  long sA, sB, sC;
  int  M, N, K;
  const float* bias; const float* bias2;
  float alpha;
  int  mode, D1, D2;
  long col_off;
};

template<int BMT, int DUAL>
__global__ __launch_bounds__(256,2) void gemm_h16(GH p){
  constexpr int WM   = BMT/32;
  constexpr int NCOL = BN/(8/WM);
  constexpr int NFR  = NCOL/8;
  constexpr int NBL  = NCOL/16;
  constexpr int ABYT = BMT*128;
  constexpr int SBYT = ABYT + BN*128;
  constexpr int GT   = (BMT+BN)*8;

  extern __shared__ float smf[];
  uint32_t sbase = (uint32_t)__cvta_generic_to_shared(smf);
  const __half* A  = p.A + (long)blockIdx.z * p.sA;
  const __half* Bg = p.B + (long)blockIdx.z * p.sB;
  float*  Cf = p.Cf ? p.Cf + (long)blockIdx.z * p.sC : (float*)0;
  __half* Ch = p.Ch ? p.Ch + (long)blockIdx.z * p.sC : (__half*)0;

  int tid = threadIdx.x;
  int lane = tid & 31, warp = tid >> 5;
  int wm = warp % WM, wn = warp / WM;
  int m0 = blockIdx.x * BMT, n0 = blockIdx.y * BN;

  float acc[2][NFR][4];
  #pragma unroll
  for (int i=0;i<2;i++)
    #pragma unroll
    for (int j=0;j<NFR;j++){ acc[i][j][0]=0.f; acc[i][j][1]=0.f; acc[i][j][2]=0.f; acc[i][j][3]=0.f; }

  int ktiles = (p.K + 63)/64;

  auto load = [&](int st, int k0){
    uint32_t ab = sbase + st*SBYT;
    uint32_t bb = ab + ABYT;
    #pragma unroll
    for (int i=0;i<GT/256;i++){
      int g = tid + i*256;
      int r = g >> 3, gc = g & 7;
      int kcol = k0 + gc*8;
      int kb = (kcol < p.K) ? 16 : 0;
      if (r < BMT){
        uint32_t soff = (uint32_t)(r*128 + ((gc ^ (r&7))<<4));
        int gm = m0 + r;
        cpa16u(ab + soff, A + (long)gm*p.lda + kcol, (gm < p.M) ? kb : 0);
      } else {
        int rb = r - BMT;
        uint32_t soff = (uint32_t)(rb*128 + ((gc ^ (rb&7))<<4));
        int gn = n0 + rb;
        const __half* src;
        if (DUAL && gn >= HID) src = p.B2 + (long)(gn-HID)*p.ldb + kcol;
        else                   src = Bg  + (long)gn*p.ldb + kcol;
        cpa16u(bb + soff, src, (gn < p.N) ? kb : 0);
      }
    }
  };

  load(0, 0); CPA_COMMIT();
  load(1, 64); CPA_COMMIT();

  int mi1 = (lane >> 3) & 1;
  int kg2 = lane >> 4;
  int ri  = lane & 7;
  int marow = wm*32 + mi1*8 + ri;
  int nbrow = wn*NCOL + mi1*8 + ri;
  int maxor = (marow & 7);
  int nbxor = (nbrow & 7);

  for (int kt = 0; kt < ktiles; kt++){
    if (kt + 2 < ktiles) load((kt+2)%3, (kt+2)*64);
    CPA_COMMIT();
    CPA_WAIT2();
    __syncthreads();

    uint32_t ab = sbase + (kt%3)*SBYT;
    uint32_t aA = ab + marow*128;
    uint32_t aB = ab + ABYT + nbrow*128;

    #pragma unroll
    for (int kk=0; kk<4; kk++){
      uint32_t asw = (uint32_t)(((kk*2 + kg2) ^ maxor) << 4);
      uint32_t bsw = (uint32_t)(((kk*2 + kg2) ^ nbxor) << 4);
      unsigned af0[4], af1[4], bf[NBL][4];
      LDSM_X4(af0[0],af0[1],af0[2],af0[3], aA + asw);
      LDSM_X4(af1[0],af1[1],af1[2],af1[3], aA + asw + 16*128);
      #pragma unroll
      for (int jp=0; jp<NBL; jp++)
        LDSM_X4(bf[jp][0],bf[jp][1],bf[jp][2],bf[jp][3], aB + bsw + jp*16*128);
      #pragma unroll
      for (int jp=0; jp<NBL; jp++){
        MMA16(acc[0][2*jp  ], af0[0],af0[1],af0[2],af0[3], bf[jp][0], bf[jp][2]);
        MMA16(acc[0][2*jp+1], af0[0],af0[1],af0[2],af0[3], bf[jp][1], bf[jp][3]);
        MMA16(acc[1][2*jp  ], af1[0],af1[1],af1[2],af1[3], bf[jp][0], bf[jp][2]);
        MMA16(acc[1][2*jp+1], af1[0],af1[1],af1[2],af1[3], bf[jp][1], bf[jp][3]);
      }
    }
    __syncthreads();
  }

  if (DUAL){
    constexpr int TP = 136;
    __half* tile = (__half*)smf;
    const float* bptr = (n0 < HID) ? p.bias : p.bias2;
    int nb0 = (n0 < HID) ? n0 : n0 - HID;
    int r = lane >> 2, c2v = (lane & 3)*2;
    #pragma unroll
    for (int im=0; im<2; im++)
      #pragma unroll
      for (int jn=0; jn<NFR; jn++){
        int ml = wm*32 + im*16 + r;
        int nl = wn*NCOL + jn*8 + c2v;
        float b0 = bptr[nb0 + nl], b1 = bptr[nb0 + nl + 1];
        tile[ ml   *TP + nl    ] = __float2half_rn(acc[im][jn][0] + b0);
        tile[ ml   *TP + nl + 1] = __float2half_rn(acc[im][jn][1] + b1);
        tile[(ml+8)*TP + nl    ] = __float2half_rn(acc[im][jn][2] + b0);
        tile[(ml+8)*TP + nl + 1] = __float2half_rn(acc[im][jn][3] + b1);
      }
    __syncthreads();
    #pragma unroll
    for (int i2=0; i2<8; i2++){
      int i = tid + i2*256;
      int rr = i >> 4, cc = (i & 15)*8;
      uint4 v = *(uint4*)&tile[rr*TP + cc];
      *(uint4*)(p.Ch + (long)(m0 + rr)*1024 + n0 + cc) = v;
    }
    return;
  }

  int r = lane >> 2, c2 = (lane & 3)*2;

  if (p.mode == 0){
    constexpr int TPF = BN + 4;
    float* tf = smf;
    #pragma unroll
    for (int im=0; im<2; im++)
      #pragma unroll
      for (int jn=0; jn<NFR; jn++){
        int ml = wm*32 + im*16 + r;
        int nl = wn*NCOL + jn*8 + c2;
        tf[ ml   *TPF + nl    ] = acc[im][jn][0];
        tf[ ml   *TPF + nl + 1] = acc[im][jn][1];
        tf[(ml+8)*TPF + nl    ] = acc[im][jn][2];
        tf[(ml+8)*TPF + nl + 1] = acc[im][jn][3];
      }
    __syncthreads();
    int nvalid = p.N - n0; if (nvalid > BN) nvalid = BN;
    #pragma unroll
    for (int i2=0; i2<8; i2++){
      int i = tid + i2*256;
      int rr = i >> 5, cc = (i & 31)*4;
      if (cc < nvalid){
        float4 v = *(float4*)&tf[rr*TPF + cc];
        *(float4*)(Cf + (long)(m0 + rr)*p.ldc + n0 + cc) = v;
      }
    }
    return;
  }

  if (p.mode == 1 || p.mode == 4){
    constexpr int TP = 136;
    __half* th = (__half*)smf;
    #pragma unroll
    for (int im=0; im<2; im++)
      #pragma unroll
      for (int jn=0; jn<NFR; jn++){
        int ml = wm*32 + im*16 + r;
        int nl = wn*NCOL + jn*8 + c2;
        float v0 = acc[im][jn][0], v1 = acc[im][jn][1];
        float v2 = acc[im][jn][2], v3 = acc[im][jn][3];
        if (p.mode == 1){
          float b0 = p.bias[n0 + nl], b1 = p.bias[n0 + nl + 1];
          v0 = p.alpha*(v0 + b0); v1 = p.alpha*(v1 + b1);
          v2 = p.alpha*(v2 + b0); v3 = p.alpha*(v3 + b1);
        }
        th[ ml   *TP + nl    ] = __float2half_rn(v0);
        th[ ml   *TP + nl + 1] = __float2half_rn(v1);
        th[(ml+8)*TP + nl    ] = __float2half_rn(v2);
        th[(ml+8)*TP + nl + 1] = __float2half_rn(v3);
      }
    __syncthreads();
    #pragma unroll
    for (int i2=0; i2<4; i2++){
      int i = tid + i2*256;
      int rr = i >> 4, cc = (i & 15)*8;
      int gm = m0 + rr;
      long grow = (p.mode == 1) ? ((long)(gm % p.D1)*p.D2 + gm/p.D1) : gm;
      uint4 v = *(uint4*)&th[rr*TP + cc];
      *(uint4*)(Ch + grow*p.ldc + n0 + cc) = v;
    }
    return;
  }

  {
    constexpr int TPF = BN + 4;
    float* tf = smf;
    #pragma unroll
    for (int im=0; im<2; im++)
      #pragma unroll
      for (int jn=0; jn<NFR; jn++){
        int ml = wm*32 + im*16 + r;
        int nl = wn*NCOL + jn*8 + c2;
        float b0 = p.bias[n0 + nl], b1 = p.bias[n0 + nl + 1];
        tf[ ml   *TPF + nl    ] = acc[im][jn][0] + b0;
        tf[ ml   *TPF + nl + 1] = acc[im][jn][1] + b1;
        tf[(ml+8)*TPF + nl    ] = acc[im][jn][2] + b0;
        tf[(ml+8)*TPF + nl + 1] = acc[im][jn][3] + b1;
      }
    __syncthreads();
    #pragma unroll
    for (int i2=0; i2<4; i2++){
      int i = tid + i2*256;
      int rr = i >> 4, cc = (i & 15)*8;
      int gm = m0 + rr;
      long grow = (long)(gm % p.D1)*p.D2 + gm/p.D1;
      long base = grow*p.ldc + p.col_off + n0 + cc;
      float4 a = *(float4*)&tf[rr*TPF + cc];
      float4 b = *(float4*)&tf[rr*TPF + cc + 4];
      *(float4*)(Cf + base)     = a;
      *(float4*)(Cf + base + 4) = b;
      __half2 hh[4];
      hh[0] = __floats2half2_rn(a.x, a.y);
      hh[1] = __floats2half2_rn(a.z, a.w);
      hh[2] = __floats2half2_rn(b.x, b.y);
      hh[3] = __floats2half2_rn(b.z, b.w);
      *(uint4*)(Ch + base) = *(uint4*)hh;
    }
  }
}

/* ---- transpose: kv val-half (S,B,512) -> valT (B,H,S) ------------------- */
__global__ void transpose_v(){
  __shared__ __half tile[32][33];
  int b  = blockIdx.z;
  int h0 = blockIdx.y * 32;
  int s0 = blockIdx.x * 32;
  int x = threadIdx.x, y = threadIdx.y;
  #pragma unroll
  for (int k2=0;k2<4;k2++){
    int s = s0 + y + k2*8;
    if (s < SEQ)
      tile[y+k2*8][x] = g_kv[((long)s*BATCH + b)*1024 + 512 + h0 + x];
  }
  __syncthreads();
  int s = s0 + x;
  if (s < SEQ){
    #pragma unroll
    for (int k2=0;k2<4;k2++){
      int hh = h0 + y + k2*8;
      g_valT16[((long)b*HID + hh)*SEQ + s] = tile[x][y+k2*8];
    }
  }
}

/* ---------------- fp16 converters (MLP=4) -------------------------------- */
#define WP_GRID  18816
#define WP_STRIDE ((long)WP_GRID*256)
__global__ void conv_wp16(const float* __restrict__ Wp){
  long i0 = (long)blockIdx.x*256 + threadIdx.x;
  float4 v[4];
  long idx[4];
  #pragma unroll
  for (int u=0; u<4; u++){
    long i = i0 + (long)u*WP_STRIDE;
    idx[u] = i;
    long row = i / (H3/4);
    long c4  = i % (H3/4);
    v[u] = (row < VOC) ? *(const float4*)(Wp + row*H3 + c4*4)
                       : make_float4(0.f,0.f,0.f,0.f);
  }
  __half2* dst = (__half2*)g_wp16;
  #pragma unroll
  for (int u=0; u<4; u++){
    dst[idx[u]*2]   = __floats2half2_rn(v[u].x, v[u].y);
    dst[idx[u]*2+1] = __floats2half2_rn(v[u].z, v[u].w);
  }
}

/* ---- merged head: mem16 + W416 + cat/cat16/h16 --------------------------- */
#define MEM_GRID 1600
#define MEM_STRIDE ((long)MEM_GRID*256)
#define WTS_GRID 256
#define WTS_STRIDE (WTS_GRID*256)
#define CAT_GRID 1024
#define HEAD_GRID (MEM_GRID + WTS_GRID + CAT_GRID)
__global__ void conv_head(const float* __restrict__ mem,
                          const float* __restrict__ Wq, const float* __restrict__ Wk,
                          const float* __restrict__ Wv, const float* __restrict__ Wo,
                          const float* __restrict__ h, const float* __restrict__ y){
  int bx = blockIdx.x;
  int tid = threadIdx.x;
  if (bx < MEM_GRID){
    long i0 = (long)bx*256 + tid;
    float4 v[4];
    #pragma unroll
    for (int u=0; u<4; u++) v[u] = *(const float4*)(mem + (i0 + (long)u*MEM_STRIDE)*4);
    __half2* dst = (__half2*)g_mem16;
    #pragma unroll
    for (int u=0; u<4; u++){
      long i = i0 + (long)u*MEM_STRIDE;
      dst[i*2]   = __floats2half2_rn(v[u].x, v[u].y);
      dst[i*2+1] = __floats2half2_rn(v[u].z, v[u].w);
    }
    return;
  }
  bx -= MEM_GRID;
  if (bx < WTS_GRID){
    int i0 = bx*256 + tid;
    const int per = HID*HID/4;
    float4 v[4];
    #pragma unroll
    for (int u=0; u<4; u++){
      int i = i0 + u*WTS_STRIDE;
      int seg = i / per, off = i % per;
      const float* src = (seg==0)?Wq:(seg==1)?Wk:(seg==2)?Wv:Wo;
      v[u] = *(const float4*)(src + (long)off*4);
    }
    __half2* dst = (__half2*)g_W416;
    #pragma unroll
    for (int u=0; u<4; u++){
      int i = i0 + u*WTS_STRIDE;
      dst[i*2]   = __floats2half2_rn(v[u].x, v[u].y);
      dst[i*2+1] = __floats2half2_rn(v[u].z, v[u].w);
    }
    return;
  }
  bx -= WTS_GRID;
  {
    int i = bx*256 + tid;
    int row = i / (HID/4);
    int c   = i % (HID/4);
    const float4 hv = ((const float4*)h)[i];
    const float4 yv = ((const float4*)y)[i];
    float4* cat4 = (float4*)g_cat;
    cat4[(long)row*(H3/4) + c]           = hv;
    cat4[(long)row*(H3/4) + (HID/4) + c] = yv;
    __half2* c16 = (__half2*)g_cat16;
    long b = (long)row*(H3/2);
    __half2 h01 = __floats2half2_rn(hv.x, hv.y);
    __half2 h23 = __floats2half2_rn(hv.z, hv.w);
    c16[b + c*2]               = h01;
    c16[b + c*2 + 1]           = h23;
    c16[b + (HID/2) + c*2]     = __floats2half2_rn(yv.x, yv.y);
    c16[b + (HID/2) + c*2 + 1] = __floats2half2_rn(yv.z, yv.w);
    __half2* h16 = (__half2*)g_h16;
    h16[i*2]   = h01;
    h16[i*2+1] = h23;
  }
}

/* == fp16 Wp GEMM: 128x128 CTA, 256 thr, 2 CTA/SM, fused softmax stats === */
#define WBM 128
#define WBN2 128
#define WABY (WBM*128)
#define WSBY (WABY + WBN2*128)
#define WSMEM (3*WSBY)

__device__ __forceinline__ void merge_ms(float& m, float& s, float m2, float s2){
  float M = fmaxf(m, m2);
  s = s*__expf(m-M) + s2*__expf(m2-M);
  m = M;
}

__global__ __launch_bounds__(256,2) void gemm_wp16(
    const __half* __restrict__ A, const __half* __restrict__ B,
    const float* __restrict__ bias, __half* __restrict__ l16,
    float* __restrict__ pm, float* __restrict__ ps)
{
  extern __shared__ float smf[];
  __shared__ float red_m[2][128], red_s[2][128];
  uint32_t sbase = (uint32_t)__cvta_generic_to_shared(smf);
  int tid = threadIdx.x;
  int lane = tid & 31, warp = tid >> 5;
  int wm = warp & 3, wn = warp >> 2;
  int m0 = blockIdx.x * WBM, n0 = blockIdx.y * WBN2;

  float acc[2][8][4];
  #pragma unroll
  for (int i=0;i<2;i++)
    #pragma unroll
    for (int j=0;j<8;j++){ acc[i][j][0]=0.f; acc[i][j][1]=0.f; acc[i][j][2]=0.f; acc[i][j][3]=0.f; }

  const int ktiles = H3/64;

  auto load = [&](int st, int k0){
    uint32_t ab = sbase + st*WSBY;
    uint32_t bb = ab + WABY;
    #pragma unroll
    for (int i=0;i<8;i++){
      int g = tid + i*256;
      int r = g >> 3, gc = g & 7;
      int kcol = k0 + gc*8;
      if (r < WBM){
        uint32_t soff = (uint32_t)(r*128 + ((gc ^ (r&7))<<4));
        cpa16u(ab + soff, A + (long)(m0 + r)*H3 + kcol, 16);
      } else {
        int rb = r - WBM;
        uint32_t soff = (uint32_t)(rb*128 + ((gc ^ (rb&7))<<4));
        cpa16u(bb + soff, B + (long)(n0 + rb)*H3 + kcol, 16);
      }
    }
  };

  load(0, 0); CPA_COMMIT();
  load(1, 64); CPA_COMMIT();

  int mi1 = (lane >> 3) & 1;
  int kg2 = lane >> 4;
  int ri  = lane & 7;
  int marow = wm*32 + mi1*8 + ri;
  int nbrow = wn*64 + mi1*8 + ri;
  int maxor = (marow & 7);
  int nbxor = (nbrow & 7);

  for (int kt = 0; kt < ktiles; kt++){
    if (kt + 2 < ktiles) load((kt+2)%3, (kt+2)*64);
    CPA_COMMIT();
    CPA_WAIT2();
    __syncthreads();

    uint32_t ab = sbase + (kt%3)*WSBY;
    uint32_t aA = ab + marow*128;
    uint32_t aB = ab + WABY + nbrow*128;

    #pragma unroll
    for (int kk=0; kk<4; kk++){
      uint32_t asw = (uint32_t)(((kk*2 + kg2) ^ maxor) << 4);
      uint32_t bsw = (uint32_t)(((kk*2 + kg2) ^ nbxor) << 4);
      unsigned af0[4], af1[4], bf[4][4];
      LDSM_X4(af0[0],af0[1],af0[2],af0[3], aA + asw);
      LDSM_X4(af1[0],af1[1],af1[2],af1[3], aA + asw + 16*128);
      #pragma unroll
      for (int jb=0; jb<4; jb++)
        LDSM_X4(bf[jb][0],bf[jb][1],bf[jb][2],bf[jb][3], aB + bsw + jb*16*128);
      #pragma unroll
      for (int jb=0; jb<4; jb++){
        MMA16(acc[0][2*jb  ], af0[0],af0[1],af0[2],af0[3], bf[jb][0], bf[jb][2]);
        MMA16(acc[0][2*jb+1], af0[0],af0[1],af0[2],af0[3], bf[jb][1], bf[jb][3]);
        MMA16(acc[1][2*jb  ], af1[0],af1[1],af1[2],af1[3], bf[jb][0], bf[jb][2]);
        MMA16(acc[1][2*jb+1], af1[0],af1[1],af1[2],af1[3], bf[jb][1], bf[jb][3]);
      }
    }
    __syncthreads();
  }

  int r2 = lane >> 2, c2 = (lane & 3)*2;
  #pragma unroll
  for (int im=0; im<2; im++){
    int mr = m0 + wm*32 + im*16 + r2;
    float m0v=-1e30f, m1v=-1e30f, s0v=0.f, s1v=0.f;
    #pragma unroll
    for (int nj=0; nj<8; nj++){
      int nc = n0 + wn*64 + nj*8 + c2;
      if (nc < VOC){
        float b0 = bias[nc], b1 = bias[nc+1];
        float v00 = acc[im][nj][0]+b0, v01 = acc[im][nj][1]+b1;
        float v10 = acc[im][nj][2]+b0, v11 = acc[im][nj][3]+b1;
        acc[im][nj][0]=v00; acc[im][nj][1]=v01;
        acc[im][nj][2]=v10; acc[im][nj][3]=v11;
        *(__half2*)(l16 + (long)mr*VPAD + nc)     = __floats2half2_rn(v00,v01);
        *(__half2*)(l16 + (long)(mr+8)*VPAD + nc) = __floats2half2_rn(v10,v11);
        m0v = fmaxf(m0v, fmaxf(v00,v01));
        m1v = fmaxf(m1v, fmaxf(v10,v11));
      }
    }
    #pragma unroll
    for (int nj=0; nj<8; nj++){
      int nc = n0 + wn*64 + nj*8 + c2;
      if (nc < VOC){
        s0v += __expf(acc[im][nj][0]-m0v) + __expf(acc[im][nj][1]-m0v);
        s1v += __expf(acc[im][nj][2]-m1v) + __expf(acc[im][nj][3]-m1v);
      }
    }
    #pragma unroll
    for (int off=1; off<4; off<<=1){
      float om0 = __shfl_xor_sync(0xFFFFFFFFu, m0v, off);
      float os0 = __shfl_xor_sync(0xFFFFFFFFu, s0v, off);
      merge_ms(m0v, s0v, om0, os0);
      float om1 = __shfl_xor_sync(0xFFFFFFFFu, m1v, off);
      float os1 = __shfl_xor_sync(0xFFFFFFFFu, s1v, off);
      merge_ms(m1v, s1v, om1, os1);
    }
    if ((lane & 3) == 0){
      int rl = wm*32 + im*16 + r2;
      red_m[wn][rl]   = m0v; red_s[wn][rl]   = s0v;
      red_m[wn][rl+8] = m1v; red_s[wn][rl+8] = s1v;
    }
  }
  __syncthreads();
  if (tid < 128){
    float M = red_m[0][tid], S = red_s[0][tid];
    merge_ms(M, S, red_m[1][tid], red_s[1][tid]);
    pm[(long)blockIdx.y*TB + m0 + tid] = M;
    ps[(long)blockIdx.y*TB + m0 + tid] = S;
  }
}

/* ------ softmax over S; writes w16 (B,T,S) + dists fp32 (T,B,S) ---------- */
__global__ void softmax_s(float* __restrict__ dists, const unsigned char* __restrict__ mask){
  int bt = blockIdx.x;
  int b = bt / T_LEN, t = bt % T_LEN;
  float* row = g_w + (long)bt*SEQ;
  const unsigned char* mrow = mask + (long)b*SEQ;
  int tid = threadIdx.x;
  __shared__ float red[128];
  float mx = -1e30f;
  for (int s=tid; s<SEQ; s+=128){
    float x = mrow[s] ? -1e9f : row[s];
    mx = fmaxf(mx, x);
  }
  red[tid]=mx; __syncthreads();
  for (int off=64; off>0; off>>=1){ if (tid<off) red[tid]=fmaxf(red[tid],red[tid+off]); __syncthreads(); }
  mx = red[0]; __syncthreads();
  float sum=0.f;
  for (int s=tid; s<SEQ; s+=128){
    float x = mrow[s] ? -1e9f : row[s];
    sum += __expf(x-mx);
  }
  red[tid]=sum; __syncthreads();
  for (int off=64; off>0; off>>=1){ if (tid<off) red[tid]+=red[tid+off]; __syncthreads(); }
  float inv = 1.f/red[0];
  for (int s=tid; s<SEQ; s+=128){
    float x = mrow[s] ? -1e9f : row[s];
    float wv = __expf(x-mx)*inv;
    g_w16[(long)bt*SEQ + s] = __float2half_rn(wv);
    dists[((long)t*BATCH + b)*SEQ + s] = wv;
  }
}

/* -------- gate (fork, overlaps Wp GEMM): sigmoid + ext zero -------------- */
__global__ void gate_k(float* __restrict__ out,
                       const float* __restrict__ vv, const float* __restrict__ bvv){
  int rid = blockIdx.x;
  float* row = out + (long)rid*VE;
  int tid = threadIdx.x;                /* 512 */
  __shared__ float rm[512];
  const float* cr = g_cat + (long)rid*H3;
  float s0 = 0.f;
  for (int j=tid; j<H3; j+=512) s0 += cr[j]*vv[j];
  rm[tid]=s0; __syncthreads();
  for (int off=256; off>0; off>>=1){ if (tid<off) rm[tid]+=rm[tid+off]; __syncthreads(); }
  if (tid==0){
    float g = 1.f/(1.f+__expf(-(rm[0]+bvv[0])));
    g_g[rid]   = g;
    g_omg[rid] = 1.f - g;
  }
  for (int j=VOC+tid; j<VE; j+=512) row[j] = 0.f;
}

/* -------- stats merge (after Wp GEMM) ------------------------------------ */
__global__ void stats_k(){
  int rid = blockIdx.x;
  int tid = threadIdx.x;                /* 512 */
  __shared__ float rm[512], rs[512];
  float m = -1e30f, s = 0.f;
  if (tid < NSTRIPE){
    m = g_pm[(long)tid*TB + rid];
    s = g_ps[(long)tid*TB + rid];
  }
  rm[tid]=m; rs[tid]=s; __syncthreads();
  for (int off=256; off>0; off>>=1){
    if (tid<off){
      float m2=rm[tid+off], s2=rs[tid+off];
      float M=fmaxf(rm[tid],m2);
      rs[tid]=rs[tid]*__expf(rm[tid]-M)+s2*__expf(m2-M);
      rm[tid]=M;
    }
    __syncthreads();
  }
  if (tid == 0){
    g_M[rid]      = rm[0];
    g_gscale[rid] = g_g[rid]/rs[0];
  }
}

/* -------- probs: streaming fp16 logit -> fp32 prob (4 cols/thread) ------- */
#define PROB_BX 49                       /* 49*1024 = 50176 >= VOC           */
__global__ void probs_k(float* __restrict__ out){
  int rid = blockIdx.y;
  int col = (blockIdx.x*256 + threadIdx.x)*4;
  if (col >= VOC) return;               /* VOC%4==0: whole quad valid        */
  float M = g_M[rid];
  float gs = g_gscale[rid];
  uint2 lv = *(const uint2*)(g_l16 + (long)rid*VPAD + col);
  float2 a = __half22float2(*(__half2*)&lv.x);
  float2 b = __half22float2(*(__half2*)&lv.y);
  float4 o;
  o.x = __expf(a.x - M)*gs;
  o.y = __expf(a.y - M)*gs;
  o.z = __expf(b.x - M)*gs;
  o.w = __expf(b.y - M)*gs;
  *(float4*)(out + (long)rid*VE + col) = o;
}

/* -------- scatter: out[rid, xids[s,b]] += (1-g)*dists -------------------- */
__global__ void scatter_k(float* __restrict__ out, const float* __restrict__ dists,
                          const int* __restrict__ xids){
  long i = (long)blockIdx.x*256 + threadIdx.x;
  if (i >= (long)TB*SEQ) return;
  int rid = (int)(i / SEQ);
  int s   = (int)(i % SEQ);
  int b = rid % BATCH, t = rid / BATCH;
  float wv = dists[((long)t*BATCH + b)*SEQ + s];
  int col = xids[(long)s*BATCH + b];
  atomicAdd(out + (long)rid*VE + col, g_omg[rid]*wv);
}

/* ------------------------------- host ----------------------------------- */
template<int BMT, int DUAL>
static inline void launch_h16(const GH& p, int batches, cudaStream_t st){
  constexpr int SM = 3*((BMT+BN)*128);
  static bool done = false;
  if (!done){
    cudaFuncSetAttribute(gemm_h16<BMT,DUAL>,
                         cudaFuncAttributeMaxDynamicSharedMemorySize, SM);
    done = true;
  }
  dim3 grid((p.M+BMT-1)/BMT, (p.N+BN-1)/BN, batches);
  gemm_h16<BMT,DUAL><<<grid, 256, SM, st>>>(p);
}

extern "C" void kernel_launch(void* const* d_in, const int* in_sizes, int n_in,
                              void* d_out, int out_size){
  const float* h    = (const float*)d_in[0];
  const float* yemb = (const float*)d_in[1];
  const float* mem  = (const float*)d_in[2];
  const unsigned char* mask = (const unsigned char*)d_in[3];
  const int* xids   = (const int*)d_in[4];
  int wb = 5;
  if (n_in >= 18 && in_sizes[5] == 1) wb = 6;
  const float* Wq = (const float*)d_in[wb+0];
  const float* bq = (const float*)d_in[wb+1];
  const float* Wk = (const float*)d_in[wb+2];
  const float* bk = (const float*)d_in[wb+3];
  const float* Wv = (const float*)d_in[wb+4];
  const float* bva= (const float*)d_in[wb+5];
  const float* Wo = (const float*)d_in[wb+6];
  const float* bo = (const float*)d_in[wb+7];
  const float* Wp = (const float*)d_in[wb+8];
  const float* bp = (const float*)d_in[wb+9];
  const float* vv = (const float*)d_in[wb+10];
  const float* bv = (const float*)d_in[wb+11];

  float* out   = (float*)d_out;
  float* dists = out + (long)TB*VE;

  cudaFuncSetAttribute(gemm_wp16, cudaFuncAttributeMaxDynamicSharedMemorySize, WSMEM);

  static cudaStream_t s1 = 0;
  static cudaEvent_t evF = 0, evJ = 0, evF2 = 0, evJ2 = 0, evF3 = 0, evJ3 = 0;
  static cudaEvent_t evF4 = 0, evJ4 = 0;
  if (!s1){
    cudaStreamCreateWithFlags(&s1, cudaStreamNonBlocking);
    cudaEventCreateWithFlags(&evF,  cudaEventDisableTiming);
    cudaEventCreateWithFlags(&evJ,  cudaEventDisableTiming);
    cudaEventCreateWithFlags(&evF2, cudaEventDisableTiming);
    cudaEventCreateWithFlags(&evJ2, cudaEventDisableTiming);
    cudaEventCreateWithFlags(&evF3, cudaEventDisableTiming);
    cudaEventCreateWithFlags(&evJ3, cudaEventDisableTiming);
    cudaEventCreateWithFlags(&evF4, cudaEventDisableTiming);
    cudaEventCreateWithFlags(&evJ4, cudaEventDisableTiming);
  }

  void *wbuf, *catp, *cat16p, *wp16p, *h16p, *mem16p, *w4p;
  void *q16p, *kvp, *valT16p, *w16p, *atts16p, *l16p, *pmp, *psp;
  cudaGetSymbolAddress(&wbuf, g_w);
  cudaGetSymbolAddress(&catp, g_cat);
  cudaGetSymbolAddress(&cat16p, g_cat16);
  cudaGetSymbolAddress(&wp16p, g_wp16);
  cudaGetSymbolAddress(&h16p, g_h16);
  cudaGetSymbolAddress(&mem16p, g_mem16);
  cudaGetSymbolAddress(&w4p, g_W416);
  cudaGetSymbolAddress(&q16p, g_q16);
  cudaGetSymbolAddress(&kvp, g_kv);
  cudaGetSymbolAddress(&valT16p, g_valT16);
  cudaGetSymbolAddress(&w16p, g_w16);
  cudaGetSymbolAddress(&atts16p, g_atts16);
  cudaGetSymbolAddress(&l16p, g_l16);
  cudaGetSymbolAddress(&pmp, g_pm);
  cudaGetSymbolAddress(&psp, g_ps);

  const __half* W16 = (const __half*)w4p;
  const __half* Wq16 = W16;
  const __half* Wk16 = W16 + (long)HID*HID;
  const __half* Wv16 = W16 + 2L*HID*HID;
  const __half* Wo16 = W16 + 3L*HID*HID;

  float scale = 1.0f/sqrtf((float)HID);

  /* fork: conv_wp16 on s1 overlaps the attention chain */
  cudaEventRecord(evF, 0);
  cudaStreamWaitEvent(s1, evF, 0);
  conv_wp16<<<WP_GRID, 256, 0, s1>>>(Wp);
  cudaEventRecord(evJ, s1);

  /* merged head converters */
  conv_head<<<HEAD_GRID, 256>>>(mem, Wq, Wk, Wv, Wo, h, yemb);

  GH p;

  /* fork q on s1 */
  cudaEventRecord(evF2, 0);
  cudaStreamWaitEvent(s1, evF2, 0);
  p = GH{};
  p.A = (const __half*)h16p; p.B = Wq16; p.Ch = (__half*)q16p;
  p.lda = HID; p.ldb = HID; p.ldc = HID;
  p.M = TB; p.N = HID; p.K = HID;
  p.bias = bq; p.alpha = scale;
  p.mode = 1; p.D1 = BATCH; p.D2 = T_LEN;
  launch_h16<64,0>(p, 1, s1);
  cudaEventRecord(evJ2, s1);

  /* fused k & val projection -> kv (S,B,1024) */
  p = GH{};
  p.A = (const __half*)mem16p; p.B = Wk16; p.B2 = Wv16;
  p.Ch = (__half*)kvp;
  p.lda = HID; p.ldb = HID;
  p.M = SEQ*BATCH; p.N = 2*HID; p.K = HID;
  p.bias = bk; p.bias2 = bva;
  p.mode = 3;
  launch_h16<128,1>(p, 1, 0);

  /* fork val transpose on s1 */
  cudaEventRecord(evF3, 0);
  cudaStreamWaitEvent(s1, evF3, 0);
  transpose_v<<<dim3((SEQ+31)/32, HID/32, BATCH), dim3(32,8), 0, s1>>>();
  cudaEventRecord(evJ3, s1);

  cudaStreamWaitEvent(0, evJ2, 0);

  /* scores: B = k half of kv */
  p = GH{};
  p.A = (const __half*)q16p; p.B = (const __half*)kvp; p.Cf = (float*)wbuf;
  p.lda = HID; p.ldb = (long)BATCH*1024; p.ldc = SEQ;
  p.sA = (long)T_LEN*HID; p.sB = 1024; p.sC = (long)T_LEN*SEQ;
  p.M = T_LEN; p.N = SEQ; p.K = HID;
  p.mode = 0;
  launch_h16<64,0>(p, BATCH, 0);

  softmax_s<<<BATCH*T_LEN, 128>>>(dists, mask);

  cudaStreamWaitEvent(0, evJ3, 0);

  /* atts */
  p = GH{};
  p.A = (const __half*)w16p; p.B = (const __half*)valT16p; p.Ch = (__half*)atts16p;
  p.lda = SEQ; p.ldb = SEQ; p.ldc = HID;
  p.sA = (long)T_LEN*SEQ; p.sB = (long)HID*SEQ; p.sC = (long)T_LEN*HID;
  p.M = T_LEN; p.N = HID; p.K = SEQ;
  p.mode = 4;
  launch_h16<64,0>(p, BATCH, 0);

  /* wo -> cat + cat16 */
  p = GH{};
  p.A = (const __half*)atts16p; p.B = Wo16;
  p.Cf = (float*)catp; p.Ch = (__half*)cat16p;
  p.lda = HID; p.ldb = HID; p.ldc = H3;
  p.M = TB; p.N = HID; p.K = HID;
  p.bias = bo;
  p.mode = 5; p.D1 = T_LEN; p.D2 = BATCH; p.col_off = 1024;
  launch_h16<64,0>(p, 1, 0);

  /* fork gate (needs cat only) -> runs concurrently with gemm_wp16 */
  cudaEventRecord(evF4, 0);
  cudaStreamWaitEvent(s1, evF4, 0);
  gate_k<<<TB, 512, 0, s1>>>(out, vv, bv);
  cudaEventRecord(evJ4, s1);

  cudaStreamWaitEvent(0, evJ, 0);

  /* logits + per-stripe stats */
  gemm_wp16<<<dim3(TB/WBM, VPAD/WBN2), 256, WSMEM>>>(
      (const __half*)cat16p, (const __half*)wp16p, bp,
      (__half*)l16p, (float*)pmp, (float*)psp);

  cudaStreamWaitEvent(0, evJ4, 0);

  /* tail: stats merge -> streaming probs -> scatter */
  stats_k<<<TB, 512>>>();
  probs_k<<<dim3(PROB_BX, TB), 256>>>(out);
  scatter_k<<<(int)(((long)TB*SEQ + 255)/256), 256>>>(out, dists, xids);

  (void)out_size; (void)n_in;
}